// round 3
// baseline (speedup 1.0000x reference)
#include <cuda_runtime.h>
#include <math.h>

#define NATOMS 500000
#define LDA 208          // padded K (max K = 206)
#define KPAD 208

// ---------------- scratch (static device globals; no runtime allocation) ----------------
__device__ float g_A[(size_t)NATOMS * LDA];      // 416 MB : [x | a_sum | b_sum] padded
__device__ float g_T[(size_t)NATOMS * 512];      // 1 GB   : pre-norm layer output t
__device__ float g_X[(size_t)NATOMS * 100];      // 200 MB : post-norm x (layers 0,1 out)
__device__ float g_Wc[4 * KPAD * 512];           // concatenated weights per degree, zero padded
__device__ float g_bc[4 * 512];                  // combined bias per degree, zero padded

// ---------------- build concatenated weight matrix ----------------
// Wcat[d] rows: [0,din): Ws ; [din,2din): Wd[d][0:din] ; [2din,2din+6): Wd[d][din:din+6]
// layout: g_Wc[d*KPAD*ldb + k*ldb + j], zero outside (k<K, j<dout)
__global__ void build_wcat_kernel(const float* __restrict__ Ws, const float* __restrict__ Wd,
                                  int din, int dout, int ldb)
{
    int K = 2 * din + 6;
    int perD = KPAD * ldb;
    int total = 4 * perD;
    for (int idx = blockIdx.x * blockDim.x + threadIdx.x; idx < total;
         idx += gridDim.x * blockDim.x) {
        int d   = idx / perD;
        int rem = idx - d * perD;
        int k   = rem / ldb;
        int j   = rem - k * ldb;
        float v = 0.f;
        if (j < dout && k < K) {
            if (k < din) v = Ws[(size_t)k * dout + j];
            else {
                int r = (k < 2 * din) ? (k - din) : (din + (k - 2 * din));
                v = Wd[((size_t)d * (din + 6) + r) * dout + j];
            }
        }
        g_Wc[idx] = v;
    }
}

__global__ void build_bias_kernel(const float* __restrict__ bs, const float* __restrict__ bd,
                                  int dout)
{
    int idx = blockIdx.x * blockDim.x + threadIdx.x;
    if (idx >= 4 * 512) return;
    int d = idx >> 9, j = idx & 511;
    g_bc[idx] = (j < dout) ? (bs[j] + bd[d * dout + j]) : 0.f;
}

// ---------------- build A = [x | sum(x[nbrs]) | sum(bond[bnbrs])], zero pad to LDA ----------------
// one warp per atom
__global__ void build_A_kernel(const float* __restrict__ x, int ldx, int din,
                               const float* __restrict__ bond,
                               const int* __restrict__ an1, const int* __restrict__ an2,
                               const int* __restrict__ an3, const int* __restrict__ an4,
                               const int* __restrict__ bn1, const int* __restrict__ bn2,
                               const int* __restrict__ bn3, const int* __restrict__ bn4,
                               int n1, int n2, int n3)
{
    int gw   = (blockIdx.x * blockDim.x + threadIdx.x) >> 5;
    int lane = threadIdx.x & 31;
    if (gw >= NATOMS) return;
    int i = gw;
    int d, r;
    const int* an; const int* bn;
    if (i < n1)                { d = 1; r = i;                 an = an1; bn = bn1; }
    else if (i < n1 + n2)      { d = 2; r = i - n1;            an = an2; bn = bn2; }
    else if (i < n1 + n2 + n3) { d = 3; r = i - n1 - n2;       an = an3; bn = bn3; }
    else                       { d = 4; r = i - n1 - n2 - n3;  an = an4; bn = bn4; }

    int nb0 = an[(size_t)r * d];
    int nb1 = (d > 1) ? an[(size_t)r * d + 1] : 0;
    int nb2 = (d > 2) ? an[(size_t)r * d + 2] : 0;
    int nb3 = (d > 3) ? an[(size_t)r * d + 3] : 0;

    float* Ar = g_A + (size_t)i * LDA;
    const float* xs = x + (size_t)i   * ldx;
    const float* p0 = x + (size_t)nb0 * ldx;
    const float* p1 = x + (size_t)nb1 * ldx;
    const float* p2 = x + (size_t)nb2 * ldx;
    const float* p3 = x + (size_t)nb3 * ldx;

    for (int c = lane; c < din; c += 32) {
        float s = p0[c];
        if (d > 1) s += p1[c];
        if (d > 2) s += p2[c];
        if (d > 3) s += p3[c];
        Ar[c]       = xs[c];
        Ar[din + c] = s;
    }
    if (lane < 6) {
        float s = 0.f;
        #pragma unroll
        for (int j = 0; j < 4; j++)
            if (j < d) s += bond[(size_t)bn[(size_t)r * d + j] * 6 + lane];
        Ar[2 * din + lane] = s;
    }
    for (int c = 2 * din + 6 + lane; c < LDA; c += 32) Ar[c] = 0.f;
}

// ---------------- fp32 SGEMM, BM=BN=128, BK=8, 256 threads, 8x8 per thread, fused bias ----------------
// A: [M, LDA] (K zero-padded)   B: [KPAD, ldb] (zero-padded)   C: [M, ldc]
__global__ __launch_bounds__(256)
void sgemm_bias_kernel(const float* __restrict__ A, const float* __restrict__ B,
                       const float* __restrict__ bias, float* __restrict__ C,
                       int M, int N, int ldc, int ldb, int Ktiles)
{
    __shared__ float As[8][128];
    __shared__ float Bs[8][128];
    int tid = threadIdx.x;
    int tx = tid & 15, ty = tid >> 4;
    int row0 = blockIdx.y * 128;
    int col0 = blockIdx.x * 128;

    int aRow = tid >> 1, aCol = (tid & 1) << 2;
    int bRow = tid >> 5, bCol = (tid & 31) << 2;
    const float* Ap = A + (size_t)(row0 + aRow) * LDA + aCol;
    const float* Bp = B + (size_t)bRow * ldb + col0 + bCol;
    bool aValid = (row0 + aRow) < M;

    float acc[8][8];
    #pragma unroll
    for (int m = 0; m < 8; m++)
        #pragma unroll
        for (int n = 0; n < 8; n++) acc[m][n] = 0.f;

    for (int kt = 0; kt < Ktiles; kt++) {
        float4 av = make_float4(0.f, 0.f, 0.f, 0.f);
        if (aValid) av = *reinterpret_cast<const float4*>(Ap);
        float4 bv = *reinterpret_cast<const float4*>(Bp);
        __syncthreads();
        As[aCol + 0][aRow] = av.x;
        As[aCol + 1][aRow] = av.y;
        As[aCol + 2][aRow] = av.z;
        As[aCol + 3][aRow] = av.w;
        *reinterpret_cast<float4*>(&Bs[bRow][bCol]) = bv;
        __syncthreads();
        #pragma unroll
        for (int k = 0; k < 8; k++) {
            float a[8], b[8];
            #pragma unroll
            for (int m = 0; m < 8; m++) a[m] = As[k][ty * 8 + m];
            #pragma unroll
            for (int n = 0; n < 8; n++) b[n] = Bs[k][tx * 8 + n];
            #pragma unroll
            for (int m = 0; m < 8; m++)
                #pragma unroll
                for (int n = 0; n < 8; n++)
                    acc[m][n] += a[m] * b[n];
        }
        Ap += 8;
        Bp += (size_t)8 * ldb;
    }

    #pragma unroll
    for (int m = 0; m < 8; m++) {
        int r = row0 + ty * 8 + m;
        if (r < M) {
            #pragma unroll
            for (int n = 0; n < 8; n++) {
                int c = col0 + tx * 8 + n;
                if (c < N) C[(size_t)r * ldc + c] = acc[m][n] + bias[c];
            }
        }
    }
}

// ---------------- normalize + relu for dout=100 layers: warp per atom, T->X ----------------
__global__ void norm_relu_kernel()
{
    int gw   = (blockIdx.x * blockDim.x + threadIdx.x) >> 5;
    int lane = threadIdx.x & 31;
    if (gw >= NATOMS) return;
    const float* t = g_T + (size_t)gw * 100;
    float v0 = t[lane];
    float v1 = t[lane + 32];
    float v2 = t[lane + 64];
    float v3 = (lane < 4) ? t[lane + 96] : 0.f;
    float ss = v0 * v0 + v1 * v1 + v2 * v2 + v3 * v3;
    #pragma unroll
    for (int o = 16; o; o >>= 1) ss += __shfl_xor_sync(0xffffffffu, ss, o);
    float inv = 1.f / fmaxf(sqrtf(ss), 1e-12f);
    float* xo = g_X + (size_t)gw * 100;
    xo[lane]      = fmaxf(v0 * inv, 0.f);
    xo[lane + 32] = fmaxf(v1 * inv, 0.f);
    xo[lane + 64] = fmaxf(v2 * inv, 0.f);
    if (lane < 4) xo[lane + 96] = fmaxf(v3 * inv, 0.f);
}

// ---------------- layer-2 normalize + relu + molecule segment-sum (20 contiguous atoms/mol) ----------------
__global__ void molsum_kernel(float* __restrict__ out)
{
    int m   = blockIdx.x;
    int tid = threadIdx.x;
    __shared__ float red[256];
    __shared__ float s_inv;
    float acc0 = 0.f, acc1 = 0.f;
    const float* base = g_T + (size_t)m * 20 * 512;
    for (int a = 0; a < 20; a++) {
        const float* row = base + a * 512;
        float t0 = row[tid];
        float t1 = row[tid + 256];
        red[tid] = t0 * t0 + t1 * t1;
        __syncthreads();
        #pragma unroll
        for (int s = 128; s >= 32; s >>= 1) {
            if (tid < s) red[tid] += red[tid + s];
            __syncthreads();
        }
        if (tid < 32) {
            float v = red[tid];
            #pragma unroll
            for (int o = 16; o; o >>= 1) v += __shfl_xor_sync(0xffffffffu, v, o);
            if (tid == 0) s_inv = 1.f / fmaxf(sqrtf(v), 1e-12f);
        }
        __syncthreads();
        float inv = s_inv;
        acc0 += fmaxf(t0 * inv, 0.f);
        acc1 += fmaxf(t1 * inv, 0.f);
        __syncthreads();   // protect red[]/s_inv before next iteration
    }
    out[(size_t)m * 512 + tid]       = acc0;
    out[(size_t)m * 512 + 256 + tid] = acc1;
}

// ---------------- host ----------------
extern "C" void kernel_launch(void* const* d_in, const int* in_sizes, int n_in,
                              void* d_out, int out_size)
{
    const float* atom = (const float*)d_in[0];
    const float* bond = (const float*)d_in[1];
    const int*   an[4];
    const int*   bn[4];
    const float *Ws[3], *bsv[3], *Wd[3], *bdv[3];
    int n1, n2, n3, n4;

    // Detect input ordering: reference-signature order vs setup_inputs dict order.
    // sig:  [2..5]=an1..an4, [6..9]=bn1..bn4   -> in_sizes[3] = 350000 (an2)
    // dict: [2]=an1,[3]=bn1,[4]=an2,[5]=bn2... -> in_sizes[3] = 100000 (bn1) == in_sizes[2]
    bool dictOrder = (in_sizes[3] == in_sizes[2]);
    if (!dictOrder) {
        for (int i = 0; i < 4; i++) { an[i] = (const int*)d_in[2 + i]; bn[i] = (const int*)d_in[6 + i]; }
        n1 = in_sizes[2]; n2 = in_sizes[3] / 2; n3 = in_sizes[4] / 3; n4 = in_sizes[5] / 4;
        Ws[0] = (const float*)d_in[11]; bsv[0] = (const float*)d_in[12];
        Ws[1] = (const float*)d_in[13]; bsv[1] = (const float*)d_in[14];
        Ws[2] = (const float*)d_in[15]; bsv[2] = (const float*)d_in[16];
        Wd[0] = (const float*)d_in[17]; bdv[0] = (const float*)d_in[18];
        Wd[1] = (const float*)d_in[19]; bdv[1] = (const float*)d_in[20];
        Wd[2] = (const float*)d_in[21]; bdv[2] = (const float*)d_in[22];
    } else {
        for (int i = 0; i < 4; i++) { an[i] = (const int*)d_in[2 + 2 * i]; bn[i] = (const int*)d_in[3 + 2 * i]; }
        n1 = in_sizes[2]; n2 = in_sizes[4] / 2; n3 = in_sizes[6] / 3; n4 = in_sizes[8] / 4;
        Ws[0] = (const float*)d_in[11]; bsv[0] = (const float*)d_in[12];
        Wd[0] = (const float*)d_in[13]; bdv[0] = (const float*)d_in[14];
        Ws[1] = (const float*)d_in[15]; bsv[1] = (const float*)d_in[16];
        Wd[1] = (const float*)d_in[17]; bdv[1] = (const float*)d_in[18];
        Ws[2] = (const float*)d_in[19]; bsv[2] = (const float*)d_in[20];
        Wd[2] = (const float*)d_in[21]; bdv[2] = (const float*)d_in[22];
    }

    float *pA, *pT, *pWc, *pbc, *pX;
    cudaGetSymbolAddress((void**)&pA,  g_A);
    cudaGetSymbolAddress((void**)&pT,  g_T);
    cudaGetSymbolAddress((void**)&pX,  g_X);
    cudaGetSymbolAddress((void**)&pWc, g_Wc);
    cudaGetSymbolAddress((void**)&pbc, g_bc);

    const int din_arr[3]  = {62, 100, 100};
    const int dout_arr[3] = {100, 100, 512};
    const int nd[4] = {n1, n2, n3, n4};

    const float* xin = atom;
    int ldx = 62;

    for (int li = 0; li < 3; li++) {
        int din  = din_arr[li];
        int dout = dout_arr[li];
        int K    = 2 * din + 6;
        int ldb  = (dout <= 128) ? 128 : 512;
        int Ktiles = (K + 7) / 8;
        int ldc  = dout;

        build_wcat_kernel<<<832, 512>>>(Ws[li], Wd[li], din, dout, ldb);
        build_bias_kernel<<<8, 256>>>(bsv[li], bdv[li], dout);
        build_A_kernel<<<(NATOMS * 32 + 255) / 256, 256>>>(
            xin, ldx, din, bond,
            an[0], an[1], an[2], an[3],
            bn[0], bn[1], bn[2], bn[3],
            n1, n2, n3);

        int base = 0;
        for (int d = 0; d < 4; d++) {
            dim3 grid((dout + 127) / 128, (nd[d] + 127) / 128);
            sgemm_bias_kernel<<<grid, 256>>>(
                pA + (size_t)base * LDA,
                pWc + (size_t)d * KPAD * ldb,
                pbc + d * 512,
                pT + (size_t)base * ldc,
                nd[d], dout, ldc, ldb, Ktiles);
            base += nd[d];
        }

        if (li < 2) {
            norm_relu_kernel<<<(NATOMS * 32 + 255) / 256, 256>>>();
            xin = pX;
            ldx = 100;
        }
    }

    int nmol = out_size / 512;
    molsum_kernel<<<nmol, 256>>>((float*)d_out);
}

// round 5
// speedup vs baseline: 1.1704x; 1.1704x over previous
#include <cuda_runtime.h>
#include <cstdint>
#include <math.h>

#define NATOMS 500000
#define WT_STRIDE 208   // padded K storage for transposed weights (max K = 206)

// ---------------- scratch (static device globals) ----------------
__device__ float g_T[(size_t)NATOMS * 512];        // 1 GB   pre-norm layer-2 output
__device__ float g_X0[(size_t)NATOMS * 100];       // post-norm x (layer0 out)
__device__ float g_X1[(size_t)NATOMS * 100];       // post-norm x (layer1 out)
__device__ float g_Wt[3 * 4 * 512 * WT_STRIDE];    // transposed concat weights, tf32-rounded
__device__ float g_bc[3 * 4 * 512];                // combined bias (fp32), zero padded

// ---------------- helpers ----------------
__device__ __forceinline__ float to_tf32(float f) {
    uint32_t u;
    asm("cvt.rna.tf32.f32 %0, %1;" : "=r"(u) : "f"(f));
    return __uint_as_float(u);
}

__device__ __forceinline__ void mma8(float& c0, float& c1, float& c2, float& c3,
                                     uint32_t a0, uint32_t a1, uint32_t a2, uint32_t a3,
                                     uint32_t b0, uint32_t b1) {
    asm volatile("mma.sync.aligned.m16n8k8.row.col.f32.tf32.tf32.f32 "
                 "{%0,%1,%2,%3}, {%4,%5,%6,%7}, {%8,%9}, {%0,%1,%2,%3};"
                 : "+f"(c0), "+f"(c1), "+f"(c2), "+f"(c3)
                 : "r"(a0), "r"(a1), "r"(a2), "r"(a3), "r"(b0), "r"(b1));
}

// ---------------- weight / bias prep ----------------
// g_Wt[li][d][n][k] = tf32( Wcat^T ): k<din -> Ws[k][n]; k<2din -> Wd[d][k-din][n];
//                     k<2din+6 -> Wd[d][din + (k-2din)][n]; zero outside.
__global__ void build_wt_kernel(const float* __restrict__ Ws, const float* __restrict__ Wd,
                                int din, int dout, int li)
{
    int total = 4 * 512 * WT_STRIDE;
    int K = 2 * din + 6;
    float* dst = g_Wt + (size_t)li * total;
    for (int idx = blockIdx.x * blockDim.x + threadIdx.x; idx < total; idx += gridDim.x * blockDim.x) {
        int d   = idx / (512 * WT_STRIDE);
        int rem = idx - d * (512 * WT_STRIDE);
        int n   = rem / WT_STRIDE;
        int k   = rem - n * WT_STRIDE;
        float v = 0.f;
        if (n < dout && k < K) {
            if (k < din) v = Ws[(size_t)k * dout + n];
            else {
                int r = (k < 2 * din) ? (k - din) : (din + (k - 2 * din));
                v = Wd[((size_t)d * (din + 6) + r) * dout + n];
            }
            v = to_tf32(v);
        }
        dst[idx] = v;
    }
}

__global__ void build_bias_kernel(const float* __restrict__ bs, const float* __restrict__ bd,
                                  int dout, int li)
{
    int idx = blockIdx.x * blockDim.x + threadIdx.x;
    if (idx >= 4 * 512) return;
    int d = idx >> 9, j = idx & 511;
    g_bc[li * 2048 + idx] = (j < dout) ? (bs[j] + bd[d * dout + j]) : 0.f;
}

// ---------------- fused gather + tf32 mma.sync GEMM + epilogue ----------------
// one launch per (layer, degree). CTA = 128 atoms (M tile), 128-wide N tiles looped inside.
// MODE 0: dout==100, fused bias + L2-normalize + relu -> outp (ld 100)
// MODE 1: bias add -> outp (ld 512) at col nt*128
template<int KPAD, int MODE>
__global__ __launch_bounds__(256)
void fused_gemm_kernel(const float* __restrict__ x, int ldx, int din,
                       const float* __restrict__ bond,
                       const int* __restrict__ an, const int* __restrict__ bn, int deg,
                       int degStart, int M,
                       const float* __restrict__ Wt, const float* __restrict__ bias,
                       int dout, int numNt, float* __restrict__ outp)
{
    constexpr int STR = KPAD + 4;            // smem row stride (floats) — bank-conflict-free
    extern __shared__ float smem[];
    float* sA    = smem;                     // [128][STR]
    float* sB    = smem + 128 * STR;         // [128][STR]
    float* sBias = smem + 2 * 128 * STR;     // [128]

    const int tid  = threadIdx.x;
    const int wid  = tid >> 5;
    const int lane = tid & 31;
    const int grp  = lane >> 2;              // 0..7
    const int tig  = lane & 3;               // 0..3
    const int wm   = wid & 3;                // warp M index (4)
    const int wn   = wid >> 2;               // warp N index (2)
    const int row0 = blockIdx.x * 128;
    const int K    = 2 * din + 6;

    // ---- gather-fill A tile (tf32-rounded): warp handles 16 rows ----
    for (int rr = 0; rr < 16; rr++) {
        int r = wid * 16 + rr;
        int m = row0 + r;
        if (m >= M) continue;
        const float* xs = x + (size_t)(degStart + m) * ldx;
        const int* ai = an + (size_t)m * deg;
        const float* p0 = x + (size_t)ai[0] * ldx;
        const float* p1 = (deg > 1) ? x + (size_t)ai[1] * ldx : p0;
        const float* p2 = (deg > 2) ? x + (size_t)ai[2] * ldx : p0;
        const float* p3 = (deg > 3) ? x + (size_t)ai[3] * ldx : p0;
        float* Ar = sA + r * STR;
        for (int c = lane; c < din; c += 32) {
            float s = p0[c];
            if (deg > 1) s += p1[c];
            if (deg > 2) s += p2[c];
            if (deg > 3) s += p3[c];
            Ar[c]       = to_tf32(xs[c]);
            Ar[din + c] = to_tf32(s);
        }
        if (lane < 6) {
            const int* bi = bn + (size_t)m * deg;
            float s = bond[(size_t)bi[0] * 6 + lane];
            if (deg > 1) s += bond[(size_t)bi[1] * 6 + lane];
            if (deg > 2) s += bond[(size_t)bi[2] * 6 + lane];
            if (deg > 3) s += bond[(size_t)bi[3] * 6 + lane];
            Ar[2 * din + lane] = to_tf32(s);
        }
        // zero K padding (so garbage never reaches valid accumulators)
        for (int c = K + lane; c < KPAD; c += 32) Ar[c] = 0.f;
    }

    const float* paBase = sA + (wm * 32 + grp) * STR + tig;
    const float* pbBase = sB + (wn * 64 + grp) * STR + tig;

    for (int nt = 0; nt < numNt; nt++) {
        const int ncol0 = nt * 128;
        __syncthreads();   // prior iteration's smem reads done before refill

        // fill B tile (already tf32): rows = output features ncol0..+127 (Wt zero-padded)
        {
            const float4* W4 = (const float4*)Wt;
            constexpr int KV4 = KPAD / 4;
            for (int i = tid; i < 128 * KV4; i += 256) {
                int rowb = i / KV4;
                int kc4  = i - rowb * KV4;
                float4 v = W4[(size_t)(ncol0 + rowb) * (WT_STRIDE / 4) + kc4];
                *(float4*)(sB + rowb * STR + kc4 * 4) = v;
            }
            if (tid < 128) sBias[tid] = bias[ncol0 + tid];
        }
        __syncthreads();

        // ---- mma.sync mainloop over full K ----
        float acc[2][8][4];
        #pragma unroll
        for (int mf = 0; mf < 2; mf++)
            #pragma unroll
            for (int nf = 0; nf < 8; nf++)
                #pragma unroll
                for (int q = 0; q < 4; q++) acc[mf][nf][q] = 0.f;

        #pragma unroll 2
        for (int k0 = 0; k0 < KPAD; k0 += 8) {
            uint32_t a[2][4], b[8][2];
            #pragma unroll
            for (int mf = 0; mf < 2; mf++) {
                a[mf][0] = __float_as_uint(paBase[(mf * 16    ) * STR + k0    ]);
                a[mf][1] = __float_as_uint(paBase[(mf * 16 + 8) * STR + k0    ]);
                a[mf][2] = __float_as_uint(paBase[(mf * 16    ) * STR + k0 + 4]);
                a[mf][3] = __float_as_uint(paBase[(mf * 16 + 8) * STR + k0 + 4]);
            }
            #pragma unroll
            for (int nf = 0; nf < 8; nf++) {
                b[nf][0] = __float_as_uint(pbBase[(nf * 8) * STR + k0    ]);
                b[nf][1] = __float_as_uint(pbBase[(nf * 8) * STR + k0 + 4]);
            }
            #pragma unroll
            for (int mf = 0; mf < 2; mf++)
                #pragma unroll
                for (int nf = 0; nf < 8; nf++)
                    mma8(acc[mf][nf][0], acc[mf][nf][1], acc[mf][nf][2], acc[mf][nf][3],
                         a[mf][0], a[mf][1], a[mf][2], a[mf][3], b[nf][0], b[nf][1]);
        }

        if (MODE == 1) {
            // direct store with bias: rows (wm*32+mf*16+grp [+8]), cols (wn*64+nf*8+2*tig [+1])
            #pragma unroll
            for (int mf = 0; mf < 2; mf++) {
                int r = wm * 32 + mf * 16 + grp;
                #pragma unroll
                for (int nf = 0; nf < 8; nf++) {
                    int c = wn * 64 + nf * 8 + 2 * tig;
                    float b0v = sBias[c], b1v = sBias[c + 1];
                    if (row0 + r < M) {
                        float2 w = make_float2(acc[mf][nf][0] + b0v, acc[mf][nf][1] + b1v);
                        *(float2*)(outp + (size_t)(degStart + row0 + r) * 512 + ncol0 + c) = w;
                    }
                    if (row0 + r + 8 < M) {
                        float2 w = make_float2(acc[mf][nf][2] + b0v, acc[mf][nf][3] + b1v);
                        *(float2*)(outp + (size_t)(degStart + row0 + r + 8) * 512 + ncol0 + c) = w;
                    }
                }
            }
        } else {
            // stage t = acc + bias into sA (A panel no longer needed), then row-norm
            __syncthreads();
            #pragma unroll
            for (int mf = 0; mf < 2; mf++) {
                int r = wm * 32 + mf * 16 + grp;
                #pragma unroll
                for (int nf = 0; nf < 8; nf++) {
                    int c = wn * 64 + nf * 8 + 2 * tig;
                    float b0v = sBias[c], b1v = sBias[c + 1];
                    sA[r * STR + c]           = acc[mf][nf][0] + b0v;
                    sA[r * STR + c + 1]       = acc[mf][nf][1] + b1v;
                    sA[(r + 8) * STR + c]     = acc[mf][nf][2] + b0v;
                    sA[(r + 8) * STR + c + 1] = acc[mf][nf][3] + b1v;
                }
            }
            __syncthreads();
            // warp wid handles rows wid*16 .. wid*16+15 (dout == 100)
            for (int rr = 0; rr < 16; rr++) {
                int r = wid * 16 + rr;
                int m = row0 + r;
                if (m >= M) continue;
                const float* tr = sA + r * STR;
                float v0 = tr[lane];
                float v1 = tr[lane + 32];
                float v2 = tr[lane + 64];
                float v3 = (lane < 4) ? tr[lane + 96] : 0.f;
                float ss = v0 * v0 + v1 * v1 + v2 * v2 + v3 * v3;
                #pragma unroll
                for (int o = 16; o; o >>= 1) ss += __shfl_xor_sync(0xffffffffu, ss, o);
                float inv = 1.f / fmaxf(sqrtf(ss), 1e-12f);
                float* o = outp + (size_t)(degStart + m) * 100;
                o[lane]      = fmaxf(v0 * inv, 0.f);
                o[lane + 32] = fmaxf(v1 * inv, 0.f);
                o[lane + 64] = fmaxf(v2 * inv, 0.f);
                if (lane < 4) o[lane + 96] = fmaxf(v3 * inv, 0.f);
            }
        }
    }
}

// ---------------- layer-2 normalize + relu + molecule segment-sum (20 atoms/mol contiguous) ----------------
__global__ void molsum_kernel(float* __restrict__ out)
{
    int m   = blockIdx.x;
    int tid = threadIdx.x;
    __shared__ float red[256];
    __shared__ float s_inv;
    float acc0 = 0.f, acc1 = 0.f;
    const float* base = g_T + (size_t)m * 20 * 512;
    for (int a = 0; a < 20; a++) {
        const float* row = base + a * 512;
        float t0 = row[tid];
        float t1 = row[tid + 256];
        red[tid] = t0 * t0 + t1 * t1;
        __syncthreads();
        #pragma unroll
        for (int s = 128; s >= 32; s >>= 1) {
            if (tid < s) red[tid] += red[tid + s];
            __syncthreads();
        }
        if (tid < 32) {
            float v = red[tid];
            #pragma unroll
            for (int o = 16; o; o >>= 1) v += __shfl_xor_sync(0xffffffffu, v, o);
            if (tid == 0) s_inv = 1.f / fmaxf(sqrtf(v), 1e-12f);
        }
        __syncthreads();
        float inv = s_inv;
        acc0 += fmaxf(t0 * inv, 0.f);
        acc1 += fmaxf(t1 * inv, 0.f);
        __syncthreads();
    }
    out[(size_t)m * 512 + tid]       = acc0;
    out[(size_t)m * 512 + 256 + tid] = acc1;
}

// ---------------- host ----------------
extern "C" void kernel_launch(void* const* d_in, const int* in_sizes, int n_in,
                              void* d_out, int out_size)
{
    const float* atom = (const float*)d_in[0];
    const float* bond = (const float*)d_in[1];
    const int*   an[4];
    const int*   bn[4];
    const float *Ws[3], *bsv[3], *Wd[3], *bdv[3];
    int n1, n2, n3, n4;

    bool dictOrder = (in_sizes[3] == in_sizes[2]);
    if (!dictOrder) {
        for (int i = 0; i < 4; i++) { an[i] = (const int*)d_in[2 + i]; bn[i] = (const int*)d_in[6 + i]; }
        n1 = in_sizes[2]; n2 = in_sizes[3] / 2; n3 = in_sizes[4] / 3; n4 = in_sizes[5] / 4;
        Ws[0] = (const float*)d_in[11]; bsv[0] = (const float*)d_in[12];
        Ws[1] = (const float*)d_in[13]; bsv[1] = (const float*)d_in[14];
        Ws[2] = (const float*)d_in[15]; bsv[2] = (const float*)d_in[16];
        Wd[0] = (const float*)d_in[17]; bdv[0] = (const float*)d_in[18];
        Wd[1] = (const float*)d_in[19]; bdv[1] = (const float*)d_in[20];
        Wd[2] = (const float*)d_in[21]; bdv[2] = (const float*)d_in[22];
    } else {
        for (int i = 0; i < 4; i++) { an[i] = (const int*)d_in[2 + 2 * i]; bn[i] = (const int*)d_in[3 + 2 * i]; }
        n1 = in_sizes[2]; n2 = in_sizes[4] / 2; n3 = in_sizes[6] / 3; n4 = in_sizes[8] / 4;
        Ws[0] = (const float*)d_in[11]; bsv[0] = (const float*)d_in[12];
        Wd[0] = (const float*)d_in[13]; bdv[0] = (const float*)d_in[14];
        Ws[1] = (const float*)d_in[15]; bsv[1] = (const float*)d_in[16];
        Wd[1] = (const float*)d_in[17]; bdv[1] = (const float*)d_in[18];
        Ws[2] = (const float*)d_in[19]; bsv[2] = (const float*)d_in[20];
        Wd[2] = (const float*)d_in[21]; bdv[2] = (const float*)d_in[22];
    }

    float *pT, *pX0, *pX1, *pWt, *pbc;
    cudaGetSymbolAddress((void**)&pT,  g_T);
    cudaGetSymbolAddress((void**)&pX0, g_X0);
    cudaGetSymbolAddress((void**)&pX1, g_X1);
    cudaGetSymbolAddress((void**)&pWt, g_Wt);
    cudaGetSymbolAddress((void**)&pbc, g_bc);

    const int din_arr[3]  = {62, 100, 100};
    const int dout_arr[3] = {100, 100, 512};
    const int nd[4] = {n1, n2, n3, n4};
    const int degStart[4] = {0, n1, n1 + n2, n1 + n2 + n3};

    for (int li = 0; li < 3; li++) {
        build_wt_kernel<<<1664, 256>>>(Ws[li], Wd[li], din_arr[li], dout_arr[li], li);
        build_bias_kernel<<<8, 256>>>(bsv[li], bdv[li], dout_arr[li], li);
    }

    // smem: 2*128*(KPAD+4) + 128 floats
    const int smem0  = (2 * 128 * 140 + 128) * 4;   // 143,872  (KPAD=136)
    const int smem12 = (2 * 128 * 212 + 128) * 4;   // 217,600  (KPAD=208)
    cudaFuncSetAttribute(fused_gemm_kernel<136, 0>, cudaFuncAttributeMaxDynamicSharedMemorySize, smem0);
    cudaFuncSetAttribute(fused_gemm_kernel<208, 0>, cudaFuncAttributeMaxDynamicSharedMemorySize, smem12);
    cudaFuncSetAttribute(fused_gemm_kernel<208, 1>, cudaFuncAttributeMaxDynamicSharedMemorySize, smem12);

    const float* xin = atom;
    int ldx = 62;
    float* xbuf[2] = {pX0, pX1};

    for (int li = 0; li < 3; li++) {
        int din  = din_arr[li];
        int dout = dout_arr[li];
        float* outp = (li < 2) ? xbuf[li] : pT;
        int numNt = (li < 2) ? 1 : 4;

        for (int d = 0; d < 4; d++) {
            if (nd[d] <= 0) continue;
            int grid = (nd[d] + 127) / 128;
            const float* WtD = pWt + (size_t)li * (4 * 512 * WT_STRIDE) + (size_t)d * (512 * WT_STRIDE);
            const float* bD  = pbc + li * 2048 + d * 512;
            if (li == 0)
                fused_gemm_kernel<136, 0><<<grid, 256, smem0>>>(
                    xin, ldx, din, bond, an[d], bn[d], d + 1,
                    degStart[d], nd[d], WtD, bD, dout, numNt, outp);
            else if (li == 1)
                fused_gemm_kernel<208, 0><<<grid, 256, smem12>>>(
                    xin, ldx, din, bond, an[d], bn[d], d + 1,
                    degStart[d], nd[d], WtD, bD, dout, numNt, outp);
            else
                fused_gemm_kernel<208, 1><<<grid, 256, smem12>>>(
                    xin, ldx, din, bond, an[d], bn[d], d + 1,
                    degStart[d], nd[d], WtD, bD, dout, numNt, outp);
        }
        if (li < 2) { xin = xbuf[li]; ldx = 100; }
    }

    int nmol = out_size / 512;
    molsum_kernel<<<nmol, 256>>>((float*)d_out);
}

// round 6
// speedup vs baseline: 1.2441x; 1.0629x over previous
#include <cuda_runtime.h>
#include <cstdint>
#include <math.h>

#define NATOMS 500000
#define WT_STRIDE 208   // padded K storage for transposed weights (max K = 206)

// ---------------- scratch (static device globals) ----------------
__device__ float g_T[(size_t)NATOMS * 512];        // 1 GB   pre-norm layer-2 output
__device__ float g_X0[(size_t)NATOMS * 100];       // post-norm x (layer0 out)
__device__ float g_X1[(size_t)NATOMS * 100];       // post-norm x (layer1 out)
__device__ float g_inv[NATOMS];                    // layer-2 per-atom 1/||t||
__device__ float g_Wt[3 * 4 * 512 * WT_STRIDE];    // transposed concat weights, tf32-rounded
__device__ float g_bc[3 * 4 * 512];                // combined bias (fp32), zero padded

// ---------------- helpers ----------------
__device__ __forceinline__ float to_tf32(float f) {
    uint32_t u;
    asm("cvt.rna.tf32.f32 %0, %1;" : "=r"(u) : "f"(f));
    return __uint_as_float(u);
}

__device__ __forceinline__ uint32_t smem_u32(const void* p) {
    uint32_t a;
    asm("{ .reg .u64 t; cvta.to.shared.u64 t, %1; cvt.u32.u64 %0, t; }" : "=r"(a) : "l"(p));
    return a;
}

__device__ __forceinline__ void cp_async16(uint32_t saddr, const void* gptr) {
    asm volatile("cp.async.cg.shared.global [%0], [%1], 16;" :: "r"(saddr), "l"(gptr));
}
__device__ __forceinline__ void cp_async_commit_wait() {
    asm volatile("cp.async.commit_group;");
    asm volatile("cp.async.wait_group 0;" ::: "memory");
}

__device__ __forceinline__ void mma8(float& c0, float& c1, float& c2, float& c3,
                                     uint32_t a0, uint32_t a1, uint32_t a2, uint32_t a3,
                                     uint32_t b0, uint32_t b1) {
    asm volatile("mma.sync.aligned.m16n8k8.row.col.f32.tf32.tf32.f32 "
                 "{%0,%1,%2,%3}, {%4,%5,%6,%7}, {%8,%9}, {%0,%1,%2,%3};"
                 : "+f"(c0), "+f"(c1), "+f"(c2), "+f"(c3)
                 : "r"(a0), "r"(a1), "r"(a2), "r"(a3), "r"(b0), "r"(b1));
}

// ---------------- single-launch weight + bias prep (all 3 layers) ----------------
// g_Wt[li][d][n][k] = tf32( Wcat^T ): k<din -> Ws[k][n]; k<2din -> Wd[d][k-din][n];
//                     k<2din+6 -> Wd[d][din + (k-2din)][n]; zero outside.
__global__ void prep_kernel(const float* __restrict__ Ws0, const float* __restrict__ Wd0,
                            const float* __restrict__ bs0, const float* __restrict__ bd0,
                            const float* __restrict__ Ws1, const float* __restrict__ Wd1,
                            const float* __restrict__ bs1, const float* __restrict__ bd1,
                            const float* __restrict__ Ws2, const float* __restrict__ Wd2,
                            const float* __restrict__ bs2, const float* __restrict__ bd2)
{
    const float* Ws[3] = {Ws0, Ws1, Ws2};
    const float* Wd[3] = {Wd0, Wd1, Wd2};
    const float* bs[3] = {bs0, bs1, bs2};
    const float* bd[3] = {bd0, bd1, bd2};
    const int din_arr[3]  = {62, 100, 100};
    const int dout_arr[3] = {100, 100, 512};

    const int perL = 4 * 512 * WT_STRIDE;
    const int total = 3 * perL;
    for (int idx = blockIdx.x * blockDim.x + threadIdx.x; idx < total; idx += gridDim.x * blockDim.x) {
        int li  = idx / perL;
        int rem = idx - li * perL;
        int d   = rem / (512 * WT_STRIDE);
        int r2  = rem - d * (512 * WT_STRIDE);
        int n   = r2 / WT_STRIDE;
        int k   = r2 - n * WT_STRIDE;
        int din = din_arr[li], dout = dout_arr[li];
        int K = 2 * din + 6;
        float v = 0.f;
        if (n < dout && k < K) {
            if (k < din) v = Ws[li][(size_t)k * dout + n];
            else {
                int r = (k < 2 * din) ? (k - din) : (din + (k - 2 * din));
                v = Wd[li][((size_t)d * (din + 6) + r) * dout + n];
            }
            v = to_tf32(v);
        }
        g_Wt[idx] = v;
    }
    // biases: 3 * 4 * 512 entries
    for (int idx = blockIdx.x * blockDim.x + threadIdx.x; idx < 3 * 2048; idx += gridDim.x * blockDim.x) {
        int li = idx / 2048;
        int r  = idx - li * 2048;
        int d  = r >> 9, j = r & 511;
        int dout = dout_arr[li];
        g_bc[idx] = (j < dout) ? (bs[li][j] + bd[li][d * dout + j]) : 0.f;
    }
}

// ---------------- fused gather + tf32 mma.sync GEMM + epilogue ----------------
// one launch per (layer, degree). CTA = 128 atoms (M tile), 128-wide N tiles looped inside.
// MODE 0: dout==100, fused bias + L2-normalize + relu -> outp (ld 100)
// MODE 1: bias add -> outp (ld 512) at col nt*128; accumulate row sum-of-squares -> g_inv
template<int KPAD, int MODE>
__global__ __launch_bounds__(256)
void fused_gemm_kernel(const float* __restrict__ x, int ldx, int din,
                       const float* __restrict__ bond,
                       const int* __restrict__ an, const int* __restrict__ bn, int deg,
                       int degStart, int M,
                       const float* __restrict__ Wt, const float* __restrict__ bias,
                       int dout, int numNt, float* __restrict__ outp)
{
    constexpr int STR = KPAD + 4;            // smem row stride (floats) — bank-conflict-free
    extern __shared__ float smem[];
    float* sA    = smem;                     // [128][STR]
    float* sB    = smem + 128 * STR;         // [128][STR]
    float* sBias = smem + 2 * 128 * STR;     // [128]
    float* sSS   = sBias + 128;              // [128] per-row sum of squares (MODE 1)
    const uint32_t sBu = smem_u32(sB);

    const int tid  = threadIdx.x;
    const int wid  = tid >> 5;
    const int lane = tid & 31;
    const int grp  = lane >> 2;              // 0..7
    const int tig  = lane & 3;               // 0..3
    const int wm   = wid & 3;                // warp M index (4)
    const int wn   = wid >> 2;               // warp N index (2)
    const int row0 = blockIdx.x * 128;
    const int K    = 2 * din + 6;

    if (MODE == 1 && tid < 128) sSS[tid] = 0.f;

    // ---- gather-fill A tile (tf32-rounded): warp handles 16 rows ----
    #pragma unroll 2
    for (int rr = 0; rr < 16; rr++) {
        int r = wid * 16 + rr;
        int m = row0 + r;
        if (m >= M) continue;
        const float* xs = x + (size_t)(degStart + m) * ldx;
        const int* ai = an + (size_t)m * deg;
        const float* p0 = x + (size_t)ai[0] * ldx;
        const float* p1 = (deg > 1) ? x + (size_t)ai[1] * ldx : p0;
        const float* p2 = (deg > 2) ? x + (size_t)ai[2] * ldx : p0;
        const float* p3 = (deg > 3) ? x + (size_t)ai[3] * ldx : p0;
        float* Ar = sA + r * STR;
        for (int c = lane; c < din; c += 32) {
            float s = p0[c];
            if (deg > 1) s += p1[c];
            if (deg > 2) s += p2[c];
            if (deg > 3) s += p3[c];
            Ar[c]       = to_tf32(xs[c]);
            Ar[din + c] = to_tf32(s);
        }
        if (lane < 6) {
            const int* bi = bn + (size_t)m * deg;
            float s = bond[(size_t)bi[0] * 6 + lane];
            if (deg > 1) s += bond[(size_t)bi[1] * 6 + lane];
            if (deg > 2) s += bond[(size_t)bi[2] * 6 + lane];
            if (deg > 3) s += bond[(size_t)bi[3] * 6 + lane];
            Ar[2 * din + lane] = to_tf32(s);
        }
        // zero K padding (so garbage never reaches valid accumulators)
        for (int c = K + lane; c < KPAD; c += 32) Ar[c] = 0.f;
    }

    const float* paBase = sA + (wm * 32 + grp) * STR + tig;
    const float* pbBase = sB + (wn * 64 + grp) * STR + tig;

    for (int nt = 0; nt < numNt; nt++) {
        const int ncol0 = nt * 128;
        __syncthreads();   // prior iteration's smem reads done before refill

        // fill B tile via cp.async (Wt rows zero-padded to 512)
        {
            const float4* W4 = (const float4*)Wt;
            constexpr int KV4 = KPAD / 4;
            for (int i = tid; i < 128 * KV4; i += 256) {
                int rowb = i / KV4;
                int kc4  = i - rowb * KV4;
                cp_async16(sBu + (uint32_t)(rowb * STR + kc4 * 4) * 4,
                           W4 + (size_t)(ncol0 + rowb) * (WT_STRIDE / 4) + kc4);
            }
            if (tid < 128) sBias[tid] = bias[ncol0 + tid];
            cp_async_commit_wait();
        }
        __syncthreads();

        // ---- mma.sync mainloop over full K ----
        float acc[2][8][4];
        #pragma unroll
        for (int mf = 0; mf < 2; mf++)
            #pragma unroll
            for (int nf = 0; nf < 8; nf++)
                #pragma unroll
                for (int q = 0; q < 4; q++) acc[mf][nf][q] = 0.f;

        #pragma unroll 4
        for (int k0 = 0; k0 < KPAD; k0 += 8) {
            uint32_t a[2][4], b[8][2];
            #pragma unroll
            for (int mf = 0; mf < 2; mf++) {
                a[mf][0] = __float_as_uint(paBase[(mf * 16    ) * STR + k0    ]);
                a[mf][1] = __float_as_uint(paBase[(mf * 16 + 8) * STR + k0    ]);
                a[mf][2] = __float_as_uint(paBase[(mf * 16    ) * STR + k0 + 4]);
                a[mf][3] = __float_as_uint(paBase[(mf * 16 + 8) * STR + k0 + 4]);
            }
            #pragma unroll
            for (int nf = 0; nf < 8; nf++) {
                b[nf][0] = __float_as_uint(pbBase[(nf * 8) * STR + k0    ]);
                b[nf][1] = __float_as_uint(pbBase[(nf * 8) * STR + k0 + 4]);
            }
            #pragma unroll
            for (int mf = 0; mf < 2; mf++)
                #pragma unroll
                for (int nf = 0; nf < 8; nf++)
                    mma8(acc[mf][nf][0], acc[mf][nf][1], acc[mf][nf][2], acc[mf][nf][3],
                         a[mf][0], a[mf][1], a[mf][2], a[mf][3], b[nf][0], b[nf][1]);
        }

        if (MODE == 1) {
            // direct store with bias + per-row sum-of-squares accumulation
            #pragma unroll
            for (int mf = 0; mf < 2; mf++) {
                int r = wm * 32 + mf * 16 + grp;
                float ss0 = 0.f, ss1 = 0.f;
                #pragma unroll
                for (int nf = 0; nf < 8; nf++) {
                    int c = wn * 64 + nf * 8 + 2 * tig;
                    float b0v = sBias[c], b1v = sBias[c + 1];
                    float t0 = acc[mf][nf][0] + b0v, t1 = acc[mf][nf][1] + b1v;
                    float t2 = acc[mf][nf][2] + b0v, t3 = acc[mf][nf][3] + b1v;
                    ss0 += t0 * t0 + t1 * t1;
                    ss1 += t2 * t2 + t3 * t3;
                    if (row0 + r < M)
                        *(float2*)(outp + (size_t)(degStart + row0 + r) * 512 + ncol0 + c)
                            = make_float2(t0, t1);
                    if (row0 + r + 8 < M)
                        *(float2*)(outp + (size_t)(degStart + row0 + r + 8) * 512 + ncol0 + c)
                            = make_float2(t2, t3);
                }
                if (row0 + r < M)     atomicAdd(&sSS[r], ss0);
                if (row0 + r + 8 < M) atomicAdd(&sSS[r + 8], ss1);
            }
        } else {
            // stage t = acc + bias into sA (A panel no longer needed), then row-norm
            __syncthreads();
            #pragma unroll
            for (int mf = 0; mf < 2; mf++) {
                int r = wm * 32 + mf * 16 + grp;
                #pragma unroll
                for (int nf = 0; nf < 8; nf++) {
                    int c = wn * 64 + nf * 8 + 2 * tig;
                    float b0v = sBias[c], b1v = sBias[c + 1];
                    sA[r * STR + c]           = acc[mf][nf][0] + b0v;
                    sA[r * STR + c + 1]       = acc[mf][nf][1] + b1v;
                    sA[(r + 8) * STR + c]     = acc[mf][nf][2] + b0v;
                    sA[(r + 8) * STR + c + 1] = acc[mf][nf][3] + b1v;
                }
            }
            __syncthreads();
            // warp wid handles rows wid*16 .. wid*16+15 (dout == 100)
            for (int rr = 0; rr < 16; rr++) {
                int r = wid * 16 + rr;
                int m = row0 + r;
                if (m >= M) continue;
                const float* tr = sA + r * STR;
                float v0 = tr[lane];
                float v1 = tr[lane + 32];
                float v2 = tr[lane + 64];
                float v3 = (lane < 4) ? tr[lane + 96] : 0.f;
                float ss = v0 * v0 + v1 * v1 + v2 * v2 + v3 * v3;
                #pragma unroll
                for (int o = 16; o; o >>= 1) ss += __shfl_xor_sync(0xffffffffu, ss, o);
                float inv = 1.f / fmaxf(sqrtf(ss), 1e-12f);
                float* o = outp + (size_t)(degStart + m) * 100;
                o[lane]      = fmaxf(v0 * inv, 0.f);
                o[lane + 32] = fmaxf(v1 * inv, 0.f);
                o[lane + 64] = fmaxf(v2 * inv, 0.f);
                if (lane < 4) o[lane + 96] = fmaxf(v3 * inv, 0.f);
            }
        }
    }

    if (MODE == 1) {
        __syncthreads();
        if (tid < 128 && row0 + tid < M)
            g_inv[degStart + row0 + tid] = 1.f / fmaxf(sqrtf(sSS[tid]), 1e-12f);
    }
}

// ---------------- layer-2 relu(t * inv) + molecule segment-sum (pure streaming) ----------------
__global__ void molsum_kernel(float* __restrict__ out)
{
    int m   = blockIdx.x;
    int tid = threadIdx.x;
    float acc0 = 0.f, acc1 = 0.f;
    const float* base = g_T + (size_t)m * 20 * 512;
    #pragma unroll 4
    for (int a = 0; a < 20; a++) {
        const float* row = base + a * 512;
        float inv = g_inv[m * 20 + a];
        acc0 += fmaxf(row[tid]       * inv, 0.f);
        acc1 += fmaxf(row[tid + 256] * inv, 0.f);
    }
    out[(size_t)m * 512 + tid]       = acc0;
    out[(size_t)m * 512 + 256 + tid] = acc1;
}

// ---------------- host ----------------
extern "C" void kernel_launch(void* const* d_in, const int* in_sizes, int n_in,
                              void* d_out, int out_size)
{
    const float* atom = (const float*)d_in[0];
    const float* bond = (const float*)d_in[1];
    const int*   an[4];
    const int*   bn[4];
    const float *Ws[3], *bsv[3], *Wd[3], *bdv[3];
    int n1, n2, n3, n4;

    bool dictOrder = (in_sizes[3] == in_sizes[2]);
    if (!dictOrder) {
        for (int i = 0; i < 4; i++) { an[i] = (const int*)d_in[2 + i]; bn[i] = (const int*)d_in[6 + i]; }
        n1 = in_sizes[2]; n2 = in_sizes[3] / 2; n3 = in_sizes[4] / 3; n4 = in_sizes[5] / 4;
        Ws[0] = (const float*)d_in[11]; bsv[0] = (const float*)d_in[12];
        Ws[1] = (const float*)d_in[13]; bsv[1] = (const float*)d_in[14];
        Ws[2] = (const float*)d_in[15]; bsv[2] = (const float*)d_in[16];
        Wd[0] = (const float*)d_in[17]; bdv[0] = (const float*)d_in[18];
        Wd[1] = (const float*)d_in[19]; bdv[1] = (const float*)d_in[20];
        Wd[2] = (const float*)d_in[21]; bdv[2] = (const float*)d_in[22];
    } else {
        for (int i = 0; i < 4; i++) { an[i] = (const int*)d_in[2 + 2 * i]; bn[i] = (const int*)d_in[3 + 2 * i]; }
        n1 = in_sizes[2]; n2 = in_sizes[4] / 2; n3 = in_sizes[6] / 3; n4 = in_sizes[8] / 4;
        Ws[0] = (const float*)d_in[11]; bsv[0] = (const float*)d_in[12];
        Wd[0] = (const float*)d_in[13]; bdv[0] = (const float*)d_in[14];
        Ws[1] = (const float*)d_in[15]; bsv[1] = (const float*)d_in[16];
        Wd[1] = (const float*)d_in[17]; bdv[1] = (const float*)d_in[18];
        Ws[2] = (const float*)d_in[19]; bsv[2] = (const float*)d_in[20];
        Wd[2] = (const float*)d_in[21]; bdv[2] = (const float*)d_in[22];
    }

    float *pT, *pX0, *pX1, *pWt, *pbc;
    cudaGetSymbolAddress((void**)&pT,  g_T);
    cudaGetSymbolAddress((void**)&pX0, g_X0);
    cudaGetSymbolAddress((void**)&pX1, g_X1);
    cudaGetSymbolAddress((void**)&pWt, g_Wt);
    cudaGetSymbolAddress((void**)&pbc, g_bc);

    const int din_arr[3]  = {62, 100, 100};
    const int nd[4] = {n1, n2, n3, n4};
    const int degStart[4] = {0, n1, n1 + n2, n1 + n2 + n3};

    // single prep launch (keeps later launches aligned for ncu -s 5 -c 1)
    prep_kernel<<<1664, 384>>>(Ws[0], Wd[0], bsv[0], bdv[0],
                               Ws[1], Wd[1], bsv[1], bdv[1],
                               Ws[2], Wd[2], bsv[2], bdv[2]);

    // smem: 2*128*(KPAD+4) + 256 floats
    const int smem0  = (2 * 128 * 140 + 256) * 4;   // 144,384  (KPAD=136)
    const int smem12 = (2 * 128 * 212 + 256) * 4;   // 218,112  (KPAD=208)
    cudaFuncSetAttribute(fused_gemm_kernel<136, 0>, cudaFuncAttributeMaxDynamicSharedMemorySize, smem0);
    cudaFuncSetAttribute(fused_gemm_kernel<208, 0>, cudaFuncAttributeMaxDynamicSharedMemorySize, smem12);
    cudaFuncSetAttribute(fused_gemm_kernel<208, 1>, cudaFuncAttributeMaxDynamicSharedMemorySize, smem12);

    const float* xin = atom;
    int ldx = 62;
    float* xbuf[2] = {pX0, pX1};

    for (int li = 0; li < 3; li++) {
        int din  = din_arr[li];
        int dout = (li < 2) ? 100 : 512;
        float* outp = (li < 2) ? xbuf[li] : pT;
        int numNt = (li < 2) ? 1 : 4;

        for (int d = 0; d < 4; d++) {
            if (nd[d] <= 0) continue;
            int grid = (nd[d] + 127) / 128;
            const float* WtD = pWt + (size_t)li * (4 * 512 * WT_STRIDE) + (size_t)d * (512 * WT_STRIDE);
            const float* bD  = pbc + li * 2048 + d * 512;
            if (li == 0)
                fused_gemm_kernel<136, 0><<<grid, 256, smem0>>>(
                    xin, ldx, din, bond, an[d], bn[d], d + 1,
                    degStart[d], nd[d], WtD, bD, dout, numNt, outp);
            else if (li == 1)
                fused_gemm_kernel<208, 0><<<grid, 256, smem12>>>(
                    xin, ldx, din, bond, an[d], bn[d], d + 1,
                    degStart[d], nd[d], WtD, bD, dout, numNt, outp);
            else
                fused_gemm_kernel<208, 1><<<grid, 256, smem12>>>(
                    xin, ldx, din, bond, an[d], bn[d], d + 1,
                    degStart[d], nd[d], WtD, bD, dout, numNt, outp);
        }
        if (li < 2) { xin = xbuf[li]; ldx = 100; }
    }

    int nmol = out_size / 512;
    molsum_kernel<<<nmol, 256>>>((float*)d_out);
}

// round 7
// speedup vs baseline: 1.8011x; 1.4478x over previous
#include <cuda_runtime.h>
#include <cstdint>
#include <math.h>

#define NATOMS 500000
#define WT_STRIDE 208   // padded K storage for transposed weights (max K = 206)

// ---------------- scratch (static device globals) ----------------
__device__ float g_T[(size_t)NATOMS * 512];        // 1 GB   pre-norm layer-2 output
__device__ float g_X0[(size_t)NATOMS * 100];       // post-norm x (layer0 out)
__device__ float g_X1[(size_t)NATOMS * 100];       // post-norm x (layer1 out)
__device__ float g_inv[NATOMS];                    // layer-2 per-atom 1/||t||
__device__ float g_Wt[3 * 4 * 512 * WT_STRIDE];    // transposed concat weights, tf32-rounded
__device__ float g_bc[3 * 4 * 512];                // combined bias (fp32), zero padded

// ---------------- helpers ----------------
__device__ __forceinline__ float to_tf32(float f) {
    uint32_t u;
    asm("cvt.rna.tf32.f32 %0, %1;" : "=r"(u) : "f"(f));
    return __uint_as_float(u);
}

__device__ __forceinline__ uint32_t smem_u32(const void* p) {
    uint32_t a;
    asm("{ .reg .u64 t; cvta.to.shared.u64 t, %1; cvt.u32.u64 %0, t; }" : "=r"(a) : "l"(p));
    return a;
}

__device__ __forceinline__ void cp_async16(uint32_t saddr, const void* gptr) {
    asm volatile("cp.async.cg.shared.global [%0], [%1], 16;" :: "r"(saddr), "l"(gptr));
}
__device__ __forceinline__ void cp_async_commit_wait() {
    asm volatile("cp.async.commit_group;");
    asm volatile("cp.async.wait_group 0;" ::: "memory");
}

__device__ __forceinline__ void mma8(float& c0, float& c1, float& c2, float& c3,
                                     uint32_t a0, uint32_t a1, uint32_t a2, uint32_t a3,
                                     uint32_t b0, uint32_t b1) {
    asm volatile("mma.sync.aligned.m16n8k8.row.col.f32.tf32.tf32.f32 "
                 "{%0,%1,%2,%3}, {%4,%5,%6,%7}, {%8,%9}, {%0,%1,%2,%3};"
                 : "+f"(c0), "+f"(c1), "+f"(c2), "+f"(c3)
                 : "r"(a0), "r"(a1), "r"(a2), "r"(a3), "r"(b0), "r"(b1));
}

// ---------------- single-launch weight + bias prep (all 3 layers) ----------------
__global__ void prep_kernel(const float* __restrict__ Ws0, const float* __restrict__ Wd0,
                            const float* __restrict__ bs0, const float* __restrict__ bd0,
                            const float* __restrict__ Ws1, const float* __restrict__ Wd1,
                            const float* __restrict__ bs1, const float* __restrict__ bd1,
                            const float* __restrict__ Ws2, const float* __restrict__ Wd2,
                            const float* __restrict__ bs2, const float* __restrict__ bd2)
{
    const float* Ws[3] = {Ws0, Ws1, Ws2};
    const float* Wd[3] = {Wd0, Wd1, Wd2};
    const float* bs[3] = {bs0, bs1, bs2};
    const float* bd[3] = {bd0, bd1, bd2};
    const int din_arr[3]  = {62, 100, 100};
    const int dout_arr[3] = {100, 100, 512};

    const int perL = 4 * 512 * WT_STRIDE;
    const int total = 3 * perL;
    for (int idx = blockIdx.x * blockDim.x + threadIdx.x; idx < total; idx += gridDim.x * blockDim.x) {
        int li  = idx / perL;
        int rem = idx - li * perL;
        int d   = rem / (512 * WT_STRIDE);
        int r2  = rem - d * (512 * WT_STRIDE);
        int n   = r2 / WT_STRIDE;
        int k   = r2 - n * WT_STRIDE;
        int din = din_arr[li], dout = dout_arr[li];
        int K = 2 * din + 6;
        float v = 0.f;
        if (n < dout && k < K) {
            if (k < din) v = Ws[li][(size_t)k * dout + n];
            else {
                int r = (k < 2 * din) ? (k - din) : (din + (k - 2 * din));
                v = Wd[li][((size_t)d * (din + 6) + r) * dout + n];
            }
            v = to_tf32(v);
        }
        g_Wt[idx] = v;
    }
    for (int idx = blockIdx.x * blockDim.x + threadIdx.x; idx < 3 * 2048; idx += gridDim.x * blockDim.x) {
        int li = idx / 2048;
        int r  = idx - li * 2048;
        int d  = r >> 9, j = r & 511;
        int dout = dout_arr[li];
        g_bc[idx] = (j < dout) ? (bs[li][j] + bd[li][d * dout + j]) : 0.f;
    }
}

// ---------------- fused gather + tf32 mma.sync GEMM + epilogue ----------------
// 512 threads, 16 warps (4x4 warp grid), warp tile 32x32 (2 m-frags x 4 n-frags).
// MODE 0: dout==100, fused bias + L2-normalize + relu -> outp (ld 100)
// MODE 1: bias add -> outp (ld 512) at col nt*128; accumulate row sum-of-squares -> g_inv
template<int KPAD, int MODE>
__global__ __launch_bounds__(512)
void fused_gemm_kernel(const float* __restrict__ x, int ldx, int din,
                       const float* __restrict__ bond,
                       const int* __restrict__ an, const int* __restrict__ bn, int deg,
                       int degStart, int M,
                       const float* __restrict__ Wt, const float* __restrict__ bias,
                       int dout, int numNt, float* __restrict__ outp)
{
    constexpr int STR = KPAD + 4;            // smem row stride (floats) — bank-conflict-free
    extern __shared__ float smem[];
    float* sA    = smem;                     // [128][STR]
    float* sB    = smem + 128 * STR;         // [128][STR]
    float* sBias = smem + 2 * 128 * STR;     // [128]
    float* sSS   = sBias + 128;              // [128] per-row sum of squares (MODE 1)
    const uint32_t sBu = smem_u32(sB);

    const int tid  = threadIdx.x;
    const int wid  = tid >> 5;               // 0..15
    const int lane = tid & 31;
    const int grp  = lane >> 2;              // 0..7
    const int tig  = lane & 3;               // 0..3
    const int wm   = wid & 3;                // warp M index (4)
    const int wn   = wid >> 2;               // warp N index (4)
    const int row0 = blockIdx.x * 128;
    const int K    = 2 * din + 6;

    if (MODE == 1 && tid < 128) sSS[tid] = 0.f;

    // ---- gather-fill A tile (tf32-rounded): warp handles 8 rows ----
    #pragma unroll 2
    for (int rr = 0; rr < 8; rr++) {
        int r = wid * 8 + rr;
        int m = row0 + r;
        if (m >= M) continue;
        const float* xs = x + (size_t)(degStart + m) * ldx;
        const int* ai = an + (size_t)m * deg;
        const float* p0 = x + (size_t)ai[0] * ldx;
        const float* p1 = (deg > 1) ? x + (size_t)ai[1] * ldx : p0;
        const float* p2 = (deg > 2) ? x + (size_t)ai[2] * ldx : p0;
        const float* p3 = (deg > 3) ? x + (size_t)ai[3] * ldx : p0;
        float* Ar = sA + r * STR;
        for (int c = lane; c < din; c += 32) {
            float s = p0[c];
            if (deg > 1) s += p1[c];
            if (deg > 2) s += p2[c];
            if (deg > 3) s += p3[c];
            Ar[c]       = to_tf32(xs[c]);
            Ar[din + c] = to_tf32(s);
        }
        if (lane < 6) {
            const int* bi = bn + (size_t)m * deg;
            float s = bond[(size_t)bi[0] * 6 + lane];
            if (deg > 1) s += bond[(size_t)bi[1] * 6 + lane];
            if (deg > 2) s += bond[(size_t)bi[2] * 6 + lane];
            if (deg > 3) s += bond[(size_t)bi[3] * 6 + lane];
            Ar[2 * din + lane] = to_tf32(s);
        }
        for (int c = K + lane; c < KPAD; c += 32) Ar[c] = 0.f;
    }

    const float* paBase = sA + (wm * 32 + grp) * STR + tig;
    const float* pbBase = sB + (wn * 32 + grp) * STR + tig;

    for (int nt = 0; nt < numNt; nt++) {
        const int ncol0 = nt * 128;
        __syncthreads();   // prior iteration's smem reads done before refill

        // fill B tile via cp.async (Wt rows zero-padded to 512)
        {
            const float4* W4 = (const float4*)Wt;
            constexpr int KV4 = KPAD / 4;
            for (int i = tid; i < 128 * KV4; i += 512) {
                int rowb = i / KV4;
                int kc4  = i - rowb * KV4;
                cp_async16(sBu + (uint32_t)(rowb * STR + kc4 * 4) * 4,
                           W4 + (size_t)(ncol0 + rowb) * (WT_STRIDE / 4) + kc4);
            }
            if (tid < 128) sBias[tid] = bias[ncol0 + tid];
            cp_async_commit_wait();
        }
        __syncthreads();

        // ---- mma.sync mainloop over full K ----
        float acc[2][4][4];
        #pragma unroll
        for (int mf = 0; mf < 2; mf++)
            #pragma unroll
            for (int nf = 0; nf < 4; nf++)
                #pragma unroll
                for (int q = 0; q < 4; q++) acc[mf][nf][q] = 0.f;

        #pragma unroll 4
        for (int k0 = 0; k0 < KPAD; k0 += 8) {
            uint32_t a[2][4], b[4][2];
            #pragma unroll
            for (int mf = 0; mf < 2; mf++) {
                a[mf][0] = __float_as_uint(paBase[(mf * 16    ) * STR + k0    ]);
                a[mf][1] = __float_as_uint(paBase[(mf * 16 + 8) * STR + k0    ]);
                a[mf][2] = __float_as_uint(paBase[(mf * 16    ) * STR + k0 + 4]);
                a[mf][3] = __float_as_uint(paBase[(mf * 16 + 8) * STR + k0 + 4]);
            }
            #pragma unroll
            for (int nf = 0; nf < 4; nf++) {
                b[nf][0] = __float_as_uint(pbBase[(nf * 8) * STR + k0    ]);
                b[nf][1] = __float_as_uint(pbBase[(nf * 8) * STR + k0 + 4]);
            }
            #pragma unroll
            for (int mf = 0; mf < 2; mf++)
                #pragma unroll
                for (int nf = 0; nf < 4; nf++)
                    mma8(acc[mf][nf][0], acc[mf][nf][1], acc[mf][nf][2], acc[mf][nf][3],
                         a[mf][0], a[mf][1], a[mf][2], a[mf][3], b[nf][0], b[nf][1]);
        }

        if (MODE == 1) {
            // direct store with bias + per-row sum-of-squares accumulation
            #pragma unroll
            for (int mf = 0; mf < 2; mf++) {
                int r = wm * 32 + mf * 16 + grp;
                float ss0 = 0.f, ss1 = 0.f;
                #pragma unroll
                for (int nf = 0; nf < 4; nf++) {
                    int c = wn * 32 + nf * 8 + 2 * tig;
                    float b0v = sBias[c], b1v = sBias[c + 1];
                    float t0 = acc[mf][nf][0] + b0v, t1 = acc[mf][nf][1] + b1v;
                    float t2 = acc[mf][nf][2] + b0v, t3 = acc[mf][nf][3] + b1v;
                    ss0 += t0 * t0 + t1 * t1;
                    ss1 += t2 * t2 + t3 * t3;
                    if (row0 + r < M)
                        *(float2*)(outp + (size_t)(degStart + row0 + r) * 512 + ncol0 + c)
                            = make_float2(t0, t1);
                    if (row0 + r + 8 < M)
                        *(float2*)(outp + (size_t)(degStart + row0 + r + 8) * 512 + ncol0 + c)
                            = make_float2(t2, t3);
                }
                if (row0 + r < M)     atomicAdd(&sSS[r], ss0);
                if (row0 + r + 8 < M) atomicAdd(&sSS[r + 8], ss1);
            }
        } else {
            // stage t = acc + bias into sA (A panel no longer needed), then row-norm
            __syncthreads();
            #pragma unroll
            for (int mf = 0; mf < 2; mf++) {
                int r = wm * 32 + mf * 16 + grp;
                #pragma unroll
                for (int nf = 0; nf < 4; nf++) {
                    int c = wn * 32 + nf * 8 + 2 * tig;
                    float b0v = sBias[c], b1v = sBias[c + 1];
                    sA[r * STR + c]           = acc[mf][nf][0] + b0v;
                    sA[r * STR + c + 1]       = acc[mf][nf][1] + b1v;
                    sA[(r + 8) * STR + c]     = acc[mf][nf][2] + b0v;
                    sA[(r + 8) * STR + c + 1] = acc[mf][nf][3] + b1v;
                }
            }
            __syncthreads();
            // warp wid handles rows wid*8 .. wid*8+7 (dout == 100)
            for (int rr = 0; rr < 8; rr++) {
                int r = wid * 8 + rr;
                int m = row0 + r;
                if (m >= M) continue;
                const float* tr = sA + r * STR;
                float v0 = tr[lane];
                float v1 = tr[lane + 32];
                float v2 = tr[lane + 64];
                float v3 = (lane < 4) ? tr[lane + 96] : 0.f;
                float ss = v0 * v0 + v1 * v1 + v2 * v2 + v3 * v3;
                #pragma unroll
                for (int o = 16; o; o >>= 1) ss += __shfl_xor_sync(0xffffffffu, ss, o);
                float inv = 1.f / fmaxf(sqrtf(ss), 1e-12f);
                float* o = outp + (size_t)(degStart + m) * 100;
                o[lane]      = fmaxf(v0 * inv, 0.f);
                o[lane + 32] = fmaxf(v1 * inv, 0.f);
                o[lane + 64] = fmaxf(v2 * inv, 0.f);
                if (lane < 4) o[lane + 96] = fmaxf(v3 * inv, 0.f);
            }
        }
    }

    if (MODE == 1) {
        __syncthreads();
        if (tid < 128 && row0 + tid < M)
            g_inv[degStart + row0 + tid] = 1.f / fmaxf(sqrtf(sSS[tid]), 1e-12f);
    }
}

// ---------------- layer-2 relu(t * inv) + molecule segment-sum (pure streaming) ----------------
__global__ void molsum_kernel(float* __restrict__ out)
{
    int m   = blockIdx.x;
    int tid = threadIdx.x;
    float acc0 = 0.f, acc1 = 0.f;
    const float* base = g_T + (size_t)m * 20 * 512;
    #pragma unroll 4
    for (int a = 0; a < 20; a++) {
        const float* row = base + a * 512;
        float inv = g_inv[m * 20 + a];
        acc0 += fmaxf(row[tid]       * inv, 0.f);
        acc1 += fmaxf(row[tid + 256] * inv, 0.f);
    }
    out[(size_t)m * 512 + tid]       = acc0;
    out[(size_t)m * 512 + 256 + tid] = acc1;
}

// ---------------- host ----------------
extern "C" void kernel_launch(void* const* d_in, const int* in_sizes, int n_in,
                              void* d_out, int out_size)
{
    const float* atom = (const float*)d_in[0];
    const float* bond = (const float*)d_in[1];
    const int*   an[4];
    const int*   bn[4];
    const float *Ws[3], *bsv[3], *Wd[3], *bdv[3];
    int n1, n2, n3, n4;

    bool dictOrder = (in_sizes[3] == in_sizes[2]);
    if (!dictOrder) {
        for (int i = 0; i < 4; i++) { an[i] = (const int*)d_in[2 + i]; bn[i] = (const int*)d_in[6 + i]; }
        n1 = in_sizes[2]; n2 = in_sizes[3] / 2; n3 = in_sizes[4] / 3; n4 = in_sizes[5] / 4;
        Ws[0] = (const float*)d_in[11]; bsv[0] = (const float*)d_in[12];
        Ws[1] = (const float*)d_in[13]; bsv[1] = (const float*)d_in[14];
        Ws[2] = (const float*)d_in[15]; bsv[2] = (const float*)d_in[16];
        Wd[0] = (const float*)d_in[17]; bdv[0] = (const float*)d_in[18];
        Wd[1] = (const float*)d_in[19]; bdv[1] = (const float*)d_in[20];
        Wd[2] = (const float*)d_in[21]; bdv[2] = (const float*)d_in[22];
    } else {
        for (int i = 0; i < 4; i++) { an[i] = (const int*)d_in[2 + 2 * i]; bn[i] = (const int*)d_in[3 + 2 * i]; }
        n1 = in_sizes[2]; n2 = in_sizes[4] / 2; n3 = in_sizes[6] / 3; n4 = in_sizes[8] / 4;
        Ws[0] = (const float*)d_in[11]; bsv[0] = (const float*)d_in[12];
        Wd[0] = (const float*)d_in[13]; bdv[0] = (const float*)d_in[14];
        Ws[1] = (const float*)d_in[15]; bsv[1] = (const float*)d_in[16];
        Wd[1] = (const float*)d_in[17]; bdv[1] = (const float*)d_in[18];
        Ws[2] = (const float*)d_in[19]; bsv[2] = (const float*)d_in[20];
        Wd[2] = (const float*)d_in[21]; bdv[2] = (const float*)d_in[22];
    }

    float *pT, *pX0, *pX1, *pWt, *pbc;
    cudaGetSymbolAddress((void**)&pT,  g_T);
    cudaGetSymbolAddress((void**)&pX0, g_X0);
    cudaGetSymbolAddress((void**)&pX1, g_X1);
    cudaGetSymbolAddress((void**)&pWt, g_Wt);
    cudaGetSymbolAddress((void**)&pbc, g_bc);

    const int din_arr[3]  = {62, 100, 100};
    const int nd[4] = {n1, n2, n3, n4};
    const int degStart[4] = {0, n1, n1 + n2, n1 + n2 + n3};

    prep_kernel<<<1664, 384>>>(Ws[0], Wd[0], bsv[0], bdv[0],
                               Ws[1], Wd[1], bsv[1], bdv[1],
                               Ws[2], Wd[2], bsv[2], bdv[2]);

    const int smem0  = (2 * 128 * 140 + 256) * 4;   // 144,384  (KPAD=136)
    const int smem12 = (2 * 128 * 212 + 256) * 4;   // 218,112  (KPAD=208)
    cudaFuncSetAttribute(fused_gemm_kernel<136, 0>, cudaFuncAttributeMaxDynamicSharedMemorySize, smem0);
    cudaFuncSetAttribute(fused_gemm_kernel<208, 0>, cudaFuncAttributeMaxDynamicSharedMemorySize, smem12);
    cudaFuncSetAttribute(fused_gemm_kernel<208, 1>, cudaFuncAttributeMaxDynamicSharedMemorySize, smem12);

    const float* xin = atom;
    int ldx = 62;
    float* xbuf[2] = {pX0, pX1};

    for (int li = 0; li < 3; li++) {
        int din  = din_arr[li];
        int dout = (li < 2) ? 100 : 512;
        float* outp = (li < 2) ? xbuf[li] : pT;
        int numNt = (li < 2) ? 1 : 4;

        for (int d = 0; d < 4; d++) {
            if (nd[d] <= 0) continue;
            int grid = (nd[d] + 127) / 128;
            const float* WtD = pWt + (size_t)li * (4 * 512 * WT_STRIDE) + (size_t)d * (512 * WT_STRIDE);
            const float* bD  = pbc + li * 2048 + d * 512;
            if (li == 0)
                fused_gemm_kernel<136, 0><<<grid, 512, smem0>>>(
                    xin, ldx, din, bond, an[d], bn[d], d + 1,
                    degStart[d], nd[d], WtD, bD, dout, numNt, outp);
            else if (li == 1)
                fused_gemm_kernel<208, 0><<<grid, 512, smem12>>>(
                    xin, ldx, din, bond, an[d], bn[d], d + 1,
                    degStart[d], nd[d], WtD, bD, dout, numNt, outp);
            else
                fused_gemm_kernel<208, 1><<<grid, 512, smem12>>>(
                    xin, ldx, din, bond, an[d], bn[d], d + 1,
                    degStart[d], nd[d], WtD, bD, dout, numNt, outp);
        }
        if (li < 2) { xin = xbuf[li]; ldx = 100; }
    }

    int nmol = out_size / 512;
    molsum_kernel<<<nmol, 256>>>((float*)d_out);
}

// round 8
// speedup vs baseline: 2.1316x; 1.1835x over previous
#include <cuda_runtime.h>
#include <cstdint>
#include <math.h>

#define NATOMS 500000
#define WT_STRIDE 208   // padded K storage for transposed weights (max K = 206)

// ---------------- scratch (static device globals) ----------------
__device__ float g_T[(size_t)NATOMS * 512];        // 1 GB   pre-norm layer-2 output
__device__ float g_X0[(size_t)NATOMS * 100];       // post-norm x (layer0 out)
__device__ float g_X1[(size_t)NATOMS * 100];       // post-norm x (layer1 out)
__device__ float g_inv[NATOMS];                    // layer-2 per-atom 1/||t||
__device__ float g_Wt[3 * 4 * 512 * WT_STRIDE];    // transposed concat weights, tf32-rounded
__device__ float g_bc[3 * 4 * 512];                // combined bias (fp32), zero padded

// ---------------- helpers ----------------
__device__ __forceinline__ float to_tf32(float f) {
    uint32_t u;
    asm("cvt.rna.tf32.f32 %0, %1;" : "=r"(u) : "f"(f));
    return __uint_as_float(u);
}

__device__ __forceinline__ uint32_t smem_u32(const void* p) {
    uint32_t a;
    asm("{ .reg .u64 t; cvta.to.shared.u64 t, %1; cvt.u32.u64 %0, t; }" : "=r"(a) : "l"(p));
    return a;
}

__device__ __forceinline__ void cp_async16(uint32_t saddr, const void* gptr) {
    asm volatile("cp.async.cg.shared.global [%0], [%1], 16;" :: "r"(saddr), "l"(gptr));
}
__device__ __forceinline__ void cp_async_commit_wait() {
    asm volatile("cp.async.commit_group;");
    asm volatile("cp.async.wait_group 0;" ::: "memory");
}

__device__ __forceinline__ void mma8(float& c0, float& c1, float& c2, float& c3,
                                     uint32_t a0, uint32_t a1, uint32_t a2, uint32_t a3,
                                     uint32_t b0, uint32_t b1) {
    asm volatile("mma.sync.aligned.m16n8k8.row.col.f32.tf32.tf32.f32 "
                 "{%0,%1,%2,%3}, {%4,%5,%6,%7}, {%8,%9}, {%0,%1,%2,%3};"
                 : "+f"(c0), "+f"(c1), "+f"(c2), "+f"(c3)
                 : "r"(a0), "r"(a1), "r"(a2), "r"(a3), "r"(b0), "r"(b1));
}

// ---------------- single-launch weight + bias prep (all 3 layers) ----------------
__global__ void prep_kernel(const float* __restrict__ Ws0, const float* __restrict__ Wd0,
                            const float* __restrict__ bs0, const float* __restrict__ bd0,
                            const float* __restrict__ Ws1, const float* __restrict__ Wd1,
                            const float* __restrict__ bs1, const float* __restrict__ bd1,
                            const float* __restrict__ Ws2, const float* __restrict__ Wd2,
                            const float* __restrict__ bs2, const float* __restrict__ bd2)
{
    const float* Ws[3] = {Ws0, Ws1, Ws2};
    const float* Wd[3] = {Wd0, Wd1, Wd2};
    const float* bs[3] = {bs0, bs1, bs2};
    const float* bd[3] = {bd0, bd1, bd2};
    const int din_arr[3]  = {62, 100, 100};
    const int dout_arr[3] = {100, 100, 512};

    const int perL = 4 * 512 * WT_STRIDE;
    const int total = 3 * perL;
    for (int idx = blockIdx.x * blockDim.x + threadIdx.x; idx < total; idx += gridDim.x * blockDim.x) {
        int li  = idx / perL;
        int rem = idx - li * perL;
        int d   = rem / (512 * WT_STRIDE);
        int r2  = rem - d * (512 * WT_STRIDE);
        int n   = r2 / WT_STRIDE;
        int k   = r2 - n * WT_STRIDE;
        int din = din_arr[li], dout = dout_arr[li];
        int K = 2 * din + 6;
        float v = 0.f;
        if (n < dout && k < K) {
            if (k < din) v = Ws[li][(size_t)k * dout + n];
            else {
                int r = (k < 2 * din) ? (k - din) : (din + (k - 2 * din));
                v = Wd[li][((size_t)d * (din + 6) + r) * dout + n];
            }
            v = to_tf32(v);
        }
        g_Wt[idx] = v;
    }
    for (int idx = blockIdx.x * blockDim.x + threadIdx.x; idx < 3 * 2048; idx += gridDim.x * blockDim.x) {
        int li = idx / 2048;
        int r  = idx - li * 2048;
        int d  = r >> 9, j = r & 511;
        int dout = dout_arr[li];
        g_bc[idx] = (j < dout) ? (bs[li][j] + bd[li][d * dout + j]) : 0.f;
    }
}

// ---------------- fused gather + tf32 mma.sync GEMM + epilogue ----------------
// 1024 threads, 32 warps (8 M x 4 N), warp tile 16x32 (1 m-frag x 4 n-frags).
// MODE 0: dout==100, fused bias + L2-normalize + relu -> outp (ld 100)
// MODE 1: bias add -> outp (ld 512) at col nt*128; accumulate row sum-of-squares -> g_inv
template<int KPAD, int MODE>
__global__ __launch_bounds__(1024)
void fused_gemm_kernel(const float* __restrict__ x, int ldx, int din,
                       const float* __restrict__ bond,
                       const int* __restrict__ an, const int* __restrict__ bn, int deg,
                       int degStart, int M,
                       const float* __restrict__ Wt, const float* __restrict__ bias,
                       int dout, int numNt, float* __restrict__ outp)
{
    constexpr int STR = KPAD + 4;            // smem row stride (floats) — bank-conflict-free
    extern __shared__ float smem[];
    float* sA    = smem;                     // [128][STR]
    float* sB    = smem + 128 * STR;         // [128][STR]
    float* sBias = smem + 2 * 128 * STR;     // [128]
    float* sSS   = sBias + 128;              // [128] per-row sum of squares (MODE 1)
    const uint32_t sBu = smem_u32(sB);

    const int tid  = threadIdx.x;
    const int wid  = tid >> 5;               // 0..31
    const int lane = tid & 31;
    const int grp  = lane >> 2;              // 0..7
    const int tig  = lane & 3;               // 0..3
    const int wm   = wid & 7;                // warp M index (8)  -> 16 rows each
    const int wn   = wid >> 3;               // warp N index (4)  -> 32 cols each
    const int row0 = blockIdx.x * 128;
    const int K    = 2 * din + 6;

    if (MODE == 1 && tid < 128) sSS[tid] = 0.f;

    // ---- gather-fill A tile (tf32-rounded): warp handles 4 rows ----
    #pragma unroll
    for (int rr = 0; rr < 4; rr++) {
        int r = wid * 4 + rr;
        int m = row0 + r;
        if (m >= M) continue;
        const float* xs = x + (size_t)(degStart + m) * ldx;
        const int* ai = an + (size_t)m * deg;
        const float* p0 = x + (size_t)ai[0] * ldx;
        const float* p1 = (deg > 1) ? x + (size_t)ai[1] * ldx : p0;
        const float* p2 = (deg > 2) ? x + (size_t)ai[2] * ldx : p0;
        const float* p3 = (deg > 3) ? x + (size_t)ai[3] * ldx : p0;
        float* Ar = sA + r * STR;
        for (int c = lane; c < din; c += 32) {
            float s = p0[c];
            if (deg > 1) s += p1[c];
            if (deg > 2) s += p2[c];
            if (deg > 3) s += p3[c];
            Ar[c]       = to_tf32(xs[c]);
            Ar[din + c] = to_tf32(s);
        }
        if (lane < 6) {
            const int* bi = bn + (size_t)m * deg;
            float s = bond[(size_t)bi[0] * 6 + lane];
            if (deg > 1) s += bond[(size_t)bi[1] * 6 + lane];
            if (deg > 2) s += bond[(size_t)bi[2] * 6 + lane];
            if (deg > 3) s += bond[(size_t)bi[3] * 6 + lane];
            Ar[2 * din + lane] = to_tf32(s);
        }
        for (int c = K + lane; c < KPAD; c += 32) Ar[c] = 0.f;
    }

    const float* paBase = sA + (wm * 16 + grp) * STR + tig;
    const float* pbBase = sB + (wn * 32 + grp) * STR + tig;

    for (int nt = 0; nt < numNt; nt++) {
        const int ncol0 = nt * 128;
        __syncthreads();   // prior iteration's smem reads done before refill

        // fill B tile via cp.async (Wt rows zero-padded to 512)
        {
            const float4* W4 = (const float4*)Wt;
            constexpr int KV4 = KPAD / 4;
            for (int i = tid; i < 128 * KV4; i += 1024) {
                int rowb = i / KV4;
                int kc4  = i - rowb * KV4;
                cp_async16(sBu + (uint32_t)(rowb * STR + kc4 * 4) * 4,
                           W4 + (size_t)(ncol0 + rowb) * (WT_STRIDE / 4) + kc4);
            }
            if (tid < 128) sBias[tid] = bias[ncol0 + tid];
            cp_async_commit_wait();
        }
        __syncthreads();

        // ---- mma.sync mainloop over full K ----
        float acc[4][4];
        #pragma unroll
        for (int nf = 0; nf < 4; nf++)
            #pragma unroll
            for (int q = 0; q < 4; q++) acc[nf][q] = 0.f;

        #pragma unroll 4
        for (int k0 = 0; k0 < KPAD; k0 += 8) {
            uint32_t a[4], b[4][2];
            a[0] = __float_as_uint(paBase[k0            ]);
            a[1] = __float_as_uint(paBase[8 * STR + k0  ]);
            a[2] = __float_as_uint(paBase[k0 + 4        ]);
            a[3] = __float_as_uint(paBase[8 * STR + k0 + 4]);
            #pragma unroll
            for (int nf = 0; nf < 4; nf++) {
                b[nf][0] = __float_as_uint(pbBase[(nf * 8) * STR + k0    ]);
                b[nf][1] = __float_as_uint(pbBase[(nf * 8) * STR + k0 + 4]);
            }
            #pragma unroll
            for (int nf = 0; nf < 4; nf++)
                mma8(acc[nf][0], acc[nf][1], acc[nf][2], acc[nf][3],
                     a[0], a[1], a[2], a[3], b[nf][0], b[nf][1]);
        }

        if (MODE == 1) {
            // direct store with bias + per-row sum-of-squares accumulation
            int r = wm * 16 + grp;
            float ss0 = 0.f, ss1 = 0.f;
            #pragma unroll
            for (int nf = 0; nf < 4; nf++) {
                int c = wn * 32 + nf * 8 + 2 * tig;
                float b0v = sBias[c], b1v = sBias[c + 1];
                float t0 = acc[nf][0] + b0v, t1 = acc[nf][1] + b1v;
                float t2 = acc[nf][2] + b0v, t3 = acc[nf][3] + b1v;
                ss0 += t0 * t0 + t1 * t1;
                ss1 += t2 * t2 + t3 * t3;
                if (row0 + r < M)
                    *(float2*)(outp + (size_t)(degStart + row0 + r) * 512 + ncol0 + c)
                        = make_float2(t0, t1);
                if (row0 + r + 8 < M)
                    *(float2*)(outp + (size_t)(degStart + row0 + r + 8) * 512 + ncol0 + c)
                        = make_float2(t2, t3);
            }
            if (row0 + r < M)     atomicAdd(&sSS[r], ss0);
            if (row0 + r + 8 < M) atomicAdd(&sSS[r + 8], ss1);
        } else {
            // stage t = acc + bias into sA (A panel no longer needed), then row-norm
            __syncthreads();
            {
                int r = wm * 16 + grp;
                #pragma unroll
                for (int nf = 0; nf < 4; nf++) {
                    int c = wn * 32 + nf * 8 + 2 * tig;
                    float b0v = sBias[c], b1v = sBias[c + 1];
                    sA[r * STR + c]           = acc[nf][0] + b0v;
                    sA[r * STR + c + 1]       = acc[nf][1] + b1v;
                    sA[(r + 8) * STR + c]     = acc[nf][2] + b0v;
                    sA[(r + 8) * STR + c + 1] = acc[nf][3] + b1v;
                }
            }
            __syncthreads();
            // warp wid handles rows wid*4 .. wid*4+3 (dout == 100)
            #pragma unroll
            for (int rr = 0; rr < 4; rr++) {
                int r = wid * 4 + rr;
                int m = row0 + r;
                if (m >= M) continue;
                const float* tr = sA + r * STR;
                float v0 = tr[lane];
                float v1 = tr[lane + 32];
                float v2 = tr[lane + 64];
                float v3 = (lane < 4) ? tr[lane + 96] : 0.f;
                float ss = v0 * v0 + v1 * v1 + v2 * v2 + v3 * v3;
                #pragma unroll
                for (int o = 16; o; o >>= 1) ss += __shfl_xor_sync(0xffffffffu, ss, o);
                float inv = 1.f / fmaxf(sqrtf(ss), 1e-12f);
                float* o = outp + (size_t)(degStart + m) * 100;
                o[lane]      = fmaxf(v0 * inv, 0.f);
                o[lane + 32] = fmaxf(v1 * inv, 0.f);
                o[lane + 64] = fmaxf(v2 * inv, 0.f);
                if (lane < 4) o[lane + 96] = fmaxf(v3 * inv, 0.f);
            }
        }
    }

    if (MODE == 1) {
        __syncthreads();
        if (tid < 128 && row0 + tid < M)
            g_inv[degStart + row0 + tid] = 1.f / fmaxf(sqrtf(sSS[tid]), 1e-12f);
    }
}

// ---------------- layer-2 relu(t * inv) + molecule segment-sum (pure streaming) ----------------
__global__ void molsum_kernel(float* __restrict__ out)
{
    int m   = blockIdx.x;
    int tid = threadIdx.x;
    float acc0 = 0.f, acc1 = 0.f;
    const float* base = g_T + (size_t)m * 20 * 512;
    #pragma unroll 4
    for (int a = 0; a < 20; a++) {
        const float* row = base + a * 512;
        float inv = g_inv[m * 20 + a];
        acc0 += fmaxf(row[tid]       * inv, 0.f);
        acc1 += fmaxf(row[tid + 256] * inv, 0.f);
    }
    out[(size_t)m * 512 + tid]       = acc0;
    out[(size_t)m * 512 + 256 + tid] = acc1;
}

// ---------------- host ----------------
extern "C" void kernel_launch(void* const* d_in, const int* in_sizes, int n_in,
                              void* d_out, int out_size)
{
    const float* atom = (const float*)d_in[0];
    const float* bond = (const float*)d_in[1];
    const int*   an[4];
    const int*   bn[4];
    const float *Ws[3], *bsv[3], *Wd[3], *bdv[3];
    int n1, n2, n3, n4;

    bool dictOrder = (in_sizes[3] == in_sizes[2]);
    if (!dictOrder) {
        for (int i = 0; i < 4; i++) { an[i] = (const int*)d_in[2 + i]; bn[i] = (const int*)d_in[6 + i]; }
        n1 = in_sizes[2]; n2 = in_sizes[3] / 2; n3 = in_sizes[4] / 3; n4 = in_sizes[5] / 4;
        Ws[0] = (const float*)d_in[11]; bsv[0] = (const float*)d_in[12];
        Ws[1] = (const float*)d_in[13]; bsv[1] = (const float*)d_in[14];
        Ws[2] = (const float*)d_in[15]; bsv[2] = (const float*)d_in[16];
        Wd[0] = (const float*)d_in[17]; bdv[0] = (const float*)d_in[18];
        Wd[1] = (const float*)d_in[19]; bdv[1] = (const float*)d_in[20];
        Wd[2] = (const float*)d_in[21]; bdv[2] = (const float*)d_in[22];
    } else {
        for (int i = 0; i < 4; i++) { an[i] = (const int*)d_in[2 + 2 * i]; bn[i] = (const int*)d_in[3 + 2 * i]; }
        n1 = in_sizes[2]; n2 = in_sizes[4] / 2; n3 = in_sizes[6] / 3; n4 = in_sizes[8] / 4;
        Ws[0] = (const float*)d_in[11]; bsv[0] = (const float*)d_in[12];
        Wd[0] = (const float*)d_in[13]; bdv[0] = (const float*)d_in[14];
        Ws[1] = (const float*)d_in[15]; bsv[1] = (const float*)d_in[16];
        Wd[1] = (const float*)d_in[17]; bdv[1] = (const float*)d_in[18];
        Ws[2] = (const float*)d_in[19]; bsv[2] = (const float*)d_in[20];
        Wd[2] = (const float*)d_in[21]; bdv[2] = (const float*)d_in[22];
    }

    float *pT, *pX0, *pX1, *pWt, *pbc;
    cudaGetSymbolAddress((void**)&pT,  g_T);
    cudaGetSymbolAddress((void**)&pX0, g_X0);
    cudaGetSymbolAddress((void**)&pX1, g_X1);
    cudaGetSymbolAddress((void**)&pWt, g_Wt);
    cudaGetSymbolAddress((void**)&pbc, g_bc);

    const int din_arr[3]  = {62, 100, 100};
    const int nd[4] = {n1, n2, n3, n4};
    const int degStart[4] = {0, n1, n1 + n2, n1 + n2 + n3};

    prep_kernel<<<1664, 384>>>(Ws[0], Wd[0], bsv[0], bdv[0],
                               Ws[1], Wd[1], bsv[1], bdv[1],
                               Ws[2], Wd[2], bsv[2], bdv[2]);

    const int smem0  = (2 * 128 * 140 + 256) * 4;   // 144,384  (KPAD=136)
    const int smem12 = (2 * 128 * 212 + 256) * 4;   // 218,112  (KPAD=208)
    cudaFuncSetAttribute(fused_gemm_kernel<136, 0>, cudaFuncAttributeMaxDynamicSharedMemorySize, smem0);
    cudaFuncSetAttribute(fused_gemm_kernel<208, 0>, cudaFuncAttributeMaxDynamicSharedMemorySize, smem12);
    cudaFuncSetAttribute(fused_gemm_kernel<208, 1>, cudaFuncAttributeMaxDynamicSharedMemorySize, smem12);

    const float* xin = atom;
    int ldx = 62;
    float* xbuf[2] = {pX0, pX1};

    for (int li = 0; li < 3; li++) {
        int din  = din_arr[li];
        int dout = (li < 2) ? 100 : 512;
        float* outp = (li < 2) ? xbuf[li] : pT;
        int numNt = (li < 2) ? 1 : 4;

        for (int d = 0; d < 4; d++) {
            if (nd[d] <= 0) continue;
            int grid = (nd[d] + 127) / 128;
            const float* WtD = pWt + (size_t)li * (4 * 512 * WT_STRIDE) + (size_t)d * (512 * WT_STRIDE);
            const float* bD  = pbc + li * 2048 + d * 512;
            if (li == 0)
                fused_gemm_kernel<136, 0><<<grid, 1024, smem0>>>(
                    xin, ldx, din, bond, an[d], bn[d], d + 1,
                    degStart[d], nd[d], WtD, bD, dout, numNt, outp);
            else if (li == 1)
                fused_gemm_kernel<208, 0><<<grid, 1024, smem12>>>(
                    xin, ldx, din, bond, an[d], bn[d], d + 1,
                    degStart[d], nd[d], WtD, bD, dout, numNt, outp);
            else
                fused_gemm_kernel<208, 1><<<grid, 1024, smem12>>>(
                    xin, ldx, din, bond, an[d], bn[d], d + 1,
                    degStart[d], nd[d], WtD, bD, dout, numNt, outp);
        }
        if (li < 2) { xin = xbuf[li]; ldx = 100; }
    }

    int nmol = out_size / 512;
    molsum_kernel<<<nmol, 256>>>((float*)d_out);
}

// round 9
// speedup vs baseline: 2.1999x; 1.0321x over previous
#include <cuda_runtime.h>
#include <cstdint>
#include <math.h>

#define NATOMS 500000
#define WT_STRIDE 208   // padded K storage for transposed weights (max K = 206)

// ---------------- scratch (static device globals) ----------------
__device__ float g_T[(size_t)NATOMS * 512];        // 1 GB   pre-norm layer-2 output
__device__ float g_X0[(size_t)NATOMS * 100];       // post-norm x (layer0 out)
__device__ float g_X1[(size_t)NATOMS * 100];       // post-norm x (layer1 out)
__device__ float g_inv[NATOMS];                    // layer-2 per-atom 1/||t||
__device__ float g_Wt[3 * 4 * 512 * WT_STRIDE];    // transposed concat weights, tf32, K-pair-interleaved
__device__ float g_bc[3 * 4 * 512];                // combined bias (fp32), zero padded

// ---------------- helpers ----------------
__device__ __forceinline__ float to_tf32(float f) {
    uint32_t u;
    asm("cvt.rna.tf32.f32 %0, %1;" : "=r"(u) : "f"(f));
    return __uint_as_float(u);
}

// K-pair interleave within each 8-block: logical k -> storage position.
// Maps pairs (t, t+4) to adjacent slots (2t, 2t+1) so fragment loads are LDS.64.
__device__ __forceinline__ int permc(int c) {
    return (c & ~7) | ((c & 3) << 1) | ((c >> 2) & 1);
}

__device__ __forceinline__ uint32_t smem_u32(const void* p) {
    uint32_t a;
    asm("{ .reg .u64 t; cvta.to.shared.u64 t, %1; cvt.u32.u64 %0, t; }" : "=r"(a) : "l"(p));
    return a;
}

__device__ __forceinline__ void cp_async16(uint32_t saddr, const void* gptr) {
    asm volatile("cp.async.cg.shared.global [%0], [%1], 16;" :: "r"(saddr), "l"(gptr));
}
__device__ __forceinline__ void cp_async_commit_wait() {
    asm volatile("cp.async.commit_group;");
    asm volatile("cp.async.wait_group 0;" ::: "memory");
}

__device__ __forceinline__ void mma8(float& c0, float& c1, float& c2, float& c3,
                                     uint32_t a0, uint32_t a1, uint32_t a2, uint32_t a3,
                                     uint32_t b0, uint32_t b1) {
    asm volatile("mma.sync.aligned.m16n8k8.row.col.f32.tf32.tf32.f32 "
                 "{%0,%1,%2,%3}, {%4,%5,%6,%7}, {%8,%9}, {%0,%1,%2,%3};"
                 : "+f"(c0), "+f"(c1), "+f"(c2), "+f"(c3)
                 : "r"(a0), "r"(a1), "r"(a2), "r"(a3), "r"(b0), "r"(b1));
}

// ---------------- single-launch weight + bias prep (all 3 layers) ----------------
// Stores Wcat^T at K-pair-interleaved positions so the GEMM's B copy stays linear.
__global__ void prep_kernel(const float* __restrict__ Ws0, const float* __restrict__ Wd0,
                            const float* __restrict__ bs0, const float* __restrict__ bd0,
                            const float* __restrict__ Ws1, const float* __restrict__ Wd1,
                            const float* __restrict__ bs1, const float* __restrict__ bd1,
                            const float* __restrict__ Ws2, const float* __restrict__ Wd2,
                            const float* __restrict__ bs2, const float* __restrict__ bd2)
{
    const float* Ws[3] = {Ws0, Ws1, Ws2};
    const float* Wd[3] = {Wd0, Wd1, Wd2};
    const float* bs[3] = {bs0, bs1, bs2};
    const float* bd[3] = {bd0, bd1, bd2};
    const int din_arr[3]  = {62, 100, 100};
    const int dout_arr[3] = {100, 100, 512};

    const int perL = 4 * 512 * WT_STRIDE;
    const int total = 3 * perL;
    for (int idx = blockIdx.x * blockDim.x + threadIdx.x; idx < total; idx += gridDim.x * blockDim.x) {
        int li  = idx / perL;
        int rem = idx - li * perL;
        int d   = rem / (512 * WT_STRIDE);
        int r2  = rem - d * (512 * WT_STRIDE);
        int n   = r2 / WT_STRIDE;
        int ks  = r2 - n * WT_STRIDE;                 // storage position
        // logical k = inverse interleave of storage position
        int k   = (ks & ~7) | ((ks & 7) >> 1) | ((ks & 1) << 2);
        int din = din_arr[li], dout = dout_arr[li];
        int K = 2 * din + 6;
        float v = 0.f;
        if (n < dout && k < K) {
            if (k < din) v = Ws[li][(size_t)k * dout + n];
            else {
                int r = (k < 2 * din) ? (k - din) : (din + (k - 2 * din));
                v = Wd[li][((size_t)d * (din + 6) + r) * dout + n];
            }
            v = to_tf32(v);
        }
        g_Wt[idx] = v;
    }
    for (int idx = blockIdx.x * blockDim.x + threadIdx.x; idx < 3 * 2048; idx += gridDim.x * blockDim.x) {
        int li = idx / 2048;
        int r  = idx - li * 2048;
        int d  = r >> 9, j = r & 511;
        int dout = dout_arr[li];
        g_bc[idx] = (j < dout) ? (bs[li][j] + bd[li][d * dout + j]) : 0.f;
    }
}

// ---------------- fused gather + tf32 mma.sync GEMM + epilogue ----------------
// 1024 threads, 32 warps (8 M x 4 N), warp tile 16x32. LDS.64 fragment loads via
// K-pair interleaved smem; STR % 32 == 24 -> phase-conflict-free 64-bit loads.
// MODE 0: dout==100, fused bias + L2-normalize + relu -> outp (ld 100)
// MODE 1: bias add -> outp (ld 512) at col nt*128; row sum-of-squares -> g_inv
template<int KPAD, int MODE>
__global__ __launch_bounds__(1024)
void fused_gemm_kernel(const float* __restrict__ x, int ldx, int din,
                       const float* __restrict__ bond,
                       const int* __restrict__ an, const int* __restrict__ bn, int deg,
                       int degStart, int M,
                       const float* __restrict__ Wt, const float* __restrict__ bias,
                       int dout, int numNt, float* __restrict__ outp)
{
    constexpr int STR = (KPAD == 136) ? 152 : 216;   // STR % 32 == 24, even
    extern __shared__ float smem[];
    float* sA    = smem;                     // [128][STR]
    float* sB    = smem + 128 * STR;         // [128][STR]
    float* sBias = smem + 2 * 128 * STR;     // [128]
    float* sSS   = sBias + 128;              // [128] per-row sum of squares (MODE 1)
    const uint32_t sBu = smem_u32(sB);

    const int tid  = threadIdx.x;
    const int wid  = tid >> 5;               // 0..31
    const int lane = tid & 31;
    const int grp  = lane >> 2;              // 0..7
    const int tig  = lane & 3;               // 0..3
    const int wm   = wid & 7;                // warp M index (8)  -> 16 rows each
    const int wn   = wid >> 3;               // warp N index (4)  -> 32 cols each
    const int row0 = blockIdx.x * 128;
    const int K    = 2 * din + 6;

    if (MODE == 1 && tid < 128) sSS[tid] = 0.f;

    // ---- issue B tile for nt=0 (async) BEFORE gather: overlap with gather latency ----
    {
        const float4* W4 = (const float4*)Wt;
        constexpr int KV4 = KPAD / 4;
        for (int i = tid; i < 128 * KV4; i += 1024) {
            int rowb = i / KV4;
            int kc4  = i - rowb * KV4;
            cp_async16(sBu + (uint32_t)(rowb * STR + kc4 * 4) * 4,
                       W4 + (size_t)rowb * (WT_STRIDE / 4) + kc4);
        }
        asm volatile("cp.async.commit_group;");
        if (tid < 128) sBias[tid] = bias[tid];
    }

    // ---- gather-fill A tile (tf32-rounded, K-pair interleaved): warp handles 4 rows ----
    #pragma unroll
    for (int rr = 0; rr < 4; rr++) {
        int r = wid * 4 + rr;
        int m = row0 + r;
        if (m >= M) continue;
        const float* xs = x + (size_t)(degStart + m) * ldx;
        const int* ai = an + (size_t)m * deg;
        const float* p0 = x + (size_t)ai[0] * ldx;
        const float* p1 = (deg > 1) ? x + (size_t)ai[1] * ldx : p0;
        const float* p2 = (deg > 2) ? x + (size_t)ai[2] * ldx : p0;
        const float* p3 = (deg > 3) ? x + (size_t)ai[3] * ldx : p0;
        float* Ar = sA + r * STR;
        for (int c = lane; c < din; c += 32) {
            float s = p0[c];
            if (deg > 1) s += p1[c];
            if (deg > 2) s += p2[c];
            if (deg > 3) s += p3[c];
            Ar[permc(c)]       = to_tf32(xs[c]);
            Ar[permc(din + c)] = to_tf32(s);
        }
        if (lane < 6) {
            const int* bi = bn + (size_t)m * deg;
            float s = bond[(size_t)bi[0] * 6 + lane];
            if (deg > 1) s += bond[(size_t)bi[1] * 6 + lane];
            if (deg > 2) s += bond[(size_t)bi[2] * 6 + lane];
            if (deg > 3) s += bond[(size_t)bi[3] * 6 + lane];
            Ar[permc(2 * din + lane)] = to_tf32(s);
        }
        for (int c = K + lane; c < KPAD; c += 32) Ar[permc(c)] = 0.f;
    }

    asm volatile("cp.async.wait_group 0;" ::: "memory");
    __syncthreads();

    // fragment base pointers (float2 = one K pair)
    const float2* paLo = (const float2*)(sA + (wm * 16 + grp) * STR) + tig;
    const float2* paHi = (const float2*)(sA + (wm * 16 + grp + 8) * STR) + tig;
    const float2* pb2  = (const float2*)(sB + (wn * 32 + grp) * STR) + tig;

    for (int nt = 0; nt < numNt; nt++) {
        const int ncol0 = nt * 128;
        if (nt > 0) {
            __syncthreads();   // prior epilogue reads done before refill
            const float4* W4 = (const float4*)Wt;
            constexpr int KV4 = KPAD / 4;
            for (int i = tid; i < 128 * KV4; i += 1024) {
                int rowb = i / KV4;
                int kc4  = i - rowb * KV4;
                cp_async16(sBu + (uint32_t)(rowb * STR + kc4 * 4) * 4,
                           W4 + (size_t)(ncol0 + rowb) * (WT_STRIDE / 4) + kc4);
            }
            if (tid < 128) sBias[tid] = bias[ncol0 + tid];
            cp_async_commit_wait();
            __syncthreads();
        }

        // ---- mma.sync mainloop over full K (LDS.64 fragment loads) ----
        float acc[4][4];
        #pragma unroll
        for (int nf = 0; nf < 4; nf++)
            #pragma unroll
            for (int q = 0; q < 4; q++) acc[nf][q] = 0.f;

        #pragma unroll 4
        for (int k0 = 0; k0 < KPAD; k0 += 8) {
            const int kk = k0 >> 1;          // float2 index
            float2 aLo = paLo[kk];
            float2 aHi = paHi[kk];
            float2 bv[4];
            #pragma unroll
            for (int nf = 0; nf < 4; nf++)
                bv[nf] = pb2[nf * 4 * STR + kk];
            #pragma unroll
            for (int nf = 0; nf < 4; nf++)
                mma8(acc[nf][0], acc[nf][1], acc[nf][2], acc[nf][3],
                     __float_as_uint(aLo.x), __float_as_uint(aHi.x),
                     __float_as_uint(aLo.y), __float_as_uint(aHi.y),
                     __float_as_uint(bv[nf].x), __float_as_uint(bv[nf].y));
        }

        if (MODE == 1) {
            // direct store with bias + per-row sum-of-squares accumulation
            int r = wm * 16 + grp;
            float ss0 = 0.f, ss1 = 0.f;
            #pragma unroll
            for (int nf = 0; nf < 4; nf++) {
                int c = wn * 32 + nf * 8 + 2 * tig;
                float b0v = sBias[c], b1v = sBias[c + 1];
                float t0 = acc[nf][0] + b0v, t1 = acc[nf][1] + b1v;
                float t2 = acc[nf][2] + b0v, t3 = acc[nf][3] + b1v;
                ss0 += t0 * t0 + t1 * t1;
                ss1 += t2 * t2 + t3 * t3;
                if (row0 + r < M)
                    *(float2*)(outp + (size_t)(degStart + row0 + r) * 512 + ncol0 + c)
                        = make_float2(t0, t1);
                if (row0 + r + 8 < M)
                    *(float2*)(outp + (size_t)(degStart + row0 + r + 8) * 512 + ncol0 + c)
                        = make_float2(t2, t3);
            }
            if (row0 + r < M)     atomicAdd(&sSS[r], ss0);
            if (row0 + r + 8 < M) atomicAdd(&sSS[r + 8], ss1);
        } else {
            // stage t = acc + bias into sA (A panel no longer needed), then row-norm
            __syncthreads();
            {
                int r = wm * 16 + grp;
                #pragma unroll
                for (int nf = 0; nf < 4; nf++) {
                    int c = wn * 32 + nf * 8 + 2 * tig;
                    float b0v = sBias[c], b1v = sBias[c + 1];
                    sA[r * STR + c]           = acc[nf][0] + b0v;
                    sA[r * STR + c + 1]       = acc[nf][1] + b1v;
                    sA[(r + 8) * STR + c]     = acc[nf][2] + b0v;
                    sA[(r + 8) * STR + c + 1] = acc[nf][3] + b1v;
                }
            }
            __syncthreads();
            // warp wid handles rows wid*4 .. wid*4+3 (dout == 100)
            #pragma unroll
            for (int rr = 0; rr < 4; rr++) {
                int r = wid * 4 + rr;
                int m = row0 + r;
                if (m >= M) continue;
                const float* tr = sA + r * STR;
                float v0 = tr[lane];
                float v1 = tr[lane + 32];
                float v2 = tr[lane + 64];
                float v3 = (lane < 4) ? tr[lane + 96] : 0.f;
                float ss = v0 * v0 + v1 * v1 + v2 * v2 + v3 * v3;
                #pragma unroll
                for (int o = 16; o; o >>= 1) ss += __shfl_xor_sync(0xffffffffu, ss, o);
                float inv = 1.f / fmaxf(sqrtf(ss), 1e-12f);
                float* o = outp + (size_t)(degStart + m) * 100;
                o[lane]      = fmaxf(v0 * inv, 0.f);
                o[lane + 32] = fmaxf(v1 * inv, 0.f);
                o[lane + 64] = fmaxf(v2 * inv, 0.f);
                if (lane < 4) o[lane + 96] = fmaxf(v3 * inv, 0.f);
            }
        }
    }

    if (MODE == 1) {
        __syncthreads();
        if (tid < 128 && row0 + tid < M)
            g_inv[degStart + row0 + tid] = 1.f / fmaxf(sqrtf(sSS[tid]), 1e-12f);
    }
}

// ---------------- layer-2 relu(t * inv) + molecule segment-sum (pure streaming) ----------------
__global__ void molsum_kernel(float* __restrict__ out)
{
    int m   = blockIdx.x;
    int tid = threadIdx.x;
    float acc0 = 0.f, acc1 = 0.f;
    const float* base = g_T + (size_t)m * 20 * 512;
    #pragma unroll 4
    for (int a = 0; a < 20; a++) {
        const float* row = base + a * 512;
        float inv = g_inv[m * 20 + a];
        acc0 += fmaxf(row[tid]       * inv, 0.f);
        acc1 += fmaxf(row[tid + 256] * inv, 0.f);
    }
    out[(size_t)m * 512 + tid]       = acc0;
    out[(size_t)m * 512 + 256 + tid] = acc1;
}

// ---------------- host ----------------
extern "C" void kernel_launch(void* const* d_in, const int* in_sizes, int n_in,
                              void* d_out, int out_size)
{
    const float* atom = (const float*)d_in[0];
    const float* bond = (const float*)d_in[1];
    const int*   an[4];
    const int*   bn[4];
    const float *Ws[3], *bsv[3], *Wd[3], *bdv[3];
    int n1, n2, n3, n4;

    bool dictOrder = (in_sizes[3] == in_sizes[2]);
    if (!dictOrder) {
        for (int i = 0; i < 4; i++) { an[i] = (const int*)d_in[2 + i]; bn[i] = (const int*)d_in[6 + i]; }
        n1 = in_sizes[2]; n2 = in_sizes[3] / 2; n3 = in_sizes[4] / 3; n4 = in_sizes[5] / 4;
        Ws[0] = (const float*)d_in[11]; bsv[0] = (const float*)d_in[12];
        Ws[1] = (const float*)d_in[13]; bsv[1] = (const float*)d_in[14];
        Ws[2] = (const float*)d_in[15]; bsv[2] = (const float*)d_in[16];
        Wd[0] = (const float*)d_in[17]; bdv[0] = (const float*)d_in[18];
        Wd[1] = (const float*)d_in[19]; bdv[1] = (const float*)d_in[20];
        Wd[2] = (const float*)d_in[21]; bdv[2] = (const float*)d_in[22];
    } else {
        for (int i = 0; i < 4; i++) { an[i] = (const int*)d_in[2 + 2 * i]; bn[i] = (const int*)d_in[3 + 2 * i]; }
        n1 = in_sizes[2]; n2 = in_sizes[4] / 2; n3 = in_sizes[6] / 3; n4 = in_sizes[8] / 4;
        Ws[0] = (const float*)d_in[11]; bsv[0] = (const float*)d_in[12];
        Wd[0] = (const float*)d_in[13]; bdv[0] = (const float*)d_in[14];
        Ws[1] = (const float*)d_in[15]; bsv[1] = (const float*)d_in[16];
        Wd[1] = (const float*)d_in[17]; bdv[1] = (const float*)d_in[18];
        Ws[2] = (const float*)d_in[19]; bsv[2] = (const float*)d_in[20];
        Wd[2] = (const float*)d_in[21]; bdv[2] = (const float*)d_in[22];
    }

    float *pT, *pX0, *pX1, *pWt, *pbc;
    cudaGetSymbolAddress((void**)&pT,  g_T);
    cudaGetSymbolAddress((void**)&pX0, g_X0);
    cudaGetSymbolAddress((void**)&pX1, g_X1);
    cudaGetSymbolAddress((void**)&pWt, g_Wt);
    cudaGetSymbolAddress((void**)&pbc, g_bc);

    const int din_arr[3]  = {62, 100, 100};
    const int nd[4] = {n1, n2, n3, n4};
    const int degStart[4] = {0, n1, n1 + n2, n1 + n2 + n3};

    prep_kernel<<<1664, 384>>>(Ws[0], Wd[0], bsv[0], bdv[0],
                               Ws[1], Wd[1], bsv[1], bdv[1],
                               Ws[2], Wd[2], bsv[2], bdv[2]);

    const int smem0  = (2 * 128 * 152 + 256) * 4;   // 156,672  (KPAD=136, STR=152)
    const int smem12 = (2 * 128 * 216 + 256) * 4;   // 222,208  (KPAD=208, STR=216)
    cudaFuncSetAttribute(fused_gemm_kernel<136, 0>, cudaFuncAttributeMaxDynamicSharedMemorySize, smem0);
    cudaFuncSetAttribute(fused_gemm_kernel<208, 0>, cudaFuncAttributeMaxDynamicSharedMemorySize, smem12);
    cudaFuncSetAttribute(fused_gemm_kernel<208, 1>, cudaFuncAttributeMaxDynamicSharedMemorySize, smem12);

    const float* xin = atom;
    int ldx = 62;
    float* xbuf[2] = {pX0, pX1};

    for (int li = 0; li < 3; li++) {
        int din  = din_arr[li];
        int dout = (li < 2) ? 100 : 512;
        float* outp = (li < 2) ? xbuf[li] : pT;
        int numNt = (li < 2) ? 1 : 4;

        for (int d = 0; d < 4; d++) {
            if (nd[d] <= 0) continue;
            int grid = (nd[d] + 127) / 128;
            const float* WtD = pWt + (size_t)li * (4 * 512 * WT_STRIDE) + (size_t)d * (512 * WT_STRIDE);
            const float* bD  = pbc + li * 2048 + d * 512;
            if (li == 0)
                fused_gemm_kernel<136, 0><<<grid, 1024, smem0>>>(
                    xin, ldx, din, bond, an[d], bn[d], d + 1,
                    degStart[d], nd[d], WtD, bD, dout, numNt, outp);
            else if (li == 1)
                fused_gemm_kernel<208, 0><<<grid, 1024, smem12>>>(
                    xin, ldx, din, bond, an[d], bn[d], d + 1,
                    degStart[d], nd[d], WtD, bD, dout, numNt, outp);
            else
                fused_gemm_kernel<208, 1><<<grid, 1024, smem12>>>(
                    xin, ldx, din, bond, an[d], bn[d], d + 1,
                    degStart[d], nd[d], WtD, bD, dout, numNt, outp);
        }
        if (li < 2) { xin = xbuf[li]; ldx = 100; }
    }

    int nmol = out_size / 512;
    molsum_kernel<<<nmol, 256>>>((float*)d_out);
}

// round 10
// speedup vs baseline: 2.5640x; 1.1655x over previous
#include <cuda_runtime.h>
#include <cstdint>
#include <math.h>

#define NATOMS 500000
#define WT_STRIDE 208   // padded K storage for transposed weights (max K = 206)

// ---------------- scratch (static device globals) ----------------
__device__ float g_T[(size_t)NATOMS * 512];        // 1 GB   pre-norm layer-2 output
__device__ float g_X0[(size_t)NATOMS * 100];       // post-norm x (layer0 out)
__device__ float g_X1[(size_t)NATOMS * 100];       // post-norm x (layer1 out)
__device__ float g_inv[NATOMS];                    // layer-2 per-atom 1/||t||
__device__ float g_Wt[3 * 4 * 512 * WT_STRIDE];    // transposed concat weights, tf32, K-pair-interleaved
__device__ float g_bc[3 * 4 * 512];                // combined bias (fp32), zero padded

// ---------------- helpers ----------------
__device__ __forceinline__ float to_tf32(float f) {
    uint32_t u;
    asm("cvt.rna.tf32.f32 %0, %1;" : "=r"(u) : "f"(f));
    return __uint_as_float(u);
}

// K-pair interleave within each 8-block: logical k -> storage position.
__device__ __forceinline__ int permc(int c) {
    return (c & ~7) | ((c & 3) << 1) | ((c >> 2) & 1);
}

__device__ __forceinline__ uint32_t smem_u32(const void* p) {
    uint32_t a;
    asm("{ .reg .u64 t; cvta.to.shared.u64 t, %1; cvt.u32.u64 %0, t; }" : "=r"(a) : "l"(p));
    return a;
}

__device__ __forceinline__ void cp_async16(uint32_t saddr, const void* gptr) {
    asm volatile("cp.async.cg.shared.global [%0], [%1], 16;" :: "r"(saddr), "l"(gptr));
}
__device__ __forceinline__ void cp_async_commit_wait() {
    asm volatile("cp.async.commit_group;");
    asm volatile("cp.async.wait_group 0;" ::: "memory");
}

__device__ __forceinline__ void mma8(float& c0, float& c1, float& c2, float& c3,
                                     uint32_t a0, uint32_t a1, uint32_t a2, uint32_t a3,
                                     uint32_t b0, uint32_t b1) {
    asm volatile("mma.sync.aligned.m16n8k8.row.col.f32.tf32.tf32.f32 "
                 "{%0,%1,%2,%3}, {%4,%5,%6,%7}, {%8,%9}, {%0,%1,%2,%3};"
                 : "+f"(c0), "+f"(c1), "+f"(c2), "+f"(c3)
                 : "r"(a0), "r"(a1), "r"(a2), "r"(a3), "r"(b0), "r"(b1));
}

// ---------------- single-launch weight + bias prep (all 3 layers) ----------------
__global__ void prep_kernel(const float* __restrict__ Ws0, const float* __restrict__ Wd0,
                            const float* __restrict__ bs0, const float* __restrict__ bd0,
                            const float* __restrict__ Ws1, const float* __restrict__ Wd1,
                            const float* __restrict__ bs1, const float* __restrict__ bd1,
                            const float* __restrict__ Ws2, const float* __restrict__ Wd2,
                            const float* __restrict__ bs2, const float* __restrict__ bd2)
{
    const float* Ws[3] = {Ws0, Ws1, Ws2};
    const float* Wd[3] = {Wd0, Wd1, Wd2};
    const float* bs[3] = {bs0, bs1, bs2};
    const float* bd[3] = {bd0, bd1, bd2};
    const int din_arr[3]  = {62, 100, 100};
    const int dout_arr[3] = {100, 100, 512};

    const int perL = 4 * 512 * WT_STRIDE;
    const int total = 3 * perL;
    for (int idx = blockIdx.x * blockDim.x + threadIdx.x; idx < total; idx += gridDim.x * blockDim.x) {
        int li  = idx / perL;
        int rem = idx - li * perL;
        int d   = rem / (512 * WT_STRIDE);
        int r2  = rem - d * (512 * WT_STRIDE);
        int n   = r2 / WT_STRIDE;
        int ks  = r2 - n * WT_STRIDE;                 // storage position
        int k   = (ks & ~7) | ((ks & 7) >> 1) | ((ks & 1) << 2);  // inverse interleave
        int din = din_arr[li], dout = dout_arr[li];
        int K = 2 * din + 6;
        float v = 0.f;
        if (n < dout && k < K) {
            if (k < din) v = Ws[li][(size_t)k * dout + n];
            else {
                int r = (k < 2 * din) ? (k - din) : (din + (k - 2 * din));
                v = Wd[li][((size_t)d * (din + 6) + r) * dout + n];
            }
            v = to_tf32(v);
        }
        g_Wt[idx] = v;
    }
    for (int idx = blockIdx.x * blockDim.x + threadIdx.x; idx < 3 * 2048; idx += gridDim.x * blockDim.x) {
        int li = idx / 2048;
        int r  = idx - li * 2048;
        int d  = r >> 9, j = r & 511;
        int dout = dout_arr[li];
        g_bc[idx] = (j < dout) ? (bs[li][j] + bd[li][d * dout + j]) : 0.f;
    }
}

// ---------------- fused gather + tf32 mma.sync GEMM + epilogue ----------------
// 1024 threads, 32 warps (8 M x 4 N), warp tile 16x32, LDS.64 fragment loads.
// DIN/DEG compile-time -> fully unrolled, branch-free gather with batched LDGs.
// MODE 0: dout==100, fused bias + L2-normalize + relu -> outp (ld 100), 1 N-tile
// MODE 1: bias add -> g_T (ld 512), 4 N-tiles; row sum-of-squares -> g_inv
template<int KPAD, int DIN, int DEG, int MODE>
__global__ __launch_bounds__(1024)
void fused_gemm_kernel(const float* __restrict__ x,
                       const float* __restrict__ bond,
                       const int* __restrict__ an, const int* __restrict__ bn,
                       int degStart, int M,
                       const float* __restrict__ Wt, const float* __restrict__ bias,
                       float* __restrict__ outp)
{
    constexpr int STR = (KPAD == 136) ? 152 : 216;   // STR % 32 == 24, even
    constexpr int K   = 2 * DIN + 6;
    constexpr int NIT = (DIN + 31) / 32;
    constexpr int numNt = (MODE == 0) ? 1 : 4;
    extern __shared__ float smem[];
    float* sA    = smem;                     // [128][STR]
    float* sB    = smem + 128 * STR;         // [128][STR]
    float* sBias = smem + 2 * 128 * STR;     // [128]
    float* sSS   = sBias + 128;              // [128] per-row sum of squares (MODE 1)
    const uint32_t sBu = smem_u32(sB);

    const int tid  = threadIdx.x;
    const int wid  = tid >> 5;               // 0..31
    const int lane = tid & 31;
    const int grp  = lane >> 2;              // 0..7
    const int tig  = lane & 3;               // 0..3
    const int wm   = wid & 7;                // warp M index (8)  -> 16 rows each
    const int wn   = wid >> 3;               // warp N index (4)  -> 32 cols each
    const int row0 = blockIdx.x * 128;

    if (MODE == 1 && tid < 128) sSS[tid] = 0.f;

    // ---- issue B tile for nt=0 (async) BEFORE gather: overlap with gather latency ----
    {
        const float4* W4 = (const float4*)Wt;
        constexpr int KV4 = KPAD / 4;
        for (int i = tid; i < 128 * KV4; i += 1024) {
            int rowb = i / KV4;
            int kc4  = i - rowb * KV4;
            cp_async16(sBu + (uint32_t)(rowb * STR + kc4 * 4) * 4,
                       W4 + (size_t)rowb * (WT_STRIDE / 4) + kc4);
        }
        asm volatile("cp.async.commit_group;");
        if (tid < 128) sBias[tid] = bias[tid];
    }

    // ---- gather-fill A tile: branch-free, batched LDGs, warp handles 4 rows ----
    #pragma unroll
    for (int rr = 0; rr < 4; rr++) {
        const int r = wid * 4 + rr;
        const bool valid = (row0 + r) < M;
        const int mi = valid ? (row0 + r) : 0;

        // prefetch all indices first (uniform per warp, L1-broadcast)
        int aidx[DEG], bidx[DEG];
        #pragma unroll
        for (int j = 0; j < DEG; j++) {
            aidx[j] = __ldg(an + (size_t)mi * DEG + j);
            bidx[j] = __ldg(bn + (size_t)mi * DEG + j);
        }

        // batched feature loads: constant trip counts, all independent
        const float* xs = x + (size_t)(degStart + mi) * DIN;
        float selfv[NIT], sumv[NIT];
        #pragma unroll
        for (int it = 0; it < NIT; it++) {
            const int c = lane + 32 * it;
            const bool inb = (c < DIN);
            const int cc = inb ? c : 0;
            selfv[it] = __ldg(xs + cc);
            float s = 0.f;
            #pragma unroll
            for (int j = 0; j < DEG; j++)
                s += __ldg(x + (size_t)aidx[j] * DIN + cc);
            sumv[it] = s;
        }
        float bsum = 0.f;
        {
            const int bl = (lane < 6) ? lane : 0;
            #pragma unroll
            for (int j = 0; j < DEG; j++)
                bsum += __ldg(bond + (size_t)bidx[j] * 6 + bl);
        }

        // stores (predicated on validity / in-bounds)
        float* Ar = sA + r * STR;
        if (valid) {
            #pragma unroll
            for (int it = 0; it < NIT; it++) {
                const int c = lane + 32 * it;
                if (c < DIN) {
                    Ar[permc(c)]       = to_tf32(selfv[it]);
                    Ar[permc(DIN + c)] = to_tf32(sumv[it]);
                }
            }
            if (lane < 6) Ar[permc(2 * DIN + lane)] = to_tf32(bsum);
        }
        #pragma unroll
        for (int c0 = K & ~31; c0 < KPAD; c0 += 32) {
            const int c = c0 + lane;
            if (c >= K && c < KPAD) Ar[permc(c)] = 0.f;
        }
    }

    asm volatile("cp.async.wait_group 0;" ::: "memory");
    __syncthreads();

    // fragment base pointers (float2 = one K pair)
    const float2* paLo = (const float2*)(sA + (wm * 16 + grp) * STR) + tig;
    const float2* paHi = (const float2*)(sA + (wm * 16 + grp + 8) * STR) + tig;
    const float2* pb2  = (const float2*)(sB + (wn * 32 + grp) * STR) + tig;

    for (int nt = 0; nt < numNt; nt++) {
        const int ncol0 = nt * 128;
        if (nt > 0) {
            __syncthreads();   // prior epilogue reads done before refill
            const float4* W4 = (const float4*)Wt;
            constexpr int KV4 = KPAD / 4;
            for (int i = tid; i < 128 * KV4; i += 1024) {
                int rowb = i / KV4;
                int kc4  = i - rowb * KV4;
                cp_async16(sBu + (uint32_t)(rowb * STR + kc4 * 4) * 4,
                           W4 + (size_t)(ncol0 + rowb) * (WT_STRIDE / 4) + kc4);
            }
            if (tid < 128) sBias[tid] = bias[ncol0 + tid];
            cp_async_commit_wait();
            __syncthreads();
        }

        // ---- mma.sync mainloop over full K (LDS.64 fragment loads) ----
        float acc[4][4];
        #pragma unroll
        for (int nf = 0; nf < 4; nf++)
            #pragma unroll
            for (int q = 0; q < 4; q++) acc[nf][q] = 0.f;

        #pragma unroll 4
        for (int k0 = 0; k0 < KPAD; k0 += 8) {
            const int kk = k0 >> 1;          // float2 index
            float2 aLo = paLo[kk];
            float2 aHi = paHi[kk];
            float2 bv[4];
            #pragma unroll
            for (int nf = 0; nf < 4; nf++)
                bv[nf] = pb2[nf * 4 * STR + kk];
            #pragma unroll
            for (int nf = 0; nf < 4; nf++)
                mma8(acc[nf][0], acc[nf][1], acc[nf][2], acc[nf][3],
                     __float_as_uint(aLo.x), __float_as_uint(aHi.x),
                     __float_as_uint(aLo.y), __float_as_uint(aHi.y),
                     __float_as_uint(bv[nf].x), __float_as_uint(bv[nf].y));
        }

        if (MODE == 1) {
            // direct streaming store with bias + per-row sum-of-squares accumulation
            int r = wm * 16 + grp;
            float ss0 = 0.f, ss1 = 0.f;
            #pragma unroll
            for (int nf = 0; nf < 4; nf++) {
                int c = wn * 32 + nf * 8 + 2 * tig;
                float b0v = sBias[c], b1v = sBias[c + 1];
                float t0 = acc[nf][0] + b0v, t1 = acc[nf][1] + b1v;
                float t2 = acc[nf][2] + b0v, t3 = acc[nf][3] + b1v;
                ss0 += t0 * t0 + t1 * t1;
                ss1 += t2 * t2 + t3 * t3;
                if (row0 + r < M)
                    __stcs((float2*)(outp + (size_t)(degStart + row0 + r) * 512 + ncol0 + c),
                           make_float2(t0, t1));
                if (row0 + r + 8 < M)
                    __stcs((float2*)(outp + (size_t)(degStart + row0 + r + 8) * 512 + ncol0 + c),
                           make_float2(t2, t3));
            }
            if (row0 + r < M)     atomicAdd(&sSS[r], ss0);
            if (row0 + r + 8 < M) atomicAdd(&sSS[r + 8], ss1);
        } else {
            // stage t = acc + bias into sA (A panel no longer needed), then row-norm
            __syncthreads();
            {
                int r = wm * 16 + grp;
                #pragma unroll
                for (int nf = 0; nf < 4; nf++) {
                    int c = wn * 32 + nf * 8 + 2 * tig;
                    float b0v = sBias[c], b1v = sBias[c + 1];
                    sA[r * STR + c]           = acc[nf][0] + b0v;
                    sA[r * STR + c + 1]       = acc[nf][1] + b1v;
                    sA[(r + 8) * STR + c]     = acc[nf][2] + b0v;
                    sA[(r + 8) * STR + c + 1] = acc[nf][3] + b1v;
                }
            }
            __syncthreads();
            // warp wid handles rows wid*4 .. wid*4+3 (dout == 100)
            #pragma unroll
            for (int rr = 0; rr < 4; rr++) {
                int r = wid * 4 + rr;
                int m = row0 + r;
                if (m >= M) continue;
                const float* tr = sA + r * STR;
                float v0 = tr[lane];
                float v1 = tr[lane + 32];
                float v2 = tr[lane + 64];
                float v3 = (lane < 4) ? tr[lane + 96] : 0.f;
                float ss = v0 * v0 + v1 * v1 + v2 * v2 + v3 * v3;
                #pragma unroll
                for (int o = 16; o; o >>= 1) ss += __shfl_xor_sync(0xffffffffu, ss, o);
                float inv = 1.f / fmaxf(sqrtf(ss), 1e-12f);
                float* o = outp + (size_t)(degStart + m) * 100;
                o[lane]      = fmaxf(v0 * inv, 0.f);
                o[lane + 32] = fmaxf(v1 * inv, 0.f);
                o[lane + 64] = fmaxf(v2 * inv, 0.f);
                if (lane < 4) o[lane + 96] = fmaxf(v3 * inv, 0.f);
            }
        }
    }

    if (MODE == 1) {
        __syncthreads();
        if (tid < 128 && row0 + tid < M)
            g_inv[degStart + row0 + tid] = 1.f / fmaxf(sqrtf(sSS[tid]), 1e-12f);
    }
}

// ---------------- layer-2 relu(t * inv) + molecule segment-sum (pure streaming) ----------------
__global__ void molsum_kernel(float* __restrict__ out)
{
    int m   = blockIdx.x;
    int tid = threadIdx.x;
    float acc0 = 0.f, acc1 = 0.f;
    const float* base = g_T + (size_t)m * 20 * 512;
    #pragma unroll 4
    for (int a = 0; a < 20; a++) {
        const float* row = base + a * 512;
        float inv = g_inv[m * 20 + a];
        acc0 += fmaxf(__ldcs(row + tid)       * inv, 0.f);
        acc1 += fmaxf(__ldcs(row + tid + 256) * inv, 0.f);
    }
    out[(size_t)m * 512 + tid]       = acc0;
    out[(size_t)m * 512 + 256 + tid] = acc1;
}

// ---------------- host ----------------
extern "C" void kernel_launch(void* const* d_in, const int* in_sizes, int n_in,
                              void* d_out, int out_size)
{
    const float* atom = (const float*)d_in[0];
    const float* bond = (const float*)d_in[1];
    const int*   an[4];
    const int*   bn[4];
    const float *Ws[3], *bsv[3], *Wd[3], *bdv[3];
    int n1, n2, n3, n4;

    bool dictOrder = (in_sizes[3] == in_sizes[2]);
    if (!dictOrder) {
        for (int i = 0; i < 4; i++) { an[i] = (const int*)d_in[2 + i]; bn[i] = (const int*)d_in[6 + i]; }
        n1 = in_sizes[2]; n2 = in_sizes[3] / 2; n3 = in_sizes[4] / 3; n4 = in_sizes[5] / 4;
        Ws[0] = (const float*)d_in[11]; bsv[0] = (const float*)d_in[12];
        Ws[1] = (const float*)d_in[13]; bsv[1] = (const float*)d_in[14];
        Ws[2] = (const float*)d_in[15]; bsv[2] = (const float*)d_in[16];
        Wd[0] = (const float*)d_in[17]; bdv[0] = (const float*)d_in[18];
        Wd[1] = (const float*)d_in[19]; bdv[1] = (const float*)d_in[20];
        Wd[2] = (const float*)d_in[21]; bdv[2] = (const float*)d_in[22];
    } else {
        for (int i = 0; i < 4; i++) { an[i] = (const int*)d_in[2 + 2 * i]; bn[i] = (const int*)d_in[3 + 2 * i]; }
        n1 = in_sizes[2]; n2 = in_sizes[4] / 2; n3 = in_sizes[6] / 3; n4 = in_sizes[8] / 4;
        Ws[0] = (const float*)d_in[11]; bsv[0] = (const float*)d_in[12];
        Wd[0] = (const float*)d_in[13]; bdv[0] = (const float*)d_in[14];
        Ws[1] = (const float*)d_in[15]; bsv[1] = (const float*)d_in[16];
        Wd[1] = (const float*)d_in[17]; bdv[1] = (const float*)d_in[18];
        Ws[2] = (const float*)d_in[19]; bsv[2] = (const float*)d_in[20];
        Wd[2] = (const float*)d_in[21]; bdv[2] = (const float*)d_in[22];
    }

    float *pT, *pX0, *pX1, *pWt, *pbc;
    cudaGetSymbolAddress((void**)&pT,  g_T);
    cudaGetSymbolAddress((void**)&pX0, g_X0);
    cudaGetSymbolAddress((void**)&pX1, g_X1);
    cudaGetSymbolAddress((void**)&pWt, g_Wt);
    cudaGetSymbolAddress((void**)&pbc, g_bc);

    const int nd[4] = {n1, n2, n3, n4};
    const int degStart[4] = {0, n1, n1 + n2, n1 + n2 + n3};

    prep_kernel<<<1664, 384>>>(Ws[0], Wd[0], bsv[0], bdv[0],
                               Ws[1], Wd[1], bsv[1], bdv[1],
                               Ws[2], Wd[2], bsv[2], bdv[2]);

    const int smem0  = (2 * 128 * 152 + 256) * 4;   // 156,672  (KPAD=136, STR=152)
    const int smem12 = (2 * 128 * 216 + 256) * 4;   // 222,208  (KPAD=208, STR=216)

    #define SETSM(KP, DN, DG, MD, SZ) \
        cudaFuncSetAttribute((const void*)fused_gemm_kernel<KP, DN, DG, MD>, \
                             cudaFuncAttributeMaxDynamicSharedMemorySize, SZ)
    SETSM(136, 62, 1, 0, smem0);  SETSM(136, 62, 2, 0, smem0);
    SETSM(136, 62, 3, 0, smem0);  SETSM(136, 62, 4, 0, smem0);
    SETSM(208, 100, 1, 0, smem12); SETSM(208, 100, 2, 0, smem12);
    SETSM(208, 100, 3, 0, smem12); SETSM(208, 100, 4, 0, smem12);
    SETSM(208, 100, 1, 1, smem12); SETSM(208, 100, 2, 1, smem12);
    SETSM(208, 100, 3, 1, smem12); SETSM(208, 100, 4, 1, smem12);

    const float* xin = atom;
    float* xbuf[2] = {pX0, pX1};

    for (int li = 0; li < 3; li++) {
        float* outp = (li < 2) ? xbuf[li] : pT;
        for (int d = 0; d < 4; d++) {
            if (nd[d] <= 0) continue;
            int grid = (nd[d] + 127) / 128;
            // layer index within g_Wt/g_bc
            const float* WtD = pWt + (size_t)li * (4 * 512 * WT_STRIDE) + (size_t)d * (512 * WT_STRIDE);
            const float* bD  = pbc + li * 2048 + d * 512;
            #define LGK(KP, DN, MD, SM) do { \
                switch (d) { \
                case 0: fused_gemm_kernel<KP, DN, 1, MD><<<grid, 1024, SM>>>(xin, bond, an[0], bn[0], degStart[0], nd[0], WtD, bD, outp); break; \
                case 1: fused_gemm_kernel<KP, DN, 2, MD><<<grid, 1024, SM>>>(xin, bond, an[1], bn[1], degStart[1], nd[1], WtD, bD, outp); break; \
                case 2: fused_gemm_kernel<KP, DN, 3, MD><<<grid, 1024, SM>>>(xin, bond, an[2], bn[2], degStart[2], nd[2], WtD, bD, outp); break; \
                case 3: fused_gemm_kernel<KP, DN, 4, MD><<<grid, 1024, SM>>>(xin, bond, an[3], bn[3], degStart[3], nd[3], WtD, bD, outp); break; \
                } } while (0)
            if (li == 0)      LGK(136, 62, 0, smem0);
            else if (li == 1) LGK(208, 100, 0, smem12);
            else              LGK(208, 100, 1, smem12);
        }
        if (li < 2) xin = xbuf[li];
    }

    int nmol = out_size / 512;
    molsum_kernel<<<nmol, 256>>>((float*)d_out);
}

// round 12
// speedup vs baseline: 2.6556x; 1.0357x over previous
#include <cuda_runtime.h>
#include <cuda_fp16.h>
#include <cstdint>
#include <math.h>

#define NATOMS 500000
#define WT_STRIDE 208   // padded K storage for transposed weights (max K = 206)

// ---------------- scratch (static device globals) ----------------
__device__ __half g_Th[(size_t)NATOMS * 512];      // 0.5 GB  pre-norm layer-2 output (fp16 staging)
__device__ float g_X0[(size_t)NATOMS * 100];       // post-norm x (layer0 out)
__device__ float g_X1[(size_t)NATOMS * 100];       // post-norm x (layer1 out)
__device__ float g_inv[NATOMS];                    // layer-2 per-atom 1/||t|| (from fp32 accs)
__device__ float g_Wt[3 * 4 * 512 * WT_STRIDE];    // transposed concat weights, tf32, K-pair-interleaved
__device__ float g_bc[3 * 4 * 512];                // combined bias (fp32), zero padded

// ---------------- helpers ----------------
__device__ __forceinline__ float to_tf32(float f) {
    uint32_t u;
    asm("cvt.rna.tf32.f32 %0, %1;" : "=r"(u) : "f"(f));
    return __uint_as_float(u);
}

// K-pair interleave within each 8-block: logical k -> storage position.
__device__ __forceinline__ int permc(int c) {
    return (c & ~7) | ((c & 3) << 1) | ((c >> 2) & 1);
}

__device__ __forceinline__ uint32_t smem_u32(const void* p) {
    uint32_t a;
    asm("{ .reg .u64 t; cvta.to.shared.u64 t, %1; cvt.u32.u64 %0, t; }" : "=r"(a) : "l"(p));
    return a;
}

__device__ __forceinline__ void cp_async16(uint32_t saddr, const void* gptr) {
    asm volatile("cp.async.cg.shared.global [%0], [%1], 16;" :: "r"(saddr), "l"(gptr));
}
__device__ __forceinline__ void cp_async_commit_wait() {
    asm volatile("cp.async.commit_group;");
    asm volatile("cp.async.wait_group 0;" ::: "memory");
}

__device__ __forceinline__ void mma8(float& c0, float& c1, float& c2, float& c3,
                                     uint32_t a0, uint32_t a1, uint32_t a2, uint32_t a3,
                                     uint32_t b0, uint32_t b1) {
    asm volatile("mma.sync.aligned.m16n8k8.row.col.f32.tf32.tf32.f32 "
                 "{%0,%1,%2,%3}, {%4,%5,%6,%7}, {%8,%9}, {%0,%1,%2,%3};"
                 : "+f"(c0), "+f"(c1), "+f"(c2), "+f"(c3)
                 : "r"(a0), "r"(a1), "r"(a2), "r"(a3), "r"(b0), "r"(b1));
}

// ---------------- single-launch weight + bias prep (all 3 layers) ----------------
__global__ void prep_kernel(const float* __restrict__ Ws0, const float* __restrict__ Wd0,
                            const float* __restrict__ bs0, const float* __restrict__ bd0,
                            const float* __restrict__ Ws1, const float* __restrict__ Wd1,
                            const float* __restrict__ bs1, const float* __restrict__ bd1,
                            const float* __restrict__ Ws2, const float* __restrict__ Wd2,
                            const float* __restrict__ bs2, const float* __restrict__ bd2)
{
    const float* Ws[3] = {Ws0, Ws1, Ws2};
    const float* Wd[3] = {Wd0, Wd1, Wd2};
    const float* bs[3] = {bs0, bs1, bs2};
    const float* bd[3] = {bd0, bd1, bd2};
    const int din_arr[3]  = {62, 100, 100};
    const int dout_arr[3] = {100, 100, 512};

    const int perL = 4 * 512 * WT_STRIDE;
    const int total = 3 * perL;
    for (int idx = blockIdx.x * blockDim.x + threadIdx.x; idx < total; idx += gridDim.x * blockDim.x) {
        int li  = idx / perL;
        int rem = idx - li * perL;
        int d   = rem / (512 * WT_STRIDE);
        int r2  = rem - d * (512 * WT_STRIDE);
        int n   = r2 / WT_STRIDE;
        int ks  = r2 - n * WT_STRIDE;                 // storage position
        int k   = (ks & ~7) | ((ks & 7) >> 1) | ((ks & 1) << 2);  // inverse interleave
        int din = din_arr[li], dout = dout_arr[li];
        int K = 2 * din + 6;
        float v = 0.f;
        if (n < dout && k < K) {
            if (k < din) v = Ws[li][(size_t)k * dout + n];
            else {
                int r = (k < 2 * din) ? (k - din) : (din + (k - 2 * din));
                v = Wd[li][((size_t)d * (din + 6) + r) * dout + n];
            }
            v = to_tf32(v);
        }
        g_Wt[idx] = v;
    }
    for (int idx = blockIdx.x * blockDim.x + threadIdx.x; idx < 3 * 2048; idx += gridDim.x * blockDim.x) {
        int li = idx / 2048;
        int r  = idx - li * 2048;
        int d  = r >> 9, j = r & 511;
        int dout = dout_arr[li];
        g_bc[idx] = (j < dout) ? (bs[li][j] + bd[li][d * dout + j]) : 0.f;
    }
}

// ---------------- fused gather + tf32 mma.sync GEMM + epilogue ----------------
// 1024 threads, 32 warps (8 M x 4 N), warp tile 16x32, LDS.64 fragment loads,
// 1-step software-pipelined mainloop (fragment float2-index stride = 4 per k-step).
// MODE 0: dout==100, fused bias + L2-normalize + relu -> (float*)outp (ld 100), 1 N-tile
// MODE 1: bias add -> g_Th (fp16, ld 512), 4 N-tiles; row sum-of-squares (fp32) -> g_inv
template<int KPAD, int DIN, int DEG, int MODE>
__global__ __launch_bounds__(1024)
void fused_gemm_kernel(const float* __restrict__ x,
                       const float* __restrict__ bond,
                       const int* __restrict__ an, const int* __restrict__ bn,
                       int degStart, int M,
                       const float* __restrict__ Wt, const float* __restrict__ bias,
                       void* __restrict__ outp)
{
    constexpr int STR = (KPAD == 136) ? 152 : 216;   // STR % 32 == 24, even
    constexpr int K   = 2 * DIN + 6;
    constexpr int NIT = (DIN + 31) / 32;
    constexpr int numNt = (MODE == 0) ? 1 : 4;
    constexpr int NKS = KPAD / 8;                    // k-steps
    extern __shared__ float smem[];
    float* sA    = smem;                     // [128][STR]
    float* sB    = smem + 128 * STR;         // [128][STR]
    float* sBias = smem + 2 * 128 * STR;     // [512]
    float* sSS   = sBias + 512;              // [128] per-row sum of squares (MODE 1)
    const uint32_t sBu = smem_u32(sB);

    const int tid  = threadIdx.x;
    const int wid  = tid >> 5;               // 0..31
    const int lane = tid & 31;
    const int grp  = lane >> 2;              // 0..7
    const int tig  = lane & 3;               // 0..3
    const int wm   = wid & 7;                // warp M index (8)  -> 16 rows each
    const int wn   = wid >> 3;               // warp N index (4)  -> 32 cols each
    const int row0 = blockIdx.x * 128;

    if (MODE == 1 && tid < 128) sSS[tid] = 0.f;

    // ---- issue B tile for nt=0 (async) BEFORE gather; load full bias (overlap gather) ----
    {
        const float4* W4 = (const float4*)Wt;
        constexpr int KV4 = KPAD / 4;
        for (int i = tid; i < 128 * KV4; i += 1024) {
            int rowb = i / KV4;
            int kc4  = i - rowb * KV4;
            cp_async16(sBu + (uint32_t)(rowb * STR + kc4 * 4) * 4,
                       W4 + (size_t)rowb * (WT_STRIDE / 4) + kc4);
        }
        asm volatile("cp.async.commit_group;");
        if (MODE == 1) { if (tid < 512) sBias[tid] = bias[tid]; }
        else           { if (tid < 128) sBias[tid] = bias[tid]; }
    }

    // ---- gather-fill A tile: branch-free, batched LDGs, warp handles 4 rows ----
    #pragma unroll
    for (int rr = 0; rr < 4; rr++) {
        const int r = wid * 4 + rr;
        const bool valid = (row0 + r) < M;
        const int mi = valid ? (row0 + r) : 0;

        int aidx[DEG], bidx[DEG];
        #pragma unroll
        for (int j = 0; j < DEG; j++) {
            aidx[j] = __ldg(an + (size_t)mi * DEG + j);
            bidx[j] = __ldg(bn + (size_t)mi * DEG + j);
        }

        const float* xs = x + (size_t)(degStart + mi) * DIN;
        float selfv[NIT], sumv[NIT];
        #pragma unroll
        for (int it = 0; it < NIT; it++) {
            const int c = lane + 32 * it;
            const int cc = (c < DIN) ? c : 0;
            selfv[it] = __ldg(xs + cc);
            float s = 0.f;
            #pragma unroll
            for (int j = 0; j < DEG; j++)
                s += __ldg(x + (size_t)aidx[j] * DIN + cc);
            sumv[it] = s;
        }
        float bsum = 0.f;
        {
            const int bl = (lane < 6) ? lane : 0;
            #pragma unroll
            for (int j = 0; j < DEG; j++)
                bsum += __ldg(bond + (size_t)bidx[j] * 6 + bl);
        }

        float* Ar = sA + r * STR;
        if (valid) {
            #pragma unroll
            for (int it = 0; it < NIT; it++) {
                const int c = lane + 32 * it;
                if (c < DIN) {
                    Ar[permc(c)]       = to_tf32(selfv[it]);
                    Ar[permc(DIN + c)] = to_tf32(sumv[it]);
                }
            }
            if (lane < 6) Ar[permc(2 * DIN + lane)] = to_tf32(bsum);
        }
        #pragma unroll
        for (int c0 = K & ~31; c0 < KPAD; c0 += 32) {
            const int c = c0 + lane;
            if (c >= K && c < KPAD) Ar[permc(c)] = 0.f;
        }
    }

    asm volatile("cp.async.wait_group 0;" ::: "memory");
    __syncthreads();

    // fragment base pointers (float2 = one K pair); per-k-step float2 stride = 4
    const float2* paLo = (const float2*)(sA + (wm * 16 + grp) * STR) + tig;
    const float2* paHi = (const float2*)(sA + (wm * 16 + grp + 8) * STR) + tig;
    const float2* pb2  = (const float2*)(sB + (wn * 32 + grp) * STR) + tig;

    for (int nt = 0; nt < numNt; nt++) {
        const int ncol0 = nt * 128;
        if (nt > 0) {
            __syncthreads();   // prior epilogue reads done before refill
            const float4* W4 = (const float4*)Wt;
            constexpr int KV4 = KPAD / 4;
            for (int i = tid; i < 128 * KV4; i += 1024) {
                int rowb = i / KV4;
                int kc4  = i - rowb * KV4;
                cp_async16(sBu + (uint32_t)(rowb * STR + kc4 * 4) * 4,
                           W4 + (size_t)(ncol0 + rowb) * (WT_STRIDE / 4) + kc4);
            }
            cp_async_commit_wait();
            __syncthreads();
        }

        // ---- mma.sync mainloop, software-pipelined 1 k-step ahead ----
        float acc[4][4];
        #pragma unroll
        for (int nf = 0; nf < 4; nf++)
            #pragma unroll
            for (int q = 0; q < 4; q++) acc[nf][q] = 0.f;

        float2 aLo = paLo[0], aHi = paHi[0];
        float2 bv[4];
        #pragma unroll
        for (int nf = 0; nf < 4; nf++) bv[nf] = pb2[nf * 4 * STR];

        #pragma unroll
        for (int ks = 0; ks < NKS; ks++) {
            float2 naLo, naHi, nbv[4];
            if (ks + 1 < NKS) {
                const int kk = 4 * (ks + 1);     // float2 index of next k-step
                naLo = paLo[kk];
                naHi = paHi[kk];
                #pragma unroll
                for (int nf = 0; nf < 4; nf++) nbv[nf] = pb2[nf * 4 * STR + kk];
            }
            #pragma unroll
            for (int nf = 0; nf < 4; nf++)
                mma8(acc[nf][0], acc[nf][1], acc[nf][2], acc[nf][3],
                     __float_as_uint(aLo.x), __float_as_uint(aHi.x),
                     __float_as_uint(aLo.y), __float_as_uint(aHi.y),
                     __float_as_uint(bv[nf].x), __float_as_uint(bv[nf].y));
            if (ks + 1 < NKS) {
                aLo = naLo; aHi = naHi;
                #pragma unroll
                for (int nf = 0; nf < 4; nf++) bv[nf] = nbv[nf];
            }
        }

        if (MODE == 1) {
            // fp16 streaming store with bias + fp32 per-row sum-of-squares accumulation
            __half* outh = (__half*)outp;
            int r = wm * 16 + grp;
            float ss0 = 0.f, ss1 = 0.f;
            #pragma unroll
            for (int nf = 0; nf < 4; nf++) {
                int c = wn * 32 + nf * 8 + 2 * tig;
                float b0v = sBias[ncol0 + c], b1v = sBias[ncol0 + c + 1];
                float t0 = acc[nf][0] + b0v, t1 = acc[nf][1] + b1v;
                float t2 = acc[nf][2] + b0v, t3 = acc[nf][3] + b1v;
                ss0 += t0 * t0 + t1 * t1;
                ss1 += t2 * t2 + t3 * t3;
                if (row0 + r < M) {
                    __half2 h = __floats2half2_rn(t0, t1);
                    __stcs((unsigned int*)(outh + (size_t)(degStart + row0 + r) * 512 + ncol0 + c),
                           *(unsigned int*)&h);
                }
                if (row0 + r + 8 < M) {
                    __half2 h = __floats2half2_rn(t2, t3);
                    __stcs((unsigned int*)(outh + (size_t)(degStart + row0 + r + 8) * 512 + ncol0 + c),
                           *(unsigned int*)&h);
                }
            }
            if (row0 + r < M)     atomicAdd(&sSS[r], ss0);
            if (row0 + r + 8 < M) atomicAdd(&sSS[r + 8], ss1);
        } else {
            // stage t = acc + bias into sA (A panel no longer needed), then row-norm
            float* outf = (float*)outp;
            __syncthreads();
            {
                int r = wm * 16 + grp;
                #pragma unroll
                for (int nf = 0; nf < 4; nf++) {
                    int c = wn * 32 + nf * 8 + 2 * tig;
                    float b0v = sBias[c], b1v = sBias[c + 1];
                    sA[r * STR + c]           = acc[nf][0] + b0v;
                    sA[r * STR + c + 1]       = acc[nf][1] + b1v;
                    sA[(r + 8) * STR + c]     = acc[nf][2] + b0v;
                    sA[(r + 8) * STR + c + 1] = acc[nf][3] + b1v;
                }
            }
            __syncthreads();
            // warp wid handles rows wid*4 .. wid*4+3 (dout == 100)
            #pragma unroll
            for (int rr = 0; rr < 4; rr++) {
                int r = wid * 4 + rr;
                int m = row0 + r;
                if (m >= M) continue;
                const float* tr = sA + r * STR;
                float v0 = tr[lane];
                float v1 = tr[lane + 32];
                float v2 = tr[lane + 64];
                float v3 = (lane < 4) ? tr[lane + 96] : 0.f;
                float ss = v0 * v0 + v1 * v1 + v2 * v2 + v3 * v3;
                #pragma unroll
                for (int o = 16; o; o >>= 1) ss += __shfl_xor_sync(0xffffffffu, ss, o);
                float inv = 1.f / fmaxf(sqrtf(ss), 1e-12f);
                float* o = outf + (size_t)(degStart + m) * 100;
                o[lane]      = fmaxf(v0 * inv, 0.f);
                o[lane + 32] = fmaxf(v1 * inv, 0.f);
                o[lane + 64] = fmaxf(v2 * inv, 0.f);
                if (lane < 4) o[lane + 96] = fmaxf(v3 * inv, 0.f);
            }
        }
    }

    if (MODE == 1) {
        __syncthreads();
        if (tid < 128 && row0 + tid < M)
            g_inv[degStart + row0 + tid] = 1.f / fmaxf(sqrtf(sSS[tid]), 1e-12f);
    }
}

// ---------------- layer-2 relu(t * inv) + molecule segment-sum (fp16 stream) ----------------
__global__ void molsum_kernel(float* __restrict__ out)
{
    int m   = blockIdx.x;
    int tid = threadIdx.x;     // 256 threads, thread handles cols 2tid, 2tid+1
    float acc0 = 0.f, acc1 = 0.f;
    const __half* base = g_Th + (size_t)m * 20 * 512;
    #pragma unroll 4
    for (int a = 0; a < 20; a++) {
        unsigned int raw = __ldcs((const unsigned int*)(base + a * 512) + tid);
        __half2 h = *(__half2*)&raw;
        float2 f = __half22float2(h);
        float inv = g_inv[m * 20 + a];
        acc0 += fmaxf(f.x * inv, 0.f);
        acc1 += fmaxf(f.y * inv, 0.f);
    }
    out[(size_t)m * 512 + 2 * tid]     = acc0;
    out[(size_t)m * 512 + 2 * tid + 1] = acc1;
}

// ---------------- host ----------------
extern "C" void kernel_launch(void* const* d_in, const int* in_sizes, int n_in,
                              void* d_out, int out_size)
{
    const float* atom = (const float*)d_in[0];
    const float* bond = (const float*)d_in[1];
    const int*   an[4];
    const int*   bn[4];
    const float *Ws[3], *bsv[3], *Wd[3], *bdv[3];
    int n1, n2, n3, n4;

    bool dictOrder = (in_sizes[3] == in_sizes[2]);
    if (!dictOrder) {
        for (int i = 0; i < 4; i++) { an[i] = (const int*)d_in[2 + i]; bn[i] = (const int*)d_in[6 + i]; }
        n1 = in_sizes[2]; n2 = in_sizes[3] / 2; n3 = in_sizes[4] / 3; n4 = in_sizes[5] / 4;
        Ws[0] = (const float*)d_in[11]; bsv[0] = (const float*)d_in[12];
        Ws[1] = (const float*)d_in[13]; bsv[1] = (const float*)d_in[14];
        Ws[2] = (const float*)d_in[15]; bsv[2] = (const float*)d_in[16];
        Wd[0] = (const float*)d_in[17]; bdv[0] = (const float*)d_in[18];
        Wd[1] = (const float*)d_in[19]; bdv[1] = (const float*)d_in[20];
        Wd[2] = (const float*)d_in[21]; bdv[2] = (const float*)d_in[22];
    } else {
        for (int i = 0; i < 4; i++) { an[i] = (const int*)d_in[2 + 2 * i]; bn[i] = (const int*)d_in[3 + 2 * i]; }
        n1 = in_sizes[2]; n2 = in_sizes[4] / 2; n3 = in_sizes[6] / 3; n4 = in_sizes[8] / 4;
        Ws[0] = (const float*)d_in[11]; bsv[0] = (const float*)d_in[12];
        Wd[0] = (const float*)d_in[13]; bdv[0] = (const float*)d_in[14];
        Ws[1] = (const float*)d_in[15]; bsv[1] = (const float*)d_in[16];
        Wd[1] = (const float*)d_in[17]; bdv[1] = (const float*)d_in[18];
        Ws[2] = (const float*)d_in[19]; bsv[2] = (const float*)d_in[20];
        Wd[2] = (const float*)d_in[21]; bdv[2] = (const float*)d_in[22];
    }

    float *pX0, *pX1, *pWt, *pbc;
    __half* pTh;
    cudaGetSymbolAddress((void**)&pTh, g_Th);
    cudaGetSymbolAddress((void**)&pX0, g_X0);
    cudaGetSymbolAddress((void**)&pX1, g_X1);
    cudaGetSymbolAddress((void**)&pWt, g_Wt);
    cudaGetSymbolAddress((void**)&pbc, g_bc);

    const int nd[4] = {n1, n2, n3, n4};
    const int degStart[4] = {0, n1, n1 + n2, n1 + n2 + n3};

    prep_kernel<<<1664, 384>>>(Ws[0], Wd[0], bsv[0], bdv[0],
                               Ws[1], Wd[1], bsv[1], bdv[1],
                               Ws[2], Wd[2], bsv[2], bdv[2]);

    const int smem0  = (2 * 128 * 152 + 512 + 128) * 4;   // 158,208  (KPAD=136, STR=152)
    const int smem12 = (2 * 128 * 216 + 512 + 128) * 4;   // 223,744  (KPAD=208, STR=216)

    #define SETSM(KP, DN, DG, MD, SZ) \
        cudaFuncSetAttribute((const void*)fused_gemm_kernel<KP, DN, DG, MD>, \
                             cudaFuncAttributeMaxDynamicSharedMemorySize, SZ)
    SETSM(136, 62, 1, 0, smem0);  SETSM(136, 62, 2, 0, smem0);
    SETSM(136, 62, 3, 0, smem0);  SETSM(136, 62, 4, 0, smem0);
    SETSM(208, 100, 1, 0, smem12); SETSM(208, 100, 2, 0, smem12);
    SETSM(208, 100, 3, 0, smem12); SETSM(208, 100, 4, 0, smem12);
    SETSM(208, 100, 1, 1, smem12); SETSM(208, 100, 2, 1, smem12);
    SETSM(208, 100, 3, 1, smem12); SETSM(208, 100, 4, 1, smem12);

    const float* xin = atom;
    float* xbuf[2] = {pX0, pX1};

    for (int li = 0; li < 3; li++) {
        void* outp = (li < 2) ? (void*)xbuf[li] : (void*)pTh;
        for (int d = 0; d < 4; d++) {
            if (nd[d] <= 0) continue;
            int grid = (nd[d] + 127) / 128;
            const float* WtD = pWt + (size_t)li * (4 * 512 * WT_STRIDE) + (size_t)d * (512 * WT_STRIDE);
            const float* bD  = pbc + li * 2048 + d * 512;
            #define LGK(KP, DN, MD, SM) do { \
                switch (d) { \
                case 0: fused_gemm_kernel<KP, DN, 1, MD><<<grid, 1024, SM>>>(xin, bond, an[0], bn[0], degStart[0], nd[0], WtD, bD, outp); break; \
                case 1: fused_gemm_kernel<KP, DN, 2, MD><<<grid, 1024, SM>>>(xin, bond, an[1], bn[1], degStart[1], nd[1], WtD, bD, outp); break; \
                case 2: fused_gemm_kernel<KP, DN, 3, MD><<<grid, 1024, SM>>>(xin, bond, an[2], bn[2], degStart[2], nd[2], WtD, bD, outp); break; \
                case 3: fused_gemm_kernel<KP, DN, 4, MD><<<grid, 1024, SM>>>(xin, bond, an[3], bn[3], degStart[3], nd[3], WtD, bD, outp); break; \
                } } while (0)
            if (li == 0)      LGK(136, 62, 0, smem0);
            else if (li == 1) LGK(208, 100, 0, smem12);
            else              LGK(208, 100, 1, smem12);
        }
        if (li < 2) xin = xbuf[li];
    }

    int nmol = out_size / 512;
    molsum_kernel<<<nmol, 256>>>((float*)d_out);
}

// round 13
// speedup vs baseline: 3.6707x; 1.3823x over previous
#include <cuda_runtime.h>
#include <cuda_fp16.h>
#include <cstdint>
#include <math.h>

#define NATOMS 500000
#define WTSTR 208    // per-row stride (halves) of transposed weights, all layers

// ---------------- scratch (static device globals) ----------------
__device__ __half g_Th[(size_t)NATOMS * 512];      // 0.5 GB  pre-norm layer-2 output (fp16 staging)
__device__ float g_X0[(size_t)NATOMS * 100];       // post-norm x (layer0 out)
__device__ float g_X1[(size_t)NATOMS * 100];       // post-norm x (layer1 out)
__device__ float g_inv[NATOMS];                    // layer-2 per-atom 1/||t|| (from fp32 accs)
__device__ __half g_Wt[3 * 4 * 512 * WTSTR];       // transposed concat weights, fp16, K16-permuted
__device__ float g_bc[3 * 4 * 512];                // combined bias (fp32), zero padded

// ---------------- helpers ----------------
// K-permutation within each 16-block: logical k -> storage position.
// Groups: [k0,k1,k8,k9][k2,k3,k10,k11][k4,k5,k12,k13][k6,k7,k14,k15]
// so fragment pair (2t,2t+1),(2t+8,2t+9) is one aligned 64-bit load.
__device__ __forceinline__ int perm16(int k) {
    int j = k & 15;
    return (k & ~15) + ((j & 7) >> 1) * 4 + (j >> 3) * 2 + (j & 1);
}
// inverse: storage position -> logical k (for prep)
__device__ __forceinline__ int iperm16(int ks) {
    int j = ks & 15;
    return (ks & ~15) + ((j >> 1) & 1) * 8 + (j >> 2) * 2 + (j & 1);
}

__device__ __forceinline__ uint32_t smem_u32(const void* p) {
    uint32_t a;
    asm("{ .reg .u64 t; cvta.to.shared.u64 t, %1; cvt.u32.u64 %0, t; }" : "=r"(a) : "l"(p));
    return a;
}

__device__ __forceinline__ void cp_async16(uint32_t saddr, const void* gptr) {
    asm volatile("cp.async.cg.shared.global [%0], [%1], 16;" :: "r"(saddr), "l"(gptr));
}
__device__ __forceinline__ void cp_async_commit_wait() {
    asm volatile("cp.async.commit_group;");
    asm volatile("cp.async.wait_group 0;" ::: "memory");
}

__device__ __forceinline__ void mma16(float& c0, float& c1, float& c2, float& c3,
                                      uint32_t a0, uint32_t a1, uint32_t a2, uint32_t a3,
                                      uint32_t b0, uint32_t b1) {
    asm volatile("mma.sync.aligned.m16n8k16.row.col.f32.f16.f16.f32 "
                 "{%0,%1,%2,%3}, {%4,%5,%6,%7}, {%8,%9}, {%0,%1,%2,%3};"
                 : "+f"(c0), "+f"(c1), "+f"(c2), "+f"(c3)
                 : "r"(a0), "r"(a1), "r"(a2), "r"(a3), "r"(b0), "r"(b1));
}

// ---------------- single-launch weight + bias prep (all 3 layers, fp16 + perm16) ----------------
__global__ void prep_kernel(const float* __restrict__ Ws0, const float* __restrict__ Wd0,
                            const float* __restrict__ bs0, const float* __restrict__ bd0,
                            const float* __restrict__ Ws1, const float* __restrict__ Wd1,
                            const float* __restrict__ bs1, const float* __restrict__ bd1,
                            const float* __restrict__ Ws2, const float* __restrict__ Wd2,
                            const float* __restrict__ bs2, const float* __restrict__ bd2)
{
    const float* Ws[3] = {Ws0, Ws1, Ws2};
    const float* Wd[3] = {Wd0, Wd1, Wd2};
    const float* bs[3] = {bs0, bs1, bs2};
    const float* bd[3] = {bd0, bd1, bd2};
    const int din_arr[3]  = {62, 100, 100};
    const int dout_arr[3] = {100, 100, 512};

    const int perL = 4 * 512 * WTSTR;
    const int total = 3 * perL;
    for (int idx = blockIdx.x * blockDim.x + threadIdx.x; idx < total; idx += gridDim.x * blockDim.x) {
        int li  = idx / perL;
        int rem = idx - li * perL;
        int d   = rem / (512 * WTSTR);
        int r2  = rem - d * (512 * WTSTR);
        int n   = r2 / WTSTR;
        int ks  = r2 - n * WTSTR;                 // storage position
        int k   = iperm16(ks);                    // logical k
        int din = din_arr[li], dout = dout_arr[li];
        int K = 2 * din + 6;
        float v = 0.f;
        if (n < dout && k < K) {
            if (k < din) v = Ws[li][(size_t)k * dout + n];
            else {
                int r = (k < 2 * din) ? (k - din) : (din + (k - 2 * din));
                v = Wd[li][((size_t)d * (din + 6) + r) * dout + n];
            }
        }
        g_Wt[idx] = __float2half_rn(v);
    }
    for (int idx = blockIdx.x * blockDim.x + threadIdx.x; idx < 3 * 2048; idx += gridDim.x * blockDim.x) {
        int li = idx / 2048;
        int r  = idx - li * 2048;
        int d  = r >> 9, j = r & 511;
        int dout = dout_arr[li];
        g_bc[idx] = (j < dout) ? (bs[li][j] + bd[li][d * dout + j]) : 0.f;
    }
}

// ---------------- fused gather + fp16 mma.sync(m16n8k16) GEMM + epilogue ----------------
// 1024 threads, 32 warps (8 M x 4 N), warp tile 16x32.
// Per k16-step: 6 LDS.64 + 4 MMA (half the instruction count of the tf32 k8 path).
// MODE 0: dout==100, fused bias + L2-normalize + relu -> (float*)outp (ld 100), 1 N-tile
// MODE 1: bias add -> g_Th (fp16, ld 512), 4 N-tiles; row sum-of-squares (fp32) -> g_inv
template<int KPAD, int DIN, int DEG, int MODE>
__global__ __launch_bounds__(1024)
void fused_gemm_kernel(const float* __restrict__ x,
                       const float* __restrict__ bond,
                       const int* __restrict__ an, const int* __restrict__ bn,
                       int degStart, int M,
                       const __half* __restrict__ Wt, const float* __restrict__ bias,
                       void* __restrict__ outp)
{
    constexpr int STRH = KPAD;               // halves per smem row; KPAD % 64 == 16 -> conflict-free LDS.64
    constexpr int K    = 2 * DIN + 6;
    constexpr int NIT  = (DIN + 31) / 32;
    constexpr int numNt = (MODE == 0) ? 1 : 4;
    constexpr int NKS  = KPAD / 16;          // k16-steps
    constexpr int CH   = KPAD / 8;           // 16B chunks per B row
    extern __shared__ char smemc[];
    __half* sAh  = (__half*)smemc;                      // [128][STRH]
    __half* sBh  = sAh + 128 * STRH;                    // [128][STRH]
    float*  sBias = (float*)(sBh + 128 * STRH);         // [512]
    float*  sSS   = sBias + 512;                        // [128]
    float*  sT    = sSS + 128;                          // [128][104] (MODE 0 only)
    const uint32_t sBu = smem_u32(sBh);

    const int tid  = threadIdx.x;
    const int wid  = tid >> 5;               // 0..31
    const int lane = tid & 31;
    const int grp  = lane >> 2;              // 0..7
    const int tig  = lane & 3;               // 0..3
    const int wm   = wid & 7;                // warp M index (8)  -> 16 rows each
    const int wn   = wid >> 3;               // warp N index (4)  -> 32 cols each
    const int row0 = blockIdx.x * 128;

    if (MODE == 1 && tid < 128) sSS[tid] = 0.f;

    // ---- issue B tile for nt=0 (async) BEFORE gather; load bias (overlap gather) ----
    {
        for (int i = tid; i < 128 * CH; i += 1024) {
            int rowb = i / CH;
            int c16  = i - rowb * CH;
            cp_async16(sBu + (uint32_t)(rowb * STRH + c16 * 8) * 2,
                       Wt + (size_t)rowb * WTSTR + c16 * 8);
        }
        asm volatile("cp.async.commit_group;");
        if (MODE == 1) { if (tid < 512) sBias[tid] = bias[tid]; }
        else           { if (tid < 128) sBias[tid] = bias[tid]; }
    }

    // ---- gather-fill A tile (fp16, perm16): branch-free, batched LDGs, warp handles 4 rows ----
    #pragma unroll
    for (int rr = 0; rr < 4; rr++) {
        const int r = wid * 4 + rr;
        const bool valid = (row0 + r) < M;
        const int mi = valid ? (row0 + r) : 0;

        int aidx[DEG], bidx[DEG];
        #pragma unroll
        for (int j = 0; j < DEG; j++) {
            aidx[j] = __ldg(an + (size_t)mi * DEG + j);
            bidx[j] = __ldg(bn + (size_t)mi * DEG + j);
        }

        const float* xs = x + (size_t)(degStart + mi) * DIN;
        float selfv[NIT], sumv[NIT];
        #pragma unroll
        for (int it = 0; it < NIT; it++) {
            const int c = lane + 32 * it;
            const int cc = (c < DIN) ? c : 0;
            selfv[it] = __ldg(xs + cc);
            float s = 0.f;
            #pragma unroll
            for (int j = 0; j < DEG; j++)
                s += __ldg(x + (size_t)aidx[j] * DIN + cc);
            sumv[it] = s;
        }
        float bsum = 0.f;
        {
            const int bl = (lane < 6) ? lane : 0;
            #pragma unroll
            for (int j = 0; j < DEG; j++)
                bsum += __ldg(bond + (size_t)bidx[j] * 6 + bl);
        }

        __half* Ar = sAh + (size_t)r * STRH;
        if (valid) {
            #pragma unroll
            for (int it = 0; it < NIT; it++) {
                const int c = lane + 32 * it;
                if (c < DIN) {
                    Ar[perm16(c)]       = __float2half_rn(selfv[it]);
                    Ar[perm16(DIN + c)] = __float2half_rn(sumv[it]);
                }
            }
            if (lane < 6) Ar[perm16(2 * DIN + lane)] = __float2half_rn(bsum);
        }
        #pragma unroll
        for (int c0 = K & ~31; c0 < KPAD; c0 += 32) {
            const int c = c0 + lane;
            if (c >= K && c < KPAD) Ar[perm16(c)] = __float2half_rn(0.f);
        }
    }

    asm volatile("cp.async.wait_group 0;" ::: "memory");
    __syncthreads();

    // fragment base pointers: uint2 = 4 halves = one fragment pair; k16-step stride = 4 uint2
    const uint2* paL = (const uint2*)(sAh + (size_t)(wm * 16 + grp) * STRH) + tig;
    const uint2* paH = (const uint2*)(sAh + (size_t)(wm * 16 + grp + 8) * STRH) + tig;
    const uint2* pb  = (const uint2*)(sBh + (size_t)(wn * 32 + grp) * STRH) + tig;
    constexpr int BNF = 8 * STRH / 4;        // uint2 stride between n-fragments (8 rows)

    for (int nt = 0; nt < numNt; nt++) {
        const int ncol0 = nt * 128;
        if (nt > 0) {
            __syncthreads();   // prior epilogue reads done before refill
            for (int i = tid; i < 128 * CH; i += 1024) {
                int rowb = i / CH;
                int c16  = i - rowb * CH;
                cp_async16(sBu + (uint32_t)(rowb * STRH + c16 * 8) * 2,
                           Wt + (size_t)(ncol0 + rowb) * WTSTR + c16 * 8);
            }
            cp_async_commit_wait();
            __syncthreads();
        }

        // ---- fp16 m16n8k16 mainloop, software-pipelined 1 k-step ahead ----
        float acc[4][4];
        #pragma unroll
        for (int nf = 0; nf < 4; nf++)
            #pragma unroll
            for (int q = 0; q < 4; q++) acc[nf][q] = 0.f;

        uint2 aL = paL[0], aH = paH[0];
        uint2 bv[4];
        #pragma unroll
        for (int nf = 0; nf < 4; nf++) bv[nf] = pb[nf * BNF];

        #pragma unroll
        for (int ks = 0; ks < NKS; ks++) {
            uint2 naL, naH, nbv[4];
            if (ks + 1 < NKS) {
                const int kk = 4 * (ks + 1);
                naL = paL[kk];
                naH = paH[kk];
                #pragma unroll
                for (int nf = 0; nf < 4; nf++) nbv[nf] = pb[nf * BNF + kk];
            }
            #pragma unroll
            for (int nf = 0; nf < 4; nf++)
                mma16(acc[nf][0], acc[nf][1], acc[nf][2], acc[nf][3],
                      aL.x, aH.x, aL.y, aH.y, bv[nf].x, bv[nf].y);
            if (ks + 1 < NKS) {
                aL = naL; aH = naH;
                #pragma unroll
                for (int nf = 0; nf < 4; nf++) bv[nf] = nbv[nf];
            }
        }

        if (MODE == 1) {
            // fp16 streaming store with bias + fp32 per-row sum-of-squares accumulation
            __half* outh = (__half*)outp;
            int r = wm * 16 + grp;
            float ss0 = 0.f, ss1 = 0.f;
            #pragma unroll
            for (int nf = 0; nf < 4; nf++) {
                int c = wn * 32 + nf * 8 + 2 * tig;
                float b0v = sBias[ncol0 + c], b1v = sBias[ncol0 + c + 1];
                float t0 = acc[nf][0] + b0v, t1 = acc[nf][1] + b1v;
                float t2 = acc[nf][2] + b0v, t3 = acc[nf][3] + b1v;
                ss0 += t0 * t0 + t1 * t1;
                ss1 += t2 * t2 + t3 * t3;
                if (row0 + r < M) {
                    __half2 h = __floats2half2_rn(t0, t1);
                    __stcs((unsigned int*)(outh + (size_t)(degStart + row0 + r) * 512 + ncol0 + c),
                           *(unsigned int*)&h);
                }
                if (row0 + r + 8 < M) {
                    __half2 h = __floats2half2_rn(t2, t3);
                    __stcs((unsigned int*)(outh + (size_t)(degStart + row0 + r + 8) * 512 + ncol0 + c),
                           *(unsigned int*)&h);
                }
            }
            if (row0 + r < M)     atomicAdd(&sSS[r], ss0);
            if (row0 + r + 8 < M) atomicAdd(&sSS[r + 8], ss1);
        } else {
            // stage t = acc + bias into sT (fp32), then row-norm
            float* outf = (float*)outp;
            __syncthreads();
            {
                int r = wm * 16 + grp;
                #pragma unroll
                for (int nf = 0; nf < 4; nf++) {
                    int c = wn * 32 + nf * 8 + 2 * tig;
                    if (c < 100) {
                        float b0v = sBias[c], b1v = sBias[c + 1];
                        sT[r * 104 + c]           = acc[nf][0] + b0v;
                        sT[r * 104 + c + 1]       = acc[nf][1] + b1v;
                        sT[(r + 8) * 104 + c]     = acc[nf][2] + b0v;
                        sT[(r + 8) * 104 + c + 1] = acc[nf][3] + b1v;
                    }
                }
            }
            __syncthreads();
            // warp wid handles rows wid*4 .. wid*4+3 (dout == 100)
            #pragma unroll
            for (int rr = 0; rr < 4; rr++) {
                int r = wid * 4 + rr;
                int m = row0 + r;
                if (m >= M) continue;
                const float* tr = sT + r * 104;
                float v0 = tr[lane];
                float v1 = tr[lane + 32];
                float v2 = tr[lane + 64];
                float v3 = (lane < 4) ? tr[lane + 96] : 0.f;
                float ss = v0 * v0 + v1 * v1 + v2 * v2 + v3 * v3;
                #pragma unroll
                for (int o = 16; o; o >>= 1) ss += __shfl_xor_sync(0xffffffffu, ss, o);
                float inv = 1.f / fmaxf(sqrtf(ss), 1e-12f);
                float* o = outf + (size_t)(degStart + m) * 100;
                o[lane]      = fmaxf(v0 * inv, 0.f);
                o[lane + 32] = fmaxf(v1 * inv, 0.f);
                o[lane + 64] = fmaxf(v2 * inv, 0.f);
                if (lane < 4) o[lane + 96] = fmaxf(v3 * inv, 0.f);
            }
        }
    }

    if (MODE == 1) {
        __syncthreads();
        if (tid < 128 && row0 + tid < M)
            g_inv[degStart + row0 + tid] = 1.f / fmaxf(sqrtf(sSS[tid]), 1e-12f);
    }
}

// ---------------- layer-2 relu(t * inv) + molecule segment-sum (fp16 stream) ----------------
__global__ void molsum_kernel(float* __restrict__ out)
{
    int m   = blockIdx.x;
    int tid = threadIdx.x;     // 256 threads, thread handles cols 2tid, 2tid+1
    float acc0 = 0.f, acc1 = 0.f;
    const __half* base = g_Th + (size_t)m * 20 * 512;
    #pragma unroll 4
    for (int a = 0; a < 20; a++) {
        unsigned int raw = __ldcs((const unsigned int*)(base + a * 512) + tid);
        __half2 h = *(__half2*)&raw;
        float2 f = __half22float2(h);
        float inv = g_inv[m * 20 + a];
        acc0 += fmaxf(f.x * inv, 0.f);
        acc1 += fmaxf(f.y * inv, 0.f);
    }
    out[(size_t)m * 512 + 2 * tid]     = acc0;
    out[(size_t)m * 512 + 2 * tid + 1] = acc1;
}

// ---------------- host ----------------
extern "C" void kernel_launch(void* const* d_in, const int* in_sizes, int n_in,
                              void* d_out, int out_size)
{
    const float* atom = (const float*)d_in[0];
    const float* bond = (const float*)d_in[1];
    const int*   an[4];
    const int*   bn[4];
    const float *Ws[3], *bsv[3], *Wd[3], *bdv[3];
    int n1, n2, n3, n4;

    bool dictOrder = (in_sizes[3] == in_sizes[2]);
    if (!dictOrder) {
        for (int i = 0; i < 4; i++) { an[i] = (const int*)d_in[2 + i]; bn[i] = (const int*)d_in[6 + i]; }
        n1 = in_sizes[2]; n2 = in_sizes[3] / 2; n3 = in_sizes[4] / 3; n4 = in_sizes[5] / 4;
        Ws[0] = (const float*)d_in[11]; bsv[0] = (const float*)d_in[12];
        Ws[1] = (const float*)d_in[13]; bsv[1] = (const float*)d_in[14];
        Ws[2] = (const float*)d_in[15]; bsv[2] = (const float*)d_in[16];
        Wd[0] = (const float*)d_in[17]; bdv[0] = (const float*)d_in[18];
        Wd[1] = (const float*)d_in[19]; bdv[1] = (const float*)d_in[20];
        Wd[2] = (const float*)d_in[21]; bdv[2] = (const float*)d_in[22];
    } else {
        for (int i = 0; i < 4; i++) { an[i] = (const int*)d_in[2 + 2 * i]; bn[i] = (const int*)d_in[3 + 2 * i]; }
        n1 = in_sizes[2]; n2 = in_sizes[4] / 2; n3 = in_sizes[6] / 3; n4 = in_sizes[8] / 4;
        Ws[0] = (const float*)d_in[11]; bsv[0] = (const float*)d_in[12];
        Wd[0] = (const float*)d_in[13]; bdv[0] = (const float*)d_in[14];
        Ws[1] = (const float*)d_in[15]; bsv[1] = (const float*)d_in[16];
        Wd[1] = (const float*)d_in[17]; bdv[1] = (const float*)d_in[18];
        Ws[2] = (const float*)d_in[19]; bsv[2] = (const float*)d_in[20];
        Wd[2] = (const float*)d_in[21]; bdv[2] = (const float*)d_in[22];
    }

    float *pX0, *pX1, *pbc;
    __half *pTh, *pWt;
    cudaGetSymbolAddress((void**)&pTh, g_Th);
    cudaGetSymbolAddress((void**)&pX0, g_X0);
    cudaGetSymbolAddress((void**)&pX1, g_X1);
    cudaGetSymbolAddress((void**)&pWt, g_Wt);
    cudaGetSymbolAddress((void**)&pbc, g_bc);

    const int nd[4] = {n1, n2, n3, n4};
    const int degStart[4] = {0, n1, n1 + n2, n1 + n2 + n3};

    prep_kernel<<<1664, 384>>>(Ws[0], Wd[0], bsv[0], bdv[0],
                               Ws[1], Wd[1], bsv[1], bdv[1],
                               Ws[2], Wd[2], bsv[2], bdv[2]);

    // smem sizes: 2*128*KPAD*2 (A+B fp16) + 512*4 (bias) + 128*4 (ss) [+ 128*104*4 sT for MODE0]
    const int smem0  = 2 * 128 * 144 * 2 + 2048 + 512 + 128 * 104 * 4;  // 129,536
    const int smem1  = 2 * 128 * 208 * 2 + 2048 + 512 + 128 * 104 * 4;  // 162,304
    const int smem2  = 2 * 128 * 208 * 2 + 2048 + 512;                  // 109,056

    #define SETSM(KP, DN, DG, MD, SZ) \
        cudaFuncSetAttribute((const void*)fused_gemm_kernel<KP, DN, DG, MD>, \
                             cudaFuncAttributeMaxDynamicSharedMemorySize, SZ)
    SETSM(144, 62, 1, 0, smem0);  SETSM(144, 62, 2, 0, smem0);
    SETSM(144, 62, 3, 0, smem0);  SETSM(144, 62, 4, 0, smem0);
    SETSM(208, 100, 1, 0, smem1); SETSM(208, 100, 2, 0, smem1);
    SETSM(208, 100, 3, 0, smem1); SETSM(208, 100, 4, 0, smem1);
    SETSM(208, 100, 1, 1, smem2); SETSM(208, 100, 2, 1, smem2);
    SETSM(208, 100, 3, 1, smem2); SETSM(208, 100, 4, 1, smem2);

    const float* xin = atom;
    float* xbuf[2] = {pX0, pX1};

    for (int li = 0; li < 3; li++) {
        void* outp = (li < 2) ? (void*)xbuf[li] : (void*)pTh;
        for (int d = 0; d < 4; d++) {
            if (nd[d] <= 0) continue;
            int grid = (nd[d] + 127) / 128;
            const __half* WtD = pWt + (size_t)li * (4 * 512 * WTSTR) + (size_t)d * (512 * WTSTR);
            const float* bD   = pbc + li * 2048 + d * 512;
            #define LGK(KP, DN, MD, SM) do { \
                switch (d) { \
                case 0: fused_gemm_kernel<KP, DN, 1, MD><<<grid, 1024, SM>>>(xin, bond, an[0], bn[0], degStart[0], nd[0], WtD, bD, outp); break; \
                case 1: fused_gemm_kernel<KP, DN, 2, MD><<<grid, 1024, SM>>>(xin, bond, an[1], bn[1], degStart[1], nd[1], WtD, bD, outp); break; \
                case 2: fused_gemm_kernel<KP, DN, 3, MD><<<grid, 1024, SM>>>(xin, bond, an[2], bn[2], degStart[2], nd[2], WtD, bD, outp); break; \
                case 3: fused_gemm_kernel<KP, DN, 4, MD><<<grid, 1024, SM>>>(xin, bond, an[3], bn[3], degStart[3], nd[3], WtD, bD, outp); break; \
                } } while (0)
            if (li == 0)      LGK(144, 62, 0, smem0);
            else if (li == 1) LGK(208, 100, 0, smem1);
            else              LGK(208, 100, 1, smem2);
        }
        if (li < 2) xin = xbuf[li];
    }

    int nmol = out_size / 512;
    molsum_kernel<<<nmol, 256>>>((float*)d_out);
}

// round 14
// speedup vs baseline: 3.8757x; 1.0558x over previous
#include <cuda_runtime.h>
#include <cuda_fp16.h>
#include <cstdint>
#include <math.h>

#define NATOMS 500000
#define NBONDS 600000
#define WTSTR 208    // per-row stride (halves) of transposed weights, all layers

// ---------------- scratch (static device globals) ----------------
__device__ __half g_Th[(size_t)NATOMS * 512];      // 0.5 GB  pre-norm layer-2 output (fp16 staging)
__device__ __half g_Xin[(size_t)NATOMS * 62];      // fp16 copy of atom_features
__device__ __half g_Bd[(size_t)NBONDS * 6];        // fp16 copy of bond_features
__device__ __half g_X0[(size_t)NATOMS * 100];      // post-norm x (layer0 out, fp16)
__device__ __half g_X1[(size_t)NATOMS * 100];      // post-norm x (layer1 out, fp16)
__device__ float g_inv[NATOMS];                    // layer-2 per-atom 1/||t|| (from fp32 accs)
__device__ __half g_Wt[3 * 4 * 512 * WTSTR];       // transposed concat weights, fp16, K16-permuted
__device__ float g_bc[3 * 4 * 512];                // combined bias (fp32), zero padded

// ---------------- helpers ----------------
// K-permutation within each 16-block: logical k -> storage position.
// Groups: [k0,k1,k8,k9][k2,k3,k10,k11][k4,k5,k12,k13][k6,k7,k14,k15]
__device__ __forceinline__ int perm16(int k) {
    int j = k & 15;
    return (k & ~15) + ((j & 7) >> 1) * 4 + (j >> 3) * 2 + (j & 1);
}
__device__ __forceinline__ int iperm16(int ks) {
    int j = ks & 15;
    return (ks & ~15) + ((j >> 1) & 1) * 8 + (j >> 2) * 2 + (j & 1);
}

__device__ __forceinline__ uint32_t smem_u32(const void* p) {
    uint32_t a;
    asm("{ .reg .u64 t; cvta.to.shared.u64 t, %1; cvt.u32.u64 %0, t; }" : "=r"(a) : "l"(p));
    return a;
}

__device__ __forceinline__ void cp_async16(uint32_t saddr, const void* gptr) {
    asm volatile("cp.async.cg.shared.global [%0], [%1], 16;" :: "r"(saddr), "l"(gptr));
}
__device__ __forceinline__ void cp_async_commit_wait() {
    asm volatile("cp.async.commit_group;");
    asm volatile("cp.async.wait_group 0;" ::: "memory");
}

__device__ __forceinline__ void mma16(float& c0, float& c1, float& c2, float& c3,
                                      uint32_t a0, uint32_t a1, uint32_t a2, uint32_t a3,
                                      uint32_t b0, uint32_t b1) {
    asm volatile("mma.sync.aligned.m16n8k16.row.col.f32.f16.f16.f32 "
                 "{%0,%1,%2,%3}, {%4,%5,%6,%7}, {%8,%9}, {%0,%1,%2,%3};"
                 : "+f"(c0), "+f"(c1), "+f"(c2), "+f"(c3)
                 : "r"(a0), "r"(a1), "r"(a2), "r"(a3), "r"(b0), "r"(b1));
}

// ---------------- single-launch prep: weights/bias (fp16+perm16) + fp16 input copies ----------------
__global__ void prep_kernel(const float* __restrict__ atomf, int nAtomF,
                            const float* __restrict__ bondf, int nBondF,
                            const float* __restrict__ Ws0, const float* __restrict__ Wd0,
                            const float* __restrict__ bs0, const float* __restrict__ bd0,
                            const float* __restrict__ Ws1, const float* __restrict__ Wd1,
                            const float* __restrict__ bs1, const float* __restrict__ bd1,
                            const float* __restrict__ Ws2, const float* __restrict__ Wd2,
                            const float* __restrict__ bs2, const float* __restrict__ bd2)
{
    const float* Ws[3] = {Ws0, Ws1, Ws2};
    const float* Wd[3] = {Wd0, Wd1, Wd2};
    const float* bs[3] = {bs0, bs1, bs2};
    const float* bd[3] = {bd0, bd1, bd2};
    const int din_arr[3]  = {62, 100, 100};
    const int dout_arr[3] = {100, 100, 512};

    const int stride = gridDim.x * blockDim.x;
    const int tid0 = blockIdx.x * blockDim.x + threadIdx.x;

    // fp16 copies of inputs
    for (int i = tid0; i < nAtomF; i += stride) g_Xin[i] = __float2half_rn(atomf[i]);
    for (int i = tid0; i < nBondF; i += stride) g_Bd[i]  = __float2half_rn(bondf[i]);

    const int perL = 4 * 512 * WTSTR;
    const int total = 3 * perL;
    for (int idx = tid0; idx < total; idx += stride) {
        int li  = idx / perL;
        int rem = idx - li * perL;
        int d   = rem / (512 * WTSTR);
        int r2  = rem - d * (512 * WTSTR);
        int n   = r2 / WTSTR;
        int ks  = r2 - n * WTSTR;                 // storage position
        int k   = iperm16(ks);                    // logical k
        int din = din_arr[li], dout = dout_arr[li];
        int K = 2 * din + 6;
        float v = 0.f;
        if (n < dout && k < K) {
            if (k < din) v = Ws[li][(size_t)k * dout + n];
            else {
                int r = (k < 2 * din) ? (k - din) : (din + (k - 2 * din));
                v = Wd[li][((size_t)d * (din + 6) + r) * dout + n];
            }
        }
        g_Wt[idx] = __float2half_rn(v);
    }
    for (int idx = tid0; idx < 3 * 2048; idx += stride) {
        int li = idx / 2048;
        int r  = idx - li * 2048;
        int d  = r >> 9, j = r & 511;
        int dout = dout_arr[li];
        g_bc[idx] = (j < dout) ? (bs[li][j] + bd[li][d * dout + j]) : 0.f;
    }
}

// ---------------- fused gather + fp16 mma.sync(m16n8k16) GEMM + epilogue ----------------
// 1024 threads, 32 warps (8 M x 4 N), warp tile 16x32. fp16 activations end-to-end.
// MODE 0: dout==100, fused bias + L2-normalize + relu -> (__half*)outp (ld 100), 1 N-tile
// MODE 1: bias add -> g_Th (fp16, ld 512), 4 N-tiles; row sum-of-squares (fp32) -> g_inv
template<int KPAD, int DIN, int DEG, int MODE>
__global__ __launch_bounds__(1024)
void fused_gemm_kernel(const __half* __restrict__ x,
                       const __half* __restrict__ bond,
                       const int* __restrict__ an, const int* __restrict__ bn,
                       int degStart, int M,
                       const __half* __restrict__ Wt, const float* __restrict__ bias,
                       void* __restrict__ outp)
{
    constexpr int STRH = KPAD;               // halves per smem row; KPAD % 64 == 16 -> conflict-free LDS.64
    constexpr int K    = 2 * DIN + 6;
    constexpr int NIT  = (DIN + 31) / 32;
    constexpr int numNt = (MODE == 0) ? 1 : 4;
    constexpr int NKS  = KPAD / 16;          // k16-steps
    constexpr int CH   = KPAD / 8;           // 16B chunks per B row
    extern __shared__ char smemc[];
    __half* sAh  = (__half*)smemc;                      // [128][STRH]
    __half* sBh  = sAh + 128 * STRH;                    // [128][STRH]
    float*  sBias = (float*)(sBh + 128 * STRH);         // [512]
    float*  sSS   = sBias + 512;                        // [128]
    float*  sT    = sSS + 128;                          // [128][104] (MODE 0 only)
    const uint32_t sBu = smem_u32(sBh);

    const int tid  = threadIdx.x;
    const int wid  = tid >> 5;               // 0..31
    const int lane = tid & 31;
    const int grp  = lane >> 2;              // 0..7
    const int tig  = lane & 3;               // 0..3
    const int wm   = wid & 7;                // warp M index (8)  -> 16 rows each
    const int wn   = wid >> 3;               // warp N index (4)  -> 32 cols each
    const int row0 = blockIdx.x * 128;

    if (MODE == 1 && tid < 128) sSS[tid] = 0.f;

    // ---- issue B tile for nt=0 (async) BEFORE gather; load bias (overlap gather) ----
    {
        for (int i = tid; i < 128 * CH; i += 1024) {
            int rowb = i / CH;
            int c16  = i - rowb * CH;
            cp_async16(sBu + (uint32_t)(rowb * STRH + c16 * 8) * 2,
                       Wt + (size_t)rowb * WTSTR + c16 * 8);
        }
        asm volatile("cp.async.commit_group;");
        if (MODE == 1) { if (tid < 512) sBias[tid] = bias[tid]; }
        else           { if (tid < 128) sBias[tid] = bias[tid]; }
    }

    // ---- gather-fill A tile (fp16 in, fp32 sums, fp16 out): warp handles 4 rows ----
    #pragma unroll
    for (int rr = 0; rr < 4; rr++) {
        const int r = wid * 4 + rr;
        const bool valid = (row0 + r) < M;
        const int mi = valid ? (row0 + r) : 0;

        int aidx[DEG], bidx[DEG];
        #pragma unroll
        for (int j = 0; j < DEG; j++) {
            aidx[j] = __ldg(an + (size_t)mi * DEG + j);
            bidx[j] = __ldg(bn + (size_t)mi * DEG + j);
        }

        const __half* xs = x + (size_t)(degStart + mi) * DIN;
        __half selfv[NIT];
        float sumv[NIT];
        #pragma unroll
        for (int it = 0; it < NIT; it++) {
            const int c = lane + 32 * it;
            const int cc = (c < DIN) ? c : 0;
            selfv[it] = __ldg(xs + cc);
            float s = 0.f;
            #pragma unroll
            for (int j = 0; j < DEG; j++)
                s += __half2float(__ldg(x + (size_t)aidx[j] * DIN + cc));
            sumv[it] = s;
        }
        float bsum = 0.f;
        {
            const int bl = (lane < 6) ? lane : 0;
            #pragma unroll
            for (int j = 0; j < DEG; j++)
                bsum += __half2float(__ldg(bond + (size_t)bidx[j] * 6 + bl));
        }

        __half* Ar = sAh + (size_t)r * STRH;
        if (valid) {
            #pragma unroll
            for (int it = 0; it < NIT; it++) {
                const int c = lane + 32 * it;
                if (c < DIN) {
                    Ar[perm16(c)]       = selfv[it];
                    Ar[perm16(DIN + c)] = __float2half_rn(sumv[it]);
                }
            }
            if (lane < 6) Ar[perm16(2 * DIN + lane)] = __float2half_rn(bsum);
        }
        #pragma unroll
        for (int c0 = K & ~31; c0 < KPAD; c0 += 32) {
            const int c = c0 + lane;
            if (c >= K && c < KPAD) Ar[perm16(c)] = __float2half_rn(0.f);
        }
    }

    asm volatile("cp.async.wait_group 0;" ::: "memory");
    __syncthreads();

    // fragment base pointers: uint2 = 4 halves = one fragment pair; k16-step stride = 4 uint2
    const uint2* paL = (const uint2*)(sAh + (size_t)(wm * 16 + grp) * STRH) + tig;
    const uint2* paH = (const uint2*)(sAh + (size_t)(wm * 16 + grp + 8) * STRH) + tig;
    const uint2* pb  = (const uint2*)(sBh + (size_t)(wn * 32 + grp) * STRH) + tig;
    constexpr int BNF = 8 * STRH / 4;        // uint2 stride between n-fragments (8 rows)

    for (int nt = 0; nt < numNt; nt++) {
        const int ncol0 = nt * 128;
        if (nt > 0) {
            __syncthreads();   // prior epilogue reads done before refill
            for (int i = tid; i < 128 * CH; i += 1024) {
                int rowb = i / CH;
                int c16  = i - rowb * CH;
                cp_async16(sBu + (uint32_t)(rowb * STRH + c16 * 8) * 2,
                           Wt + (size_t)(ncol0 + rowb) * WTSTR + c16 * 8);
            }
            cp_async_commit_wait();
            __syncthreads();
        }

        // ---- fp16 m16n8k16 mainloop, software-pipelined 1 k-step ahead ----
        float acc[4][4];
        #pragma unroll
        for (int nf = 0; nf < 4; nf++)
            #pragma unroll
            for (int q = 0; q < 4; q++) acc[nf][q] = 0.f;

        uint2 aL = paL[0], aH = paH[0];
        uint2 bv[4];
        #pragma unroll
        for (int nf = 0; nf < 4; nf++) bv[nf] = pb[nf * BNF];

        #pragma unroll
        for (int ks = 0; ks < NKS; ks++) {
            uint2 naL, naH, nbv[4];
            if (ks + 1 < NKS) {
                const int kk = 4 * (ks + 1);
                naL = paL[kk];
                naH = paH[kk];
                #pragma unroll
                for (int nf = 0; nf < 4; nf++) nbv[nf] = pb[nf * BNF + kk];
            }
            #pragma unroll
            for (int nf = 0; nf < 4; nf++)
                mma16(acc[nf][0], acc[nf][1], acc[nf][2], acc[nf][3],
                      aL.x, aH.x, aL.y, aH.y, bv[nf].x, bv[nf].y);
            if (ks + 1 < NKS) {
                aL = naL; aH = naH;
                #pragma unroll
                for (int nf = 0; nf < 4; nf++) bv[nf] = nbv[nf];
            }
        }

        if (MODE == 1) {
            // fp16 streaming store with bias + fp32 per-row sum-of-squares accumulation
            __half* outh = (__half*)outp;
            int r = wm * 16 + grp;
            float ss0 = 0.f, ss1 = 0.f;
            #pragma unroll
            for (int nf = 0; nf < 4; nf++) {
                int c = wn * 32 + nf * 8 + 2 * tig;
                float b0v = sBias[ncol0 + c], b1v = sBias[ncol0 + c + 1];
                float t0 = acc[nf][0] + b0v, t1 = acc[nf][1] + b1v;
                float t2 = acc[nf][2] + b0v, t3 = acc[nf][3] + b1v;
                ss0 += t0 * t0 + t1 * t1;
                ss1 += t2 * t2 + t3 * t3;
                if (row0 + r < M) {
                    __half2 h = __floats2half2_rn(t0, t1);
                    __stcs((unsigned int*)(outh + (size_t)(degStart + row0 + r) * 512 + ncol0 + c),
                           *(unsigned int*)&h);
                }
                if (row0 + r + 8 < M) {
                    __half2 h = __floats2half2_rn(t2, t3);
                    __stcs((unsigned int*)(outh + (size_t)(degStart + row0 + r + 8) * 512 + ncol0 + c),
                           *(unsigned int*)&h);
                }
            }
            if (row0 + r < M)     atomicAdd(&sSS[r], ss0);
            if (row0 + r + 8 < M) atomicAdd(&sSS[r + 8], ss1);
        } else {
            // stage t = acc + bias into sT (fp32), then row-norm -> fp16 x out
            __half* outh = (__half*)outp;
            __syncthreads();
            {
                int r = wm * 16 + grp;
                #pragma unroll
                for (int nf = 0; nf < 4; nf++) {
                    int c = wn * 32 + nf * 8 + 2 * tig;
                    if (c < 100) {
                        float b0v = sBias[c], b1v = sBias[c + 1];
                        sT[r * 104 + c]           = acc[nf][0] + b0v;
                        sT[r * 104 + c + 1]       = acc[nf][1] + b1v;
                        sT[(r + 8) * 104 + c]     = acc[nf][2] + b0v;
                        sT[(r + 8) * 104 + c + 1] = acc[nf][3] + b1v;
                    }
                }
            }
            __syncthreads();
            // warp wid handles rows wid*4 .. wid*4+3 (dout == 100)
            #pragma unroll
            for (int rr = 0; rr < 4; rr++) {
                int r = wid * 4 + rr;
                int m = row0 + r;
                if (m >= M) continue;
                const float* tr = sT + r * 104;
                float v0 = tr[lane];
                float v1 = tr[lane + 32];
                float v2 = tr[lane + 64];
                float v3 = (lane < 4) ? tr[lane + 96] : 0.f;
                float ss = v0 * v0 + v1 * v1 + v2 * v2 + v3 * v3;
                #pragma unroll
                for (int o = 16; o; o >>= 1) ss += __shfl_xor_sync(0xffffffffu, ss, o);
                float inv = 1.f / fmaxf(sqrtf(ss), 1e-12f);
                __half* o = outh + (size_t)(degStart + m) * 100;
                o[lane]      = __float2half_rn(fmaxf(v0 * inv, 0.f));
                o[lane + 32] = __float2half_rn(fmaxf(v1 * inv, 0.f));
                o[lane + 64] = __float2half_rn(fmaxf(v2 * inv, 0.f));
                if (lane < 4) o[lane + 96] = __float2half_rn(fmaxf(v3 * inv, 0.f));
            }
        }
    }

    if (MODE == 1) {
        __syncthreads();
        if (tid < 128 && row0 + tid < M)
            g_inv[degStart + row0 + tid] = 1.f / fmaxf(sqrtf(sSS[tid]), 1e-12f);
    }
}

// ---------------- layer-2 relu(t * inv) + molecule segment-sum (fp16 stream) ----------------
__global__ void molsum_kernel(float* __restrict__ out)
{
    int m   = blockIdx.x;
    int tid = threadIdx.x;     // 256 threads, thread handles cols 2tid, 2tid+1
    float acc0 = 0.f, acc1 = 0.f;
    const __half* base = g_Th + (size_t)m * 20 * 512;
    #pragma unroll 4
    for (int a = 0; a < 20; a++) {
        unsigned int raw = __ldcs((const unsigned int*)(base + a * 512) + tid);
        __half2 h = *(__half2*)&raw;
        float2 f = __half22float2(h);
        float inv = g_inv[m * 20 + a];
        acc0 += fmaxf(f.x * inv, 0.f);
        acc1 += fmaxf(f.y * inv, 0.f);
    }
    out[(size_t)m * 512 + 2 * tid]     = acc0;
    out[(size_t)m * 512 + 2 * tid + 1] = acc1;
}

// ---------------- host ----------------
extern "C" void kernel_launch(void* const* d_in, const int* in_sizes, int n_in,
                              void* d_out, int out_size)
{
    const float* atom = (const float*)d_in[0];
    const float* bond = (const float*)d_in[1];
    const int*   an[4];
    const int*   bn[4];
    const float *Ws[3], *bsv[3], *Wd[3], *bdv[3];
    int n1, n2, n3, n4;

    bool dictOrder = (in_sizes[3] == in_sizes[2]);
    if (!dictOrder) {
        for (int i = 0; i < 4; i++) { an[i] = (const int*)d_in[2 + i]; bn[i] = (const int*)d_in[6 + i]; }
        n1 = in_sizes[2]; n2 = in_sizes[3] / 2; n3 = in_sizes[4] / 3; n4 = in_sizes[5] / 4;
        Ws[0] = (const float*)d_in[11]; bsv[0] = (const float*)d_in[12];
        Ws[1] = (const float*)d_in[13]; bsv[1] = (const float*)d_in[14];
        Ws[2] = (const float*)d_in[15]; bsv[2] = (const float*)d_in[16];
        Wd[0] = (const float*)d_in[17]; bdv[0] = (const float*)d_in[18];
        Wd[1] = (const float*)d_in[19]; bdv[1] = (const float*)d_in[20];
        Wd[2] = (const float*)d_in[21]; bdv[2] = (const float*)d_in[22];
    } else {
        for (int i = 0; i < 4; i++) { an[i] = (const int*)d_in[2 + 2 * i]; bn[i] = (const int*)d_in[3 + 2 * i]; }
        n1 = in_sizes[2]; n2 = in_sizes[4] / 2; n3 = in_sizes[6] / 3; n4 = in_sizes[8] / 4;
        Ws[0] = (const float*)d_in[11]; bsv[0] = (const float*)d_in[12];
        Wd[0] = (const float*)d_in[13]; bdv[0] = (const float*)d_in[14];
        Ws[1] = (const float*)d_in[15]; bsv[1] = (const float*)d_in[16];
        Wd[1] = (const float*)d_in[17]; bdv[1] = (const float*)d_in[18];
        Ws[2] = (const float*)d_in[19]; bsv[2] = (const float*)d_in[20];
        Wd[2] = (const float*)d_in[21]; bdv[2] = (const float*)d_in[22];
    }

    float *pbc, *pinv;
    __half *pTh, *pWt, *pXin, *pBd, *pX0, *pX1;
    cudaGetSymbolAddress((void**)&pTh,  g_Th);
    cudaGetSymbolAddress((void**)&pXin, g_Xin);
    cudaGetSymbolAddress((void**)&pBd,  g_Bd);
    cudaGetSymbolAddress((void**)&pX0,  g_X0);
    cudaGetSymbolAddress((void**)&pX1,  g_X1);
    cudaGetSymbolAddress((void**)&pWt,  g_Wt);
    cudaGetSymbolAddress((void**)&pbc,  g_bc);
    cudaGetSymbolAddress((void**)&pinv, g_inv);
    (void)pinv;

    const int nd[4] = {n1, n2, n3, n4};
    const int degStart[4] = {0, n1, n1 + n2, n1 + n2 + n3};

    prep_kernel<<<1664, 384>>>(atom, in_sizes[0], bond, in_sizes[1],
                               Ws[0], Wd[0], bsv[0], bdv[0],
                               Ws[1], Wd[1], bsv[1], bdv[1],
                               Ws[2], Wd[2], bsv[2], bdv[2]);

    // smem sizes: 2*128*KPAD*2 (A+B fp16) + 512*4 (bias) + 128*4 (ss) [+ 128*104*4 sT for MODE0]
    const int smem0  = 2 * 128 * 144 * 2 + 2048 + 512 + 128 * 104 * 4;  // 129,536
    const int smem1  = 2 * 128 * 208 * 2 + 2048 + 512 + 128 * 104 * 4;  // 162,304
    const int smem2  = 2 * 128 * 208 * 2 + 2048 + 512;                  // 109,056

    #define SETSM(KP, DN, DG, MD, SZ) \
        cudaFuncSetAttribute((const void*)fused_gemm_kernel<KP, DN, DG, MD>, \
                             cudaFuncAttributeMaxDynamicSharedMemorySize, SZ)
    SETSM(144, 62, 1, 0, smem0);  SETSM(144, 62, 2, 0, smem0);
    SETSM(144, 62, 3, 0, smem0);  SETSM(144, 62, 4, 0, smem0);
    SETSM(208, 100, 1, 0, smem1); SETSM(208, 100, 2, 0, smem1);
    SETSM(208, 100, 3, 0, smem1); SETSM(208, 100, 4, 0, smem1);
    SETSM(208, 100, 1, 1, smem2); SETSM(208, 100, 2, 1, smem2);
    SETSM(208, 100, 3, 1, smem2); SETSM(208, 100, 4, 1, smem2);

    const __half* xin = pXin;
    __half* xbuf[2] = {pX0, pX1};

    for (int li = 0; li < 3; li++) {
        void* outp = (li < 2) ? (void*)xbuf[li] : (void*)pTh;
        for (int d = 0; d < 4; d++) {
            if (nd[d] <= 0) continue;
            int grid = (nd[d] + 127) / 128;
            const __half* WtD = pWt + (size_t)li * (4 * 512 * WTSTR) + (size_t)d * (512 * WTSTR);
            const float* bD   = pbc + li * 2048 + d * 512;
            #define LGK(KP, DN, MD, SM) do { \
                switch (d) { \
                case 0: fused_gemm_kernel<KP, DN, 1, MD><<<grid, 1024, SM>>>(xin, pBd, an[0], bn[0], degStart[0], nd[0], WtD, bD, outp); break; \
                case 1: fused_gemm_kernel<KP, DN, 2, MD><<<grid, 1024, SM>>>(xin, pBd, an[1], bn[1], degStart[1], nd[1], WtD, bD, outp); break; \
                case 2: fused_gemm_kernel<KP, DN, 3, MD><<<grid, 1024, SM>>>(xin, pBd, an[2], bn[2], degStart[2], nd[2], WtD, bD, outp); break; \
                case 3: fused_gemm_kernel<KP, DN, 4, MD><<<grid, 1024, SM>>>(xin, pBd, an[3], bn[3], degStart[3], nd[3], WtD, bD, outp); break; \
                } } while (0)
            if (li == 0)      LGK(144, 62, 0, smem0);
            else if (li == 1) LGK(208, 100, 0, smem1);
            else              LGK(208, 100, 1, smem2);
        }
        if (li < 2) xin = xbuf[li];
    }

    int nmol = out_size / 512;
    molsum_kernel<<<nmol, 256>>>((float*)d_out);
}

// round 15
// speedup vs baseline: 3.9260x; 1.0130x over previous
#include <cuda_runtime.h>
#include <cuda_fp16.h>
#include <cstdint>
#include <math.h>

#define NATOMS 500000
#define NBONDS 600000
#define WTSTR 208    // per-row stride (halves) of transposed weights, all layers

// ---------------- scratch (static device globals) ----------------
__device__ __half g_Th[(size_t)NATOMS * 512];      // 0.5 GB  pre-norm layer-2 output (fp16, L2-resident reuse)
__device__ __half g_Xin[(size_t)NATOMS * 62];      // fp16 copy of atom_features
__device__ __half g_Bd[(size_t)NBONDS * 6];        // fp16 copy of bond_features
__device__ __half g_X0[(size_t)NATOMS * 100];      // post-norm x (layer0 out, fp16)
__device__ __half g_X1[(size_t)NATOMS * 100];      // post-norm x (layer1 out, fp16)
__device__ __half g_Wt[3 * 4 * 512 * WTSTR];       // transposed concat weights, fp16, K16-permuted
__device__ float g_bc[3 * 4 * 512];                // combined bias (fp32), zero padded

// ---------------- helpers ----------------
__device__ __forceinline__ int perm16(int k) {
    int j = k & 15;
    return (k & ~15) + ((j & 7) >> 1) * 4 + (j >> 3) * 2 + (j & 1);
}
__device__ __forceinline__ int iperm16(int ks) {
    int j = ks & 15;
    return (ks & ~15) + ((j >> 1) & 1) * 8 + (j >> 2) * 2 + (j & 1);
}

__device__ __forceinline__ uint32_t smem_u32(const void* p) {
    uint32_t a;
    asm("{ .reg .u64 t; cvta.to.shared.u64 t, %1; cvt.u32.u64 %0, t; }" : "=r"(a) : "l"(p));
    return a;
}

__device__ __forceinline__ void cp_async16(uint32_t saddr, const void* gptr) {
    asm volatile("cp.async.cg.shared.global [%0], [%1], 16;" :: "r"(saddr), "l"(gptr));
}
__device__ __forceinline__ void cp_async_commit_wait() {
    asm volatile("cp.async.commit_group;");
    asm volatile("cp.async.wait_group 0;" ::: "memory");
}

__device__ __forceinline__ void mma16(float& c0, float& c1, float& c2, float& c3,
                                      uint32_t a0, uint32_t a1, uint32_t a2, uint32_t a3,
                                      uint32_t b0, uint32_t b1) {
    asm volatile("mma.sync.aligned.m16n8k16.row.col.f32.f16.f16.f32 "
                 "{%0,%1,%2,%3}, {%4,%5,%6,%7}, {%8,%9}, {%0,%1,%2,%3};"
                 : "+f"(c0), "+f"(c1), "+f"(c2), "+f"(c3)
                 : "r"(a0), "r"(a1), "r"(a2), "r"(a3), "r"(b0), "r"(b1));
}

// ---------------- single-launch prep: weights/bias + fp16 copies + d_out zeroing ----------------
__global__ void prep_kernel(const float* __restrict__ atomf, int nAtomF,
                            const float* __restrict__ bondf, int nBondF,
                            float* __restrict__ outZ, int nOut,
                            const float* __restrict__ Ws0, const float* __restrict__ Wd0,
                            const float* __restrict__ bs0, const float* __restrict__ bd0,
                            const float* __restrict__ Ws1, const float* __restrict__ Wd1,
                            const float* __restrict__ bs1, const float* __restrict__ bd1,
                            const float* __restrict__ Ws2, const float* __restrict__ Wd2,
                            const float* __restrict__ bs2, const float* __restrict__ bd2)
{
    const float* Ws[3] = {Ws0, Ws1, Ws2};
    const float* Wd[3] = {Wd0, Wd1, Wd2};
    const float* bs[3] = {bs0, bs1, bs2};
    const float* bd[3] = {bd0, bd1, bd2};
    const int din_arr[3]  = {62, 100, 100};
    const int dout_arr[3] = {100, 100, 512};

    const int stride = gridDim.x * blockDim.x;
    const int tid0 = blockIdx.x * blockDim.x + threadIdx.x;

    for (int i = tid0; i < nAtomF; i += stride) g_Xin[i] = __float2half_rn(atomf[i]);
    for (int i = tid0; i < nBondF; i += stride) g_Bd[i]  = __float2half_rn(bondf[i]);
    for (int i = tid0; i < nOut;   i += stride) outZ[i] = 0.f;

    const int perL = 4 * 512 * WTSTR;
    const int total = 3 * perL;
    for (int idx = tid0; idx < total; idx += stride) {
        int li  = idx / perL;
        int rem = idx - li * perL;
        int d   = rem / (512 * WTSTR);
        int r2  = rem - d * (512 * WTSTR);
        int n   = r2 / WTSTR;
        int ks  = r2 - n * WTSTR;
        int k   = iperm16(ks);
        int din = din_arr[li], dout = dout_arr[li];
        int K = 2 * din + 6;
        float v = 0.f;
        if (n < dout && k < K) {
            if (k < din) v = Ws[li][(size_t)k * dout + n];
            else {
                int r = (k < 2 * din) ? (k - din) : (din + (k - 2 * din));
                v = Wd[li][((size_t)d * (din + 6) + r) * dout + n];
            }
        }
        g_Wt[idx] = __float2half_rn(v);
    }
    for (int idx = tid0; idx < 3 * 2048; idx += stride) {
        int li = idx / 2048;
        int r  = idx - li * 2048;
        int d  = r >> 9, j = r & 511;
        int dout = dout_arr[li];
        g_bc[idx] = (j < dout) ? (bs[li][j] + bd[li][d * dout + j]) : 0.f;
    }
}

// ---------------- templated gather helper (fully unrolled per degree) ----------------
template<int KPAD, int DIN, int DEG>
__device__ __forceinline__ void gather_fill(__half* sAh,
                                            const __half* __restrict__ x,
                                            const __half* __restrict__ bond,
                                            const int* __restrict__ an,
                                            const int* __restrict__ bn,
                                            int degStart, int M, int row0,
                                            int wid, int lane)
{
    constexpr int K = 2 * DIN + 6;
    constexpr int NIT = (DIN + 31) / 32;
    #pragma unroll
    for (int rr = 0; rr < 4; rr++) {
        const int r = wid * 4 + rr;
        const bool valid = (row0 + r) < M;
        const int mi = valid ? (row0 + r) : 0;

        int aidx[DEG], bidx[DEG];
        #pragma unroll
        for (int j = 0; j < DEG; j++) {
            aidx[j] = __ldg(an + (size_t)mi * DEG + j);
            bidx[j] = __ldg(bn + (size_t)mi * DEG + j);
        }

        const __half* xs = x + (size_t)(degStart + mi) * DIN;
        __half selfv[NIT];
        float sumv[NIT];
        #pragma unroll
        for (int it = 0; it < NIT; it++) {
            const int c = lane + 32 * it;
            const int cc = (c < DIN) ? c : 0;
            selfv[it] = __ldg(xs + cc);
            float s = 0.f;
            #pragma unroll
            for (int j = 0; j < DEG; j++)
                s += __half2float(__ldg(x + (size_t)aidx[j] * DIN + cc));
            sumv[it] = s;
        }
        float bsum = 0.f;
        {
            const int bl = (lane < 6) ? lane : 0;
            #pragma unroll
            for (int j = 0; j < DEG; j++)
                bsum += __half2float(__ldg(bond + (size_t)bidx[j] * 6 + bl));
        }

        __half* Ar = sAh + (size_t)r * KPAD;
        if (valid) {
            #pragma unroll
            for (int it = 0; it < NIT; it++) {
                const int c = lane + 32 * it;
                if (c < DIN) {
                    Ar[perm16(c)]       = selfv[it];
                    Ar[perm16(DIN + c)] = __float2half_rn(sumv[it]);
                }
            }
            if (lane < 6) Ar[perm16(2 * DIN + lane)] = __float2half_rn(bsum);
        }
        #pragma unroll
        for (int c0 = K & ~31; c0 < KPAD; c0 += 32) {
            const int c = c0 + lane;
            if (c >= K && c < KPAD) Ar[perm16(c)] = __float2half_rn(0.f);
        }
    }
}

// ---------------- fused gather + fp16 mma GEMM + epilogue (one launch per layer) ----------------
// blockIdx -> degree segment via grid offsets. 1024 threads, 32 warps (8M x 4N), warp tile 16x32.
// MODE 0: fused bias + L2-normalize + relu -> (__half*)outp (ld 100), 1 N-tile
// MODE 1: bias -> g_Th (4 N-tiles) + fused molecule segment-sum (L2 re-read + atomics) -> gout
template<int KPAD, int DIN, int MODE>
__global__ __launch_bounds__(1024)
void fused_gemm_kernel(const __half* __restrict__ x,
                       const __half* __restrict__ bond,
                       const int* __restrict__ an0, const int* __restrict__ bn0,
                       const int* __restrict__ an1, const int* __restrict__ bn1,
                       const int* __restrict__ an2, const int* __restrict__ bn2,
                       const int* __restrict__ an3, const int* __restrict__ bn3,
                       int go1, int go2, int go3,
                       int ds1, int ds2, int ds3,
                       int n1, int n2, int n3, int n4,
                       const __half* __restrict__ WtL, const float* __restrict__ biasL,
                       void* __restrict__ outp, float* __restrict__ gout)
{
    constexpr int STRH = KPAD;
    constexpr int numNt = (MODE == 0) ? 1 : 4;
    constexpr int NKS  = KPAD / 16;
    constexpr int CH   = KPAD / 8;
    extern __shared__ char smemc[];
    __half* sAh  = (__half*)smemc;                      // [128][STRH]
    __half* sBh  = sAh + 128 * STRH;                    // [128][STRH]
    float*  sBias = (float*)(sBh + 128 * STRH);         // [512]
    float*  sSS   = sBias + 512;                        // [128]
    float*  sInv  = sSS + 128;                          // [128]
    float*  sT    = sInv + 128;                         // [128][104] (MODE 0 only)
    const uint32_t sBu = smem_u32(sBh);

    const int tid  = threadIdx.x;
    const int wid  = tid >> 5;
    const int lane = tid & 31;
    const int grp  = lane >> 2;
    const int tig  = lane & 3;
    const int wm   = wid & 7;
    const int wn   = wid >> 3;

    // blockIdx -> (degree, local block, segment start, segment size)
    const int b = blockIdx.x;
    int deg, bloc, degStart, M;
    const int *an, *bn;
    if (b < go1)      { deg = 1; bloc = b;       degStart = 0;   M = n1; an = an0; bn = bn0; }
    else if (b < go2) { deg = 2; bloc = b - go1; degStart = ds1; M = n2; an = an1; bn = bn1; }
    else if (b < go3) { deg = 3; bloc = b - go2; degStart = ds2; M = n3; an = an2; bn = bn2; }
    else              { deg = 4; bloc = b - go3; degStart = ds3; M = n4; an = an3; bn = bn3; }
    const int row0 = bloc * 128;
    const __half* Wt  = WtL + (size_t)(deg - 1) * 512 * WTSTR;
    const float* bias = biasL + (deg - 1) * 512;

    if (MODE == 1 && tid < 128) sSS[tid] = 0.f;

    // ---- issue B tile for nt=0 BEFORE gather; load bias (overlap gather) ----
    {
        for (int i = tid; i < 128 * CH; i += 1024) {
            int rowb = i / CH;
            int c16  = i - rowb * CH;
            cp_async16(sBu + (uint32_t)(rowb * STRH + c16 * 8) * 2,
                       Wt + (size_t)rowb * WTSTR + c16 * 8);
        }
        asm volatile("cp.async.commit_group;");
        if (MODE == 1) { if (tid < 512) sBias[tid] = bias[tid]; }
        else           { if (tid < 128) sBias[tid] = bias[tid]; }
    }

    // ---- gather (uniform branch per block, each path fully unrolled) ----
    switch (deg) {
    case 1: gather_fill<KPAD, DIN, 1>(sAh, x, bond, an, bn, degStart, M, row0, wid, lane); break;
    case 2: gather_fill<KPAD, DIN, 2>(sAh, x, bond, an, bn, degStart, M, row0, wid, lane); break;
    case 3: gather_fill<KPAD, DIN, 3>(sAh, x, bond, an, bn, degStart, M, row0, wid, lane); break;
    default: gather_fill<KPAD, DIN, 4>(sAh, x, bond, an, bn, degStart, M, row0, wid, lane); break;
    }

    asm volatile("cp.async.wait_group 0;" ::: "memory");
    __syncthreads();

    const uint2* paL = (const uint2*)(sAh + (size_t)(wm * 16 + grp) * STRH) + tig;
    const uint2* paH = (const uint2*)(sAh + (size_t)(wm * 16 + grp + 8) * STRH) + tig;
    const uint2* pb  = (const uint2*)(sBh + (size_t)(wn * 32 + grp) * STRH) + tig;
    constexpr int BNF = 8 * STRH / 4;

    for (int nt = 0; nt < numNt; nt++) {
        const int ncol0 = nt * 128;
        if (nt > 0) {
            __syncthreads();
            for (int i = tid; i < 128 * CH; i += 1024) {
                int rowb = i / CH;
                int c16  = i - rowb * CH;
                cp_async16(sBu + (uint32_t)(rowb * STRH + c16 * 8) * 2,
                           Wt + (size_t)(ncol0 + rowb) * WTSTR + c16 * 8);
            }
            cp_async_commit_wait();
            __syncthreads();
        }

        float acc[4][4];
        #pragma unroll
        for (int nf = 0; nf < 4; nf++)
            #pragma unroll
            for (int q = 0; q < 4; q++) acc[nf][q] = 0.f;

        uint2 aL = paL[0], aH = paH[0];
        uint2 bv[4];
        #pragma unroll
        for (int nf = 0; nf < 4; nf++) bv[nf] = pb[nf * BNF];

        #pragma unroll
        for (int ks = 0; ks < NKS; ks++) {
            uint2 naL, naH, nbv[4];
            if (ks + 1 < NKS) {
                const int kk = 4 * (ks + 1);
                naL = paL[kk];
                naH = paH[kk];
                #pragma unroll
                for (int nf = 0; nf < 4; nf++) nbv[nf] = pb[nf * BNF + kk];
            }
            #pragma unroll
            for (int nf = 0; nf < 4; nf++)
                mma16(acc[nf][0], acc[nf][1], acc[nf][2], acc[nf][3],
                      aL.x, aH.x, aL.y, aH.y, bv[nf].x, bv[nf].y);
            if (ks + 1 < NKS) {
                aL = naL; aH = naH;
                #pragma unroll
                for (int nf = 0; nf < 4; nf++) bv[nf] = nbv[nf];
            }
        }

        if (MODE == 1) {
            // fp16 store (default: keep L2-resident for fused molsum) + fp32 row sum-of-squares
            __half* outh = (__half*)outp;
            int r = wm * 16 + grp;
            float ss0 = 0.f, ss1 = 0.f;
            #pragma unroll
            for (int nf = 0; nf < 4; nf++) {
                int c = wn * 32 + nf * 8 + 2 * tig;
                float b0v = sBias[ncol0 + c], b1v = sBias[ncol0 + c + 1];
                float t0 = acc[nf][0] + b0v, t1 = acc[nf][1] + b1v;
                float t2 = acc[nf][2] + b0v, t3 = acc[nf][3] + b1v;
                ss0 += t0 * t0 + t1 * t1;
                ss1 += t2 * t2 + t3 * t3;
                if (row0 + r < M)
                    *(__half2*)(outh + (size_t)(degStart + row0 + r) * 512 + ncol0 + c)
                        = __floats2half2_rn(t0, t1);
                if (row0 + r + 8 < M)
                    *(__half2*)(outh + (size_t)(degStart + row0 + r + 8) * 512 + ncol0 + c)
                        = __floats2half2_rn(t2, t3);
            }
            if (row0 + r < M)     atomicAdd(&sSS[r], ss0);
            if (row0 + r + 8 < M) atomicAdd(&sSS[r + 8], ss1);
        } else {
            // stage t = acc + bias into sT (fp32), then row-norm -> fp16 x out
            __half* outh = (__half*)outp;
            __syncthreads();
            {
                int r = wm * 16 + grp;
                #pragma unroll
                for (int nf = 0; nf < 4; nf++) {
                    int c = wn * 32 + nf * 8 + 2 * tig;
                    if (c < 100) {
                        float b0v = sBias[c], b1v = sBias[c + 1];
                        sT[r * 104 + c]           = acc[nf][0] + b0v;
                        sT[r * 104 + c + 1]       = acc[nf][1] + b1v;
                        sT[(r + 8) * 104 + c]     = acc[nf][2] + b0v;
                        sT[(r + 8) * 104 + c + 1] = acc[nf][3] + b1v;
                    }
                }
            }
            __syncthreads();
            #pragma unroll
            for (int rr = 0; rr < 4; rr++) {
                int r = wid * 4 + rr;
                int m = row0 + r;
                if (m >= M) continue;
                const float* tr = sT + r * 104;
                float v0 = tr[lane];
                float v1 = tr[lane + 32];
                float v2 = tr[lane + 64];
                float v3 = (lane < 4) ? tr[lane + 96] : 0.f;
                float ss = v0 * v0 + v1 * v1 + v2 * v2 + v3 * v3;
                #pragma unroll
                for (int o = 16; o; o >>= 1) ss += __shfl_xor_sync(0xffffffffu, ss, o);
                float inv = 1.f / fmaxf(sqrtf(ss), 1e-12f);
                __half* o = outh + (size_t)(degStart + m) * 100;
                o[lane]      = __float2half_rn(fmaxf(v0 * inv, 0.f));
                o[lane + 32] = __float2half_rn(fmaxf(v1 * inv, 0.f));
                o[lane + 64] = __float2half_rn(fmaxf(v2 * inv, 0.f));
                if (lane < 4) o[lane + 96] = __float2half_rn(fmaxf(v3 * inv, 0.f));
            }
        }
    }

    if (MODE == 1) {
        // ---- fused molecule segment-sum: re-read own t tile (L2-hot), accumulate per (mol,col) ----
        __syncthreads();
        if (tid < 128) {
            float iv = 0.f;
            if (row0 + tid < M) iv = 1.f / fmaxf(sqrtf(sSS[tid]), 1e-12f);
            sInv[tid] = iv;
        }
        __syncthreads();
        const __half* outh = (const __half*)outp;
        int aStart = degStart + row0;
        int aEnd   = degStart + ((row0 + 128 < M) ? (row0 + 128) : M);
        if (aEnd > aStart) {
            int molBase = aStart / 20;
            int nMol = (aEnd - 1) / 20 - molBase + 1;     // <= 8
            for (int p = tid; p < nMol * 512; p += 1024) {
                int ml = p >> 9, c = p & 511;
                int mol = molBase + ml;
                int a0 = mol * 20; if (a0 < aStart) a0 = aStart;
                int a1 = mol * 20 + 20; if (a1 > aEnd) a1 = aEnd;
                float s = 0.f;
                for (int a = a0; a < a1; a++) {
                    float t = __half2float(outh[(size_t)a * 512 + c]);
                    s += fmaxf(t * sInv[a - aStart], 0.f);
                }
                atomicAdd(gout + (size_t)mol * 512 + c, s);
            }
        }
    }
}

// ---------------- host ----------------
extern "C" void kernel_launch(void* const* d_in, const int* in_sizes, int n_in,
                              void* d_out, int out_size)
{
    const float* atom = (const float*)d_in[0];
    const float* bond = (const float*)d_in[1];
    const int*   an[4];
    const int*   bn[4];
    const float *Ws[3], *bsv[3], *Wd[3], *bdv[3];
    int n1, n2, n3, n4;

    bool dictOrder = (in_sizes[3] == in_sizes[2]);
    if (!dictOrder) {
        for (int i = 0; i < 4; i++) { an[i] = (const int*)d_in[2 + i]; bn[i] = (const int*)d_in[6 + i]; }
        n1 = in_sizes[2]; n2 = in_sizes[3] / 2; n3 = in_sizes[4] / 3; n4 = in_sizes[5] / 4;
        Ws[0] = (const float*)d_in[11]; bsv[0] = (const float*)d_in[12];
        Ws[1] = (const float*)d_in[13]; bsv[1] = (const float*)d_in[14];
        Ws[2] = (const float*)d_in[15]; bsv[2] = (const float*)d_in[16];
        Wd[0] = (const float*)d_in[17]; bdv[0] = (const float*)d_in[18];
        Wd[1] = (const float*)d_in[19]; bdv[1] = (const float*)d_in[20];
        Wd[2] = (const float*)d_in[21]; bdv[2] = (const float*)d_in[22];
    } else {
        for (int i = 0; i < 4; i++) { an[i] = (const int*)d_in[2 + 2 * i]; bn[i] = (const int*)d_in[3 + 2 * i]; }
        n1 = in_sizes[2]; n2 = in_sizes[4] / 2; n3 = in_sizes[6] / 3; n4 = in_sizes[8] / 4;
        Ws[0] = (const float*)d_in[11]; bsv[0] = (const float*)d_in[12];
        Wd[0] = (const float*)d_in[13]; bdv[0] = (const float*)d_in[14];
        Ws[1] = (const float*)d_in[15]; bsv[1] = (const float*)d_in[16];
        Wd[1] = (const float*)d_in[17]; bdv[1] = (const float*)d_in[18];
        Ws[2] = (const float*)d_in[19]; bsv[2] = (const float*)d_in[20];
        Wd[2] = (const float*)d_in[21]; bdv[2] = (const float*)d_in[22];
    }

    float *pbc;
    __half *pTh, *pWt, *pXin, *pBd, *pX0, *pX1;
    cudaGetSymbolAddress((void**)&pTh,  g_Th);
    cudaGetSymbolAddress((void**)&pXin, g_Xin);
    cudaGetSymbolAddress((void**)&pBd,  g_Bd);
    cudaGetSymbolAddress((void**)&pX0,  g_X0);
    cudaGetSymbolAddress((void**)&pX1,  g_X1);
    cudaGetSymbolAddress((void**)&pWt,  g_Wt);
    cudaGetSymbolAddress((void**)&pbc,  g_bc);

    const int nd[4] = {n1, n2, n3, n4};
    const int ds1 = n1, ds2 = n1 + n2, ds3 = n1 + n2 + n3;

    prep_kernel<<<1664, 384>>>(atom, in_sizes[0], bond, in_sizes[1],
                               (float*)d_out, out_size,
                               Ws[0], Wd[0], bsv[0], bdv[0],
                               Ws[1], Wd[1], bsv[1], bdv[1],
                               Ws[2], Wd[2], bsv[2], bdv[2]);

    // grid offsets (cumulative block counts per degree)
    int nb[4], go[4];
    int total = 0;
    for (int d = 0; d < 4; d++) { nb[d] = (nd[d] + 127) / 128; total += nb[d]; }
    go[0] = nb[0]; go[1] = go[0] + nb[1]; go[2] = go[1] + nb[2]; go[3] = total;

    // smem: A+B fp16 + bias 512f + sSS 128f + sInv 128f [+ sT 128*104f MODE0]
    const int smem0 = 2 * 128 * 144 * 2 + (512 + 128 + 128) * 4 + 128 * 104 * 4;  // 129,792
    const int smem1 = 2 * 128 * 208 * 2 + (512 + 128 + 128) * 4 + 128 * 104 * 4;  // 162,560
    const int smem2 = 2 * 128 * 208 * 2 + (512 + 128 + 128) * 4;                  // 109,568

    cudaFuncSetAttribute((const void*)fused_gemm_kernel<144, 62, 0>,
                         cudaFuncAttributeMaxDynamicSharedMemorySize, smem0);
    cudaFuncSetAttribute((const void*)fused_gemm_kernel<208, 100, 0>,
                         cudaFuncAttributeMaxDynamicSharedMemorySize, smem1);
    cudaFuncSetAttribute((const void*)fused_gemm_kernel<208, 100, 1>,
                         cudaFuncAttributeMaxDynamicSharedMemorySize, smem2);

    // layer 0
    fused_gemm_kernel<144, 62, 0><<<total, 1024, smem0>>>(
        pXin, pBd, an[0], bn[0], an[1], bn[1], an[2], bn[2], an[3], bn[3],
        go[0], go[1], go[2], ds1, ds2, ds3, n1, n2, n3, n4,
        pWt + 0 * (4 * 512 * WTSTR), pbc + 0 * 2048, (void*)pX0, (float*)d_out);
    // layer 1
    fused_gemm_kernel<208, 100, 0><<<total, 1024, smem1>>>(
        pX0, pBd, an[0], bn[0], an[1], bn[1], an[2], bn[2], an[3], bn[3],
        go[0], go[1], go[2], ds1, ds2, ds3, n1, n2, n3, n4,
        pWt + 1 * (size_t)(4 * 512 * WTSTR), pbc + 1 * 2048, (void*)pX1, (float*)d_out);
    // layer 2 (with fused molecule segment-sum into d_out)
    fused_gemm_kernel<208, 100, 1><<<total, 1024, smem2>>>(
        pX1, pBd, an[0], bn[0], an[1], bn[1], an[2], bn[2], an[3], bn[3],
        go[0], go[1], go[2], ds1, ds2, ds3, n1, n2, n3, n4,
        pWt + 2 * (size_t)(4 * 512 * WTSTR), pbc + 2 * 2048, (void*)pTh, (float*)d_out);
}